// round 4
// baseline (speedup 1.0000x reference)
#include <cuda_runtime.h>
#include <float.h>
#include <stdint.h>

// Problem constants
#define BB   2
#define SS   2048
#define HIDD 2048
#define NH   32
#define NKV  8
#define HD   64
#define MROWS (BB*SS)          // 4096
#define SCALE 0.125f           // HD^-0.5
#define EPS   1e-6f

// ---------------- scratch -----------------------------------------------------
__device__ float g_q[(size_t)MROWS * NH * HD];    // (4096, 2048)
__device__ float g_k[(size_t)MROWS * NKV * HD];   // (4096, 512)
__device__ float g_v[(size_t)MROWS * NKV * HD];   // (4096, 512)
__device__ float g_attn[(size_t)MROWS * NH * HD]; // (4096, 2048)

// ---------------- TF32 helpers ------------------------------------------------
__device__ __forceinline__ float2 split_tf32(float x) {
    uint32_t h;
    asm("cvt.rna.tf32.f32 %0, %1;" : "=r"(h) : "f"(x));
    float r = x - __uint_as_float(h);
    uint32_t l;
    asm("cvt.rna.tf32.f32 %0, %1;" : "=r"(l) : "f"(r));
    return make_float2(__uint_as_float(h), __uint_as_float(l));
}

__device__ __forceinline__ void mma_tf32(float c[4],
    float a0, float a1, float a2, float a3, float b0, float b1)
{
    asm volatile(
        "mma.sync.aligned.m16n8k8.row.col.f32.tf32.tf32.f32 "
        "{%0,%1,%2,%3}, {%4,%5,%6,%7}, {%8,%9}, {%0,%1,%2,%3};"
        : "+f"(c[0]), "+f"(c[1]), "+f"(c[2]), "+f"(c[3])
        : "r"(__float_as_uint(a0)), "r"(__float_as_uint(a1)),
          "r"(__float_as_uint(a2)), "r"(__float_as_uint(a3)),
          "r"(__float_as_uint(b0)), "r"(__float_as_uint(b1)));
}

// ---------------- 3xTF32 tensor-core GEMM body:  C = A[M,K] @ B[N,K]^T ---------
// Block tile 128x128, BK=16, 256 threads (8 warps), warp tile 64x32.
// SMEM holds pre-split {hi,lo} pairs -> conversions done once per element.
#define TBM 128
#define TBN 128
#define TBK 16
#define SP2 18    // float2 row stride (16 + 2 pad)

__device__ __forceinline__ void gemm_body(
    const float* __restrict__ A, const float* __restrict__ Bm,
    float* __restrict__ C, int N, int K, int m0, int n0)
{
    __shared__ float2 As2[TBM][SP2];
    __shared__ float2 Bs2[TBN][SP2];

    const int t    = threadIdx.x;
    const int lane = t & 31;
    const int warp = t >> 5;                  // 0..7
    const int wm   = warp & 1;                // 2 warps along M
    const int wn   = warp >> 1;               // 4 warps along N

    const int grp = lane >> 2;                // 0..7
    const int kc  = lane & 3;                 // 0..3

    // gmem loader mapping: each thread loads 2 float4 of A and 2 of B per tile
    const int lr = t >> 2;                    // 0..63
    const int lq = (t & 3) * 4;               // k offset 0,4,8,12
    const float* Ap0 = A  + (size_t)(m0 + lr)      * K + lq;
    const float* Ap1 = A  + (size_t)(m0 + lr + 64) * K + lq;
    const float* Bp0 = Bm + (size_t)(n0 + lr)      * K + lq;
    const float* Bp1 = Bm + (size_t)(n0 + lr + 64) * K + lq;

    float acc[4][4][4];                       // [mt][nt][frag]
#pragma unroll
    for (int i = 0; i < 4; i++)
#pragma unroll
        for (int j = 0; j < 4; j++)
#pragma unroll
            for (int f = 0; f < 4; f++) acc[i][j][f] = 0.f;

    // preload tile 0
    float4 ra0 = *reinterpret_cast<const float4*>(Ap0);
    float4 ra1 = *reinterpret_cast<const float4*>(Ap1);
    float4 rb0 = *reinterpret_cast<const float4*>(Bp0);
    float4 rb1 = *reinterpret_cast<const float4*>(Bp1);
    As2[lr][lq + 0]      = split_tf32(ra0.x); As2[lr][lq + 1]      = split_tf32(ra0.y);
    As2[lr][lq + 2]      = split_tf32(ra0.z); As2[lr][lq + 3]      = split_tf32(ra0.w);
    As2[lr + 64][lq + 0] = split_tf32(ra1.x); As2[lr + 64][lq + 1] = split_tf32(ra1.y);
    As2[lr + 64][lq + 2] = split_tf32(ra1.z); As2[lr + 64][lq + 3] = split_tf32(ra1.w);
    Bs2[lr][lq + 0]      = split_tf32(rb0.x); Bs2[lr][lq + 1]      = split_tf32(rb0.y);
    Bs2[lr][lq + 2]      = split_tf32(rb0.z); Bs2[lr][lq + 3]      = split_tf32(rb0.w);
    Bs2[lr + 64][lq + 0] = split_tf32(rb1.x); Bs2[lr + 64][lq + 1] = split_tf32(rb1.y);
    Bs2[lr + 64][lq + 2] = split_tf32(rb1.z); Bs2[lr + 64][lq + 3] = split_tf32(rb1.w);
    __syncthreads();

    const int mrow = wm * 64 + grp;           // A fragment base row
    const int nrow = wn * 32 + grp;           // B fragment base row

    for (int k0 = TBK; ; k0 += TBK) {
        const bool more = (k0 < K);
        if (more) {
            ra0 = *reinterpret_cast<const float4*>(Ap0 + k0);
            ra1 = *reinterpret_cast<const float4*>(Ap1 + k0);
            rb0 = *reinterpret_cast<const float4*>(Bp0 + k0);
            rb1 = *reinterpret_cast<const float4*>(Bp1 + k0);
        }

#pragma unroll
        for (int ks = 0; ks < TBK; ks += 8) {
            float2 b[4][2];
#pragma unroll
            for (int nt = 0; nt < 4; nt++) {
                const int n = nrow + nt * 8;
                b[nt][0] = Bs2[n][ks + kc];
                b[nt][1] = Bs2[n][ks + kc + 4];
            }
#pragma unroll
            for (int mt = 0; mt < 4; mt++) {
                const int r = mrow + mt * 16;
                float2 a0 = As2[r][ks + kc];
                float2 a1 = As2[r + 8][ks + kc];
                float2 a2 = As2[r][ks + kc + 4];
                float2 a3 = As2[r + 8][ks + kc + 4];
#pragma unroll
                for (int nt = 0; nt < 4; nt++) {
                    mma_tf32(acc[mt][nt], a0.x, a1.x, a2.x, a3.x, b[nt][0].x, b[nt][1].x);
                    mma_tf32(acc[mt][nt], a0.y, a1.y, a2.y, a3.y, b[nt][0].x, b[nt][1].x);
                    mma_tf32(acc[mt][nt], a0.x, a1.x, a2.x, a3.x, b[nt][0].y, b[nt][1].y);
                }
            }
        }
        __syncthreads();
        if (!more) break;
        As2[lr][lq + 0]      = split_tf32(ra0.x); As2[lr][lq + 1]      = split_tf32(ra0.y);
        As2[lr][lq + 2]      = split_tf32(ra0.z); As2[lr][lq + 3]      = split_tf32(ra0.w);
        As2[lr + 64][lq + 0] = split_tf32(ra1.x); As2[lr + 64][lq + 1] = split_tf32(ra1.y);
        As2[lr + 64][lq + 2] = split_tf32(ra1.z); As2[lr + 64][lq + 3] = split_tf32(ra1.w);
        Bs2[lr][lq + 0]      = split_tf32(rb0.x); Bs2[lr][lq + 1]      = split_tf32(rb0.y);
        Bs2[lr][lq + 2]      = split_tf32(rb0.z); Bs2[lr][lq + 3]      = split_tf32(rb0.w);
        Bs2[lr + 64][lq + 0] = split_tf32(rb1.x); Bs2[lr + 64][lq + 1] = split_tf32(rb1.y);
        Bs2[lr + 64][lq + 2] = split_tf32(rb1.z); Bs2[lr + 64][lq + 3] = split_tf32(rb1.w);
        __syncthreads();
    }

    // epilogue
#pragma unroll
    for (int mt = 0; mt < 4; mt++) {
        const int row = m0 + wm * 64 + mt * 16 + grp;
#pragma unroll
        for (int nt = 0; nt < 4; nt++) {
            const int col = n0 + wn * 32 + nt * 8 + kc * 2;
            *reinterpret_cast<float2*>(C + (size_t)row * N + col) =
                make_float2(acc[mt][nt][0], acc[mt][nt][1]);
            *reinterpret_cast<float2*>(C + (size_t)(row + 8) * N + col) =
                make_float2(acc[mt][nt][2], acc[mt][nt][3]);
        }
    }
}

// Fused QKV projection: one launch covers Wq (16 n-blocks), Wk (4), Wv (4).
__global__ __launch_bounds__(256, 2) void gemm_qkv(
    const float* __restrict__ A,
    const float* __restrict__ Wq, const float* __restrict__ Wk,
    const float* __restrict__ Wv,
    float* __restrict__ Cq, float* __restrict__ Ck, float* __restrict__ Cv)
{
    const int bx = blockIdx.x;                // 0..23
    const int m0 = blockIdx.y * TBM;
    const float* Bm; float* C; int N, n0;
    if (bx < 16)      { Bm = Wq; C = Cq; N = NH  * HD; n0 = bx * TBN; }
    else if (bx < 20) { Bm = Wk; C = Ck; N = NKV * HD; n0 = (bx - 16) * TBN; }
    else              { Bm = Wv; C = Cv; N = NKV * HD; n0 = (bx - 20) * TBN; }
    gemm_body(A, Bm, C, N, HIDD, m0, n0);
}

__global__ __launch_bounds__(256, 2) void gemm_tc(
    const float* __restrict__ A, const float* __restrict__ Bm,
    float* __restrict__ C, int N, int K)
{
    gemm_body(A, Bm, C, N, K, blockIdx.y * TBM, blockIdx.x * TBN);
}

// ---------------- RMSNorm + RoPE over q and k head-rows -----------------------
__global__ void norm_rope_kernel(
    const float* __restrict__ cosv, const float* __restrict__ sinv,
    const float* __restrict__ qw,   const float* __restrict__ kw)
{
    const int gid  = blockIdx.x * blockDim.x + threadIdx.x;
    const int wid  = gid >> 5;
    const int lane = gid & 31;
    const int nqr  = MROWS * NH;
    const int ntot = nqr + MROWS * NKV;
    if (wid >= ntot) return;

    float* base;
    int bs;
    const float* w;
    if (wid < nqr) { base = g_q + (size_t)wid * HD;        bs = wid / NH;  w = qw; }
    else { int r = wid - nqr; base = g_k + (size_t)r * HD; bs = r / NKV;   w = kw; }

    float x0 = base[lane];
    float x1 = base[lane + 32];
    float ss = x0 * x0 + x1 * x1;
#pragma unroll
    for (int o = 16; o > 0; o >>= 1) ss += __shfl_xor_sync(0xffffffffu, ss, o);
    const float rinv = rsqrtf(ss * (1.0f / HD) + EPS);

    const float n0 = w[lane]      * (x0 * rinv);
    const float n1 = w[lane + 32] * (x1 * rinv);

    const float c0 = cosv[(size_t)bs * HD + lane];
    const float c1 = cosv[(size_t)bs * HD + lane + 32];
    const float s0 = sinv[(size_t)bs * HD + lane];
    const float s1 = sinv[(size_t)bs * HD + lane + 32];

    base[lane]      = n0 * c0 - n1 * s0;
    base[lane + 32] = n1 * c1 + n0 * s1;
}

// ---------------- causal flash attention (fp32, per-thread query row) ---------
#define FBQ 128
#define FBK 64
#define HDP (HD + 4)   // padded row: kills 2-way STS.128 bank conflict
__global__ __launch_bounds__(FBQ) void flash_kernel()
{
    const int bh  = blockIdx.y;
    const int b   = bh / NH;
    const int h   = bh % NH;
    const int kvh = h / (NH / NKV);
    const int q0  = blockIdx.x * FBQ;
    const int tid = threadIdx.x;
    const int qi  = q0 + tid;

    __shared__ float Ks[FBK][HDP];
    __shared__ float Vs[FBK][HDP];

    float4 qr[16], acc[16];
    const float4* qp = reinterpret_cast<const float4*>(
        g_q + ((size_t)(b * SS + qi) * NH + h) * HD);
#pragma unroll
    for (int i = 0; i < 16; i++) { qr[i] = qp[i]; acc[i] = make_float4(0.f, 0.f, 0.f, 0.f); }

    float m = -FLT_MAX, l = 0.f;

    for (int k0 = 0; k0 < q0 + FBQ; k0 += FBK) {
        // cooperative tile load (float4, coalesced)
        for (int idx = tid; idx < FBK * (HD / 4); idx += FBQ) {
            const int row = idx >> 4;
            const int c   = idx & 15;
            const size_t g = ((size_t)(b * SS + k0 + row) * NKV + kvh) * HD + c * 4;
            *reinterpret_cast<float4*>(&Ks[row][c * 4]) = *reinterpret_cast<const float4*>(g_k + g);
            *reinterpret_cast<float4*>(&Vs[row][c * 4]) = *reinterpret_cast<const float4*>(g_v + g);
        }
        __syncthreads();

        // inner bound: full tiles process all FBK keys; diagonal tiles stop at qi
        const int jmax = (k0 + FBK <= q0) ? FBK : min(FBK, qi - k0 + 1);

#pragma unroll 2
        for (int j = 0; j < jmax; j++) {
            const float4* kr = reinterpret_cast<const float4*>(&Ks[j][0]);
            float s = 0.f;
#pragma unroll
            for (int i = 0; i < 16; i++) {
                float4 kv = kr[i];
                s += qr[i].x * kv.x + qr[i].y * kv.y + qr[i].z * kv.z + qr[i].w * kv.w;
            }
            const float sc = s * SCALE;
            if (sc > m) {                      // rare: lazy rescale on new max
                const float corr = __expf(m - sc);
                l *= corr;
#pragma unroll
                for (int i = 0; i < 16; i++) {
                    acc[i].x *= corr; acc[i].y *= corr;
                    acc[i].z *= corr; acc[i].w *= corr;
                }
                m = sc;
            }
            const float p = __expf(sc - m);
            l += p;
            const float4* vr = reinterpret_cast<const float4*>(&Vs[j][0]);
#pragma unroll
            for (int i = 0; i < 16; i++) {
                float4 vv = vr[i];
                acc[i].x += p * vv.x; acc[i].y += p * vv.y;
                acc[i].z += p * vv.z; acc[i].w += p * vv.w;
            }
        }
        __syncthreads();
    }

    const float inv = 1.f / l;
    float4* op = reinterpret_cast<float4*>(
        g_attn + ((size_t)(b * SS + qi) * NH + h) * HD);
#pragma unroll
    for (int i = 0; i < 16; i++) {
        float4 r = acc[i];
        r.x *= inv; r.y *= inv; r.z *= inv; r.w *= inv;
        op[i] = r;
    }
}

// ------------------------------- launch ---------------------------------------
extern "C" void kernel_launch(void* const* d_in, const int* in_sizes, int n_in,
                              void* d_out, int out_size)
{
    const float* hidden = (const float*)d_in[0];
    const float* cosv   = (const float*)d_in[1];
    const float* sinv   = (const float*)d_in[2];
    const float* Wq     = (const float*)d_in[3];
    const float* Wk     = (const float*)d_in[4];
    const float* Wv     = (const float*)d_in[5];
    const float* Wo     = (const float*)d_in[6];
    const float* qw     = (const float*)d_in[7];
    const float* kw     = (const float*)d_in[8];
    float* out          = (float*)d_out;

    float *pq, *pk, *pv, *pattn;
    cudaGetSymbolAddress((void**)&pq,    g_q);
    cudaGetSymbolAddress((void**)&pk,    g_k);
    cudaGetSymbolAddress((void**)&pv,    g_v);
    cudaGetSymbolAddress((void**)&pattn, g_attn);

    // Fused QKV projections (tensor-core 3xTF32): 24 n-blocks x 32 m-blocks
    gemm_qkv<<<dim3(24, MROWS / TBM), 256>>>(hidden, Wq, Wk, Wv, pq, pk, pv);

    // RMSNorm + RoPE on q and k
    {
        const int warps = MROWS * NH + MROWS * NKV;
        const int threads = warps * 32;
        norm_rope_kernel<<<(threads + 255) / 256, 256>>>(cosv, sinv, qw, kw);
    }

    // causal flash attention
    flash_kernel<<<dim3(SS / FBQ, BB * NH), FBQ>>>();

    // output projection -> d_out
    gemm_tc<<<dim3(HIDD / TBN, MROWS / TBM), 256>>>(pattn, Wo, out, HIDD, NH * HD);
}

// round 5
// speedup vs baseline: 1.0058x; 1.0058x over previous
#include <cuda_runtime.h>
#include <float.h>
#include <stdint.h>

// Problem constants
#define BB   2
#define SS   2048
#define HIDD 2048
#define NH   32
#define NKV  8
#define HD   64
#define MROWS (BB*SS)          // 4096
#define SCALE 0.125f           // HD^-0.5
#define EPS   1e-6f

// ---------------- scratch -----------------------------------------------------
__device__ float g_q[(size_t)MROWS * NH * HD];    // (4096, 2048)
__device__ float g_k[(size_t)MROWS * NKV * HD];   // (4096, 512)
__device__ float g_v[(size_t)MROWS * NKV * HD];   // (4096, 512)
__device__ float g_attn[(size_t)MROWS * NH * HD]; // (4096, 2048)

// ---------------- TF32 helpers ------------------------------------------------
__device__ __forceinline__ float2 split_tf32(float x) {
    uint32_t h;
    asm("cvt.rna.tf32.f32 %0, %1;" : "=r"(h) : "f"(x));
    float r = x - __uint_as_float(h);
    uint32_t l;
    asm("cvt.rna.tf32.f32 %0, %1;" : "=r"(l) : "f"(r));
    return make_float2(__uint_as_float(h), __uint_as_float(l));
}

__device__ __forceinline__ void mma_tf32(float c[4],
    float a0, float a1, float a2, float a3, float b0, float b1)
{
    asm volatile(
        "mma.sync.aligned.m16n8k8.row.col.f32.tf32.tf32.f32 "
        "{%0,%1,%2,%3}, {%4,%5,%6,%7}, {%8,%9}, {%0,%1,%2,%3};"
        : "+f"(c[0]), "+f"(c[1]), "+f"(c[2]), "+f"(c[3])
        : "r"(__float_as_uint(a0)), "r"(__float_as_uint(a1)),
          "r"(__float_as_uint(a2)), "r"(__float_as_uint(a3)),
          "r"(__float_as_uint(b0)), "r"(__float_as_uint(b1)));
}

// ---------------- 3xTF32 tensor-core GEMM body:  C = A[M,K] @ B[N,K]^T ---------
// Block tile 128x128, BK=16, 256 threads (8 warps), warp tile 64x32.
// SMEM holds pre-split {hi,lo} pairs -> conversions done once per element.
// SP2 = 20: bank-pair index (20r+c) mod 16 = (4r+c) mod 16, so within each
// 16-lane LDS.64 wavefront phase (grp 0-3 / 4-7), 4*grp + kc hits all 16
// bank pairs exactly once -> CONFLICT-FREE fragment loads (SP2=18 was 2-way).
#define TBM 128
#define TBN 128
#define TBK 16
#define SP2 20    // float2 row stride (16 + 4 pad)

__device__ __forceinline__ void gemm_body(
    const float* __restrict__ A, const float* __restrict__ Bm,
    float* __restrict__ C, int N, int K, int m0, int n0)
{
    __shared__ float2 As2[TBM][SP2];
    __shared__ float2 Bs2[TBN][SP2];

    const int t    = threadIdx.x;
    const int lane = t & 31;
    const int warp = t >> 5;                  // 0..7
    const int wm   = warp & 1;                // 2 warps along M
    const int wn   = warp >> 1;               // 4 warps along N

    const int grp = lane >> 2;                // 0..7
    const int kc  = lane & 3;                 // 0..3

    // gmem loader mapping: each thread loads 2 float4 of A and 2 of B per tile
    const int lr = t >> 2;                    // 0..63
    const int lq = (t & 3) * 4;               // k offset 0,4,8,12
    const float* Ap0 = A  + (size_t)(m0 + lr)      * K + lq;
    const float* Ap1 = A  + (size_t)(m0 + lr + 64) * K + lq;
    const float* Bp0 = Bm + (size_t)(n0 + lr)      * K + lq;
    const float* Bp1 = Bm + (size_t)(n0 + lr + 64) * K + lq;

    float acc[4][4][4];                       // [mt][nt][frag]
#pragma unroll
    for (int i = 0; i < 4; i++)
#pragma unroll
        for (int j = 0; j < 4; j++)
#pragma unroll
            for (int f = 0; f < 4; f++) acc[i][j][f] = 0.f;

    // preload tile 0
    float4 ra0 = *reinterpret_cast<const float4*>(Ap0);
    float4 ra1 = *reinterpret_cast<const float4*>(Ap1);
    float4 rb0 = *reinterpret_cast<const float4*>(Bp0);
    float4 rb1 = *reinterpret_cast<const float4*>(Bp1);
    As2[lr][lq + 0]      = split_tf32(ra0.x); As2[lr][lq + 1]      = split_tf32(ra0.y);
    As2[lr][lq + 2]      = split_tf32(ra0.z); As2[lr][lq + 3]      = split_tf32(ra0.w);
    As2[lr + 64][lq + 0] = split_tf32(ra1.x); As2[lr + 64][lq + 1] = split_tf32(ra1.y);
    As2[lr + 64][lq + 2] = split_tf32(ra1.z); As2[lr + 64][lq + 3] = split_tf32(ra1.w);
    Bs2[lr][lq + 0]      = split_tf32(rb0.x); Bs2[lr][lq + 1]      = split_tf32(rb0.y);
    Bs2[lr][lq + 2]      = split_tf32(rb0.z); Bs2[lr][lq + 3]      = split_tf32(rb0.w);
    Bs2[lr + 64][lq + 0] = split_tf32(rb1.x); Bs2[lr + 64][lq + 1] = split_tf32(rb1.y);
    Bs2[lr + 64][lq + 2] = split_tf32(rb1.z); Bs2[lr + 64][lq + 3] = split_tf32(rb1.w);
    __syncthreads();

    const int mrow = wm * 64 + grp;           // A fragment base row
    const int nrow = wn * 32 + grp;           // B fragment base row

    for (int k0 = TBK; ; k0 += TBK) {
        const bool more = (k0 < K);
        if (more) {
            ra0 = *reinterpret_cast<const float4*>(Ap0 + k0);
            ra1 = *reinterpret_cast<const float4*>(Ap1 + k0);
            rb0 = *reinterpret_cast<const float4*>(Bp0 + k0);
            rb1 = *reinterpret_cast<const float4*>(Bp1 + k0);
        }

#pragma unroll
        for (int ks = 0; ks < TBK; ks += 8) {
            float2 b[4][2];
#pragma unroll
            for (int nt = 0; nt < 4; nt++) {
                const int n = nrow + nt * 8;
                b[nt][0] = Bs2[n][ks + kc];
                b[nt][1] = Bs2[n][ks + kc + 4];
            }
#pragma unroll
            for (int mt = 0; mt < 4; mt++) {
                const int r = mrow + mt * 16;
                float2 a0 = As2[r][ks + kc];
                float2 a1 = As2[r + 8][ks + kc];
                float2 a2 = As2[r][ks + kc + 4];
                float2 a3 = As2[r + 8][ks + kc + 4];
#pragma unroll
                for (int nt = 0; nt < 4; nt++) {
                    mma_tf32(acc[mt][nt], a0.x, a1.x, a2.x, a3.x, b[nt][0].x, b[nt][1].x);
                    mma_tf32(acc[mt][nt], a0.y, a1.y, a2.y, a3.y, b[nt][0].x, b[nt][1].x);
                    mma_tf32(acc[mt][nt], a0.x, a1.x, a2.x, a3.x, b[nt][0].y, b[nt][1].y);
                }
            }
        }
        __syncthreads();
        if (!more) break;
        As2[lr][lq + 0]      = split_tf32(ra0.x); As2[lr][lq + 1]      = split_tf32(ra0.y);
        As2[lr][lq + 2]      = split_tf32(ra0.z); As2[lr][lq + 3]      = split_tf32(ra0.w);
        As2[lr + 64][lq + 0] = split_tf32(ra1.x); As2[lr + 64][lq + 1] = split_tf32(ra1.y);
        As2[lr + 64][lq + 2] = split_tf32(ra1.z); As2[lr + 64][lq + 3] = split_tf32(ra1.w);
        Bs2[lr][lq + 0]      = split_tf32(rb0.x); Bs2[lr][lq + 1]      = split_tf32(rb0.y);
        Bs2[lr][lq + 2]      = split_tf32(rb0.z); Bs2[lr][lq + 3]      = split_tf32(rb0.w);
        Bs2[lr + 64][lq + 0] = split_tf32(rb1.x); Bs2[lr + 64][lq + 1] = split_tf32(rb1.y);
        Bs2[lr + 64][lq + 2] = split_tf32(rb1.z); Bs2[lr + 64][lq + 3] = split_tf32(rb1.w);
        __syncthreads();
    }

    // epilogue
#pragma unroll
    for (int mt = 0; mt < 4; mt++) {
        const int row = m0 + wm * 64 + mt * 16 + grp;
#pragma unroll
        for (int nt = 0; nt < 4; nt++) {
            const int col = n0 + wn * 32 + nt * 8 + kc * 2;
            *reinterpret_cast<float2*>(C + (size_t)row * N + col) =
                make_float2(acc[mt][nt][0], acc[mt][nt][1]);
            *reinterpret_cast<float2*>(C + (size_t)(row + 8) * N + col) =
                make_float2(acc[mt][nt][2], acc[mt][nt][3]);
        }
    }
}

// Fused QKV projection: one launch covers Wq (16 n-blocks), Wk (4), Wv (4).
__global__ __launch_bounds__(256, 2) void gemm_qkv(
    const float* __restrict__ A,
    const float* __restrict__ Wq, const float* __restrict__ Wk,
    const float* __restrict__ Wv,
    float* __restrict__ Cq, float* __restrict__ Ck, float* __restrict__ Cv)
{
    const int bx = blockIdx.x;                // 0..23
    const int m0 = blockIdx.y * TBM;
    const float* Bm; float* C; int N, n0;
    if (bx < 16)      { Bm = Wq; C = Cq; N = NH  * HD; n0 = bx * TBN; }
    else if (bx < 20) { Bm = Wk; C = Ck; N = NKV * HD; n0 = (bx - 16) * TBN; }
    else              { Bm = Wv; C = Cv; N = NKV * HD; n0 = (bx - 20) * TBN; }
    gemm_body(A, Bm, C, N, HIDD, m0, n0);
}

__global__ __launch_bounds__(256, 2) void gemm_tc(
    const float* __restrict__ A, const float* __restrict__ Bm,
    float* __restrict__ C, int N, int K)
{
    gemm_body(A, Bm, C, N, K, blockIdx.y * TBM, blockIdx.x * TBN);
}

// ---------------- RMSNorm + RoPE over q and k head-rows -----------------------
__global__ void norm_rope_kernel(
    const float* __restrict__ cosv, const float* __restrict__ sinv,
    const float* __restrict__ qw,   const float* __restrict__ kw)
{
    const int gid  = blockIdx.x * blockDim.x + threadIdx.x;
    const int wid  = gid >> 5;
    const int lane = gid & 31;
    const int nqr  = MROWS * NH;
    const int ntot = nqr + MROWS * NKV;
    if (wid >= ntot) return;

    float* base;
    int bs;
    const float* w;
    if (wid < nqr) { base = g_q + (size_t)wid * HD;        bs = wid / NH;  w = qw; }
    else { int r = wid - nqr; base = g_k + (size_t)r * HD; bs = r / NKV;   w = kw; }

    float x0 = base[lane];
    float x1 = base[lane + 32];
    float ss = x0 * x0 + x1 * x1;
#pragma unroll
    for (int o = 16; o > 0; o >>= 1) ss += __shfl_xor_sync(0xffffffffu, ss, o);
    const float rinv = rsqrtf(ss * (1.0f / HD) + EPS);

    const float n0 = w[lane]      * (x0 * rinv);
    const float n1 = w[lane + 32] * (x1 * rinv);

    const float c0 = cosv[(size_t)bs * HD + lane];
    const float c1 = cosv[(size_t)bs * HD + lane + 32];
    const float s0 = sinv[(size_t)bs * HD + lane];
    const float s1 = sinv[(size_t)bs * HD + lane + 32];

    base[lane]      = n0 * c0 - n1 * s0;
    base[lane + 32] = n1 * c1 + n0 * s1;
}

// ---------------- causal flash attention (fp32, per-thread query row) ---------
#define FBQ 128
#define FBK 64
#define HDP (HD + 4)   // padded row: kills 2-way STS.128 bank conflict
__global__ __launch_bounds__(FBQ) void flash_kernel()
{
    const int bh  = blockIdx.y;
    const int b   = bh / NH;
    const int h   = bh % NH;
    const int kvh = h / (NH / NKV);
    const int q0  = blockIdx.x * FBQ;
    const int tid = threadIdx.x;
    const int qi  = q0 + tid;

    __shared__ float Ks[FBK][HDP];
    __shared__ float Vs[FBK][HDP];

    float4 qr[16], acc[16];
    const float4* qp = reinterpret_cast<const float4*>(
        g_q + ((size_t)(b * SS + qi) * NH + h) * HD);
#pragma unroll
    for (int i = 0; i < 16; i++) { qr[i] = qp[i]; acc[i] = make_float4(0.f, 0.f, 0.f, 0.f); }

    float m = -FLT_MAX, l = 0.f;

    for (int k0 = 0; k0 < q0 + FBQ; k0 += FBK) {
        // cooperative tile load (float4, coalesced)
        for (int idx = tid; idx < FBK * (HD / 4); idx += FBQ) {
            const int row = idx >> 4;
            const int c   = idx & 15;
            const size_t g = ((size_t)(b * SS + k0 + row) * NKV + kvh) * HD + c * 4;
            *reinterpret_cast<float4*>(&Ks[row][c * 4]) = *reinterpret_cast<const float4*>(g_k + g);
            *reinterpret_cast<float4*>(&Vs[row][c * 4]) = *reinterpret_cast<const float4*>(g_v + g);
        }
        __syncthreads();

        // inner bound: full tiles process all FBK keys; diagonal tiles stop at qi
        const int jmax = (k0 + FBK <= q0) ? FBK : min(FBK, qi - k0 + 1);

#pragma unroll 2
        for (int j = 0; j < jmax; j++) {
            const float4* kr = reinterpret_cast<const float4*>(&Ks[j][0]);
            float s = 0.f;
#pragma unroll
            for (int i = 0; i < 16; i++) {
                float4 kv = kr[i];
                s += qr[i].x * kv.x + qr[i].y * kv.y + qr[i].z * kv.z + qr[i].w * kv.w;
            }
            const float sc = s * SCALE;
            if (sc > m) {                      // rare: lazy rescale on new max
                const float corr = __expf(m - sc);
                l *= corr;
#pragma unroll
                for (int i = 0; i < 16; i++) {
                    acc[i].x *= corr; acc[i].y *= corr;
                    acc[i].z *= corr; acc[i].w *= corr;
                }
                m = sc;
            }
            const float p = __expf(sc - m);
            l += p;
            const float4* vr = reinterpret_cast<const float4*>(&Vs[j][0]);
#pragma unroll
            for (int i = 0; i < 16; i++) {
                float4 vv = vr[i];
                acc[i].x += p * vv.x; acc[i].y += p * vv.y;
                acc[i].z += p * vv.z; acc[i].w += p * vv.w;
            }
        }
        __syncthreads();
    }

    const float inv = 1.f / l;
    float4* op = reinterpret_cast<float4*>(
        g_attn + ((size_t)(b * SS + qi) * NH + h) * HD);
#pragma unroll
    for (int i = 0; i < 16; i++) {
        float4 r = acc[i];
        r.x *= inv; r.y *= inv; r.z *= inv; r.w *= inv;
        op[i] = r;
    }
}

// ------------------------------- launch ---------------------------------------
extern "C" void kernel_launch(void* const* d_in, const int* in_sizes, int n_in,
                              void* d_out, int out_size)
{
    const float* hidden = (const float*)d_in[0];
    const float* cosv   = (const float*)d_in[1];
    const float* sinv   = (const float*)d_in[2];
    const float* Wq     = (const float*)d_in[3];
    const float* Wk     = (const float*)d_in[4];
    const float* Wv     = (const float*)d_in[5];
    const float* Wo     = (const float*)d_in[6];
    const float* qw     = (const float*)d_in[7];
    const float* kw     = (const float*)d_in[8];
    float* out          = (float*)d_out;

    float *pq, *pk, *pv, *pattn;
    cudaGetSymbolAddress((void**)&pq,    g_q);
    cudaGetSymbolAddress((void**)&pk,    g_k);
    cudaGetSymbolAddress((void**)&pv,    g_v);
    cudaGetSymbolAddress((void**)&pattn, g_attn);

    // Fused QKV projections (tensor-core 3xTF32): 24 n-blocks x 32 m-blocks
    gemm_qkv<<<dim3(24, MROWS / TBM), 256>>>(hidden, Wq, Wk, Wv, pq, pk, pv);

    // RMSNorm + RoPE on q and k
    {
        const int warps = MROWS * NH + MROWS * NKV;
        const int threads = warps * 32;
        norm_rope_kernel<<<(threads + 255) / 256, 256>>>(cosv, sinv, qw, kw);
    }

    // causal flash attention
    flash_kernel<<<dim3(SS / FBQ, BB * NH), FBQ>>>();

    // output projection -> d_out
    gemm_tc<<<dim3(HIDD / TBN, MROWS / TBM), 256>>>(pattn, Wo, out, HIDD, NH * HD);
}

// round 6
// speedup vs baseline: 1.2503x; 1.2431x over previous
#include <cuda_runtime.h>
#include <float.h>
#include <stdint.h>

// Problem constants
#define BB   2
#define SS   2048
#define HIDD 2048
#define NH   32
#define NKV  8
#define HD   64
#define MROWS (BB*SS)          // 4096
#define SCALE 0.125f           // HD^-0.5
#define EPS   1e-6f

// ---------------- scratch -----------------------------------------------------
__device__ float g_q[(size_t)MROWS * NH * HD];    // (4096, 2048)
__device__ float g_k[(size_t)MROWS * NKV * HD];   // (4096, 512)
__device__ float g_v[(size_t)MROWS * NKV * HD];   // (4096, 512)
__device__ float g_attn[(size_t)MROWS * NH * HD]; // (4096, 2048)

// ---------------- TF32 helpers ------------------------------------------------
__device__ __forceinline__ float2 split_tf32(float x) {
    uint32_t h;
    asm("cvt.rna.tf32.f32 %0, %1;" : "=r"(h) : "f"(x));
    float r = x - __uint_as_float(h);
    uint32_t l;
    asm("cvt.rna.tf32.f32 %0, %1;" : "=r"(l) : "f"(r));
    return make_float2(__uint_as_float(h), __uint_as_float(l));
}

__device__ __forceinline__ float tf32_hi(float x) {
    uint32_t h;
    asm("cvt.rna.tf32.f32 %0, %1;" : "=r"(h) : "f"(x));
    return __uint_as_float(h);
}

__device__ __forceinline__ void mma_tf32(float c[4],
    float a0, float a1, float a2, float a3, float b0, float b1)
{
    asm volatile(
        "mma.sync.aligned.m16n8k8.row.col.f32.tf32.tf32.f32 "
        "{%0,%1,%2,%3}, {%4,%5,%6,%7}, {%8,%9}, {%0,%1,%2,%3};"
        : "+f"(c[0]), "+f"(c[1]), "+f"(c[2]), "+f"(c[3])
        : "r"(__float_as_uint(a0)), "r"(__float_as_uint(a1)),
          "r"(__float_as_uint(a2)), "r"(__float_as_uint(a3)),
          "r"(__float_as_uint(b0)), "r"(__float_as_uint(b1)));
}

// ---------------- 2xTF32 tensor-core GEMM body:  C = A[M,K] @ B[N,K]^T ---------
// Block tile 128x128, TBK=8, double-buffered SMEM (one sync per stage).
// A stored as pre-split {hi,lo} float2 (stride 12: (12g+kc) mod 16 distinct per
// 16-lane phase -> conflict-free LDS.64). B stored hi-only float (stride 12:
// (12g+kc) mod 32 distinct over 32 lanes -> conflict-free LDS.32).
// 2xTF32 = ahi*bhi + alo*bhi  (drops ahi*blo: ~2.5e-4 rel err, under 1e-3).
#define TBM 128
#define TBN 128
#define TBK 8
#define SPA 12
#define SPB 12

__device__ __forceinline__ void gemm_body(
    const float* __restrict__ A, const float* __restrict__ Bm,
    float* __restrict__ C, int N, int K, int m0, int n0)
{
    __shared__ float2 As2[2][TBM][SPA];   // 24 KB
    __shared__ float  Bs [2][TBN][SPB];   // 12 KB

    const int t    = threadIdx.x;
    const int lane = t & 31;
    const int warp = t >> 5;                  // 0..7
    const int wm   = warp & 1;                // 2 warps along M
    const int wn   = warp >> 1;               // 4 warps along N
    const int grp  = lane >> 2;               // 0..7
    const int kc   = lane & 3;                // 0..3

    // loader: each thread owns one float4 of A and one of B per stage
    const int lr = t >> 1;                    // 0..127
    const int lq = (t & 1) * 4;               // 0 or 4
    const float* Ap = A  + (size_t)(m0 + lr) * K + lq;
    const float* Bp = Bm + (size_t)(n0 + lr) * K + lq;

    float acc[4][4][4];                       // [mt][nt][frag]
#pragma unroll
    for (int i = 0; i < 4; i++)
#pragma unroll
        for (int j = 0; j < 4; j++)
#pragma unroll
            for (int f = 0; f < 4; f++) acc[i][j][f] = 0.f;

    // preload stage 0
    {
        float4 ra = *reinterpret_cast<const float4*>(Ap);
        float4 rb = *reinterpret_cast<const float4*>(Bp);
        As2[0][lr][lq + 0] = split_tf32(ra.x);
        As2[0][lr][lq + 1] = split_tf32(ra.y);
        As2[0][lr][lq + 2] = split_tf32(ra.z);
        As2[0][lr][lq + 3] = split_tf32(ra.w);
        Bs[0][lr][lq + 0] = tf32_hi(rb.x);
        Bs[0][lr][lq + 1] = tf32_hi(rb.y);
        Bs[0][lr][lq + 2] = tf32_hi(rb.z);
        Bs[0][lr][lq + 3] = tf32_hi(rb.w);
    }
    __syncthreads();

    const int mrow = wm * 64 + grp;           // A fragment base row
    const int nrow = wn * 32 + grp;           // B fragment base row
    const int NT   = K / TBK;

#pragma unroll 2
    for (int kt = 0; kt < NT; kt++) {
        const int cur = kt & 1;
        const bool more = (kt + 1 < NT);
        float4 ra, rb;
        if (more) {                            // prefetch next stage early
            ra = *reinterpret_cast<const float4*>(Ap + (kt + 1) * TBK);
            rb = *reinterpret_cast<const float4*>(Bp + (kt + 1) * TBK);
        }

        float b0[4], b1[4];
#pragma unroll
        for (int nt = 0; nt < 4; nt++) {
            b0[nt] = Bs[cur][nrow + nt * 8][kc];
            b1[nt] = Bs[cur][nrow + nt * 8][kc + 4];
        }
#pragma unroll
        for (int mt = 0; mt < 4; mt++) {
            const int r = mrow + mt * 16;
            float2 a0 = As2[cur][r][kc];
            float2 a1 = As2[cur][r + 8][kc];
            float2 a2 = As2[cur][r][kc + 4];
            float2 a3 = As2[cur][r + 8][kc + 4];
#pragma unroll
            for (int nt = 0; nt < 4; nt++) {
                mma_tf32(acc[mt][nt], a0.x, a1.x, a2.x, a3.x, b0[nt], b1[nt]);
                mma_tf32(acc[mt][nt], a0.y, a1.y, a2.y, a3.y, b0[nt], b1[nt]);
            }
        }

        if (more) {
            const int nxt = cur ^ 1;
            As2[nxt][lr][lq + 0] = split_tf32(ra.x);
            As2[nxt][lr][lq + 1] = split_tf32(ra.y);
            As2[nxt][lr][lq + 2] = split_tf32(ra.z);
            As2[nxt][lr][lq + 3] = split_tf32(ra.w);
            Bs[nxt][lr][lq + 0] = tf32_hi(rb.x);
            Bs[nxt][lr][lq + 1] = tf32_hi(rb.y);
            Bs[nxt][lr][lq + 2] = tf32_hi(rb.z);
            Bs[nxt][lr][lq + 3] = tf32_hi(rb.w);
        }
        __syncthreads();
    }

    // epilogue
#pragma unroll
    for (int mt = 0; mt < 4; mt++) {
        const int row = m0 + wm * 64 + mt * 16 + grp;
#pragma unroll
        for (int nt = 0; nt < 4; nt++) {
            const int col = n0 + wn * 32 + nt * 8 + kc * 2;
            *reinterpret_cast<float2*>(C + (size_t)row * N + col) =
                make_float2(acc[mt][nt][0], acc[mt][nt][1]);
            *reinterpret_cast<float2*>(C + (size_t)(row + 8) * N + col) =
                make_float2(acc[mt][nt][2], acc[mt][nt][3]);
        }
    }
}

// Fused QKV projection: one launch covers Wq (16 n-blocks), Wk (4), Wv (4).
__global__ __launch_bounds__(256, 2) void gemm_qkv(
    const float* __restrict__ A,
    const float* __restrict__ Wq, const float* __restrict__ Wk,
    const float* __restrict__ Wv,
    float* __restrict__ Cq, float* __restrict__ Ck, float* __restrict__ Cv)
{
    const int bx = blockIdx.x;                // 0..23
    const int m0 = blockIdx.y * TBM;
    const float* Bm; float* C; int N, n0;
    if (bx < 16)      { Bm = Wq; C = Cq; N = NH  * HD; n0 = bx * TBN; }
    else if (bx < 20) { Bm = Wk; C = Ck; N = NKV * HD; n0 = (bx - 16) * TBN; }
    else              { Bm = Wv; C = Cv; N = NKV * HD; n0 = (bx - 20) * TBN; }
    gemm_body(A, Bm, C, N, HIDD, m0, n0);
}

__global__ __launch_bounds__(256, 2) void gemm_tc(
    const float* __restrict__ A, const float* __restrict__ Bm,
    float* __restrict__ C, int N, int K)
{
    gemm_body(A, Bm, C, N, K, blockIdx.y * TBM, blockIdx.x * TBN);
}

// ---------------- RMSNorm + RoPE over q and k head-rows -----------------------
__global__ void norm_rope_kernel(
    const float* __restrict__ cosv, const float* __restrict__ sinv,
    const float* __restrict__ qw,   const float* __restrict__ kw)
{
    const int gid  = blockIdx.x * blockDim.x + threadIdx.x;
    const int wid  = gid >> 5;
    const int lane = gid & 31;
    const int nqr  = MROWS * NH;
    const int ntot = nqr + MROWS * NKV;
    if (wid >= ntot) return;

    float* base;
    int bs;
    const float* w;
    if (wid < nqr) { base = g_q + (size_t)wid * HD;        bs = wid / NH;  w = qw; }
    else { int r = wid - nqr; base = g_k + (size_t)r * HD; bs = r / NKV;   w = kw; }

    float x0 = base[lane];
    float x1 = base[lane + 32];
    float ss = x0 * x0 + x1 * x1;
#pragma unroll
    for (int o = 16; o > 0; o >>= 1) ss += __shfl_xor_sync(0xffffffffu, ss, o);
    const float rinv = rsqrtf(ss * (1.0f / HD) + EPS);

    const float n0 = w[lane]      * (x0 * rinv);
    const float n1 = w[lane + 32] * (x1 * rinv);

    const float c0 = cosv[(size_t)bs * HD + lane];
    const float c1 = cosv[(size_t)bs * HD + lane + 32];
    const float s0 = sinv[(size_t)bs * HD + lane];
    const float s1 = sinv[(size_t)bs * HD + lane + 32];

    base[lane]      = n0 * c0 - n1 * s0;
    base[lane + 32] = n1 * c1 + n0 * s1;
}

// ---------------- causal flash attention (fp32, per-thread query row) ---------
#define FBQ 128
#define FBK 64
#define HDP (HD + 4)
__global__ __launch_bounds__(FBQ) void flash_kernel()
{
    const int bh  = blockIdx.y;
    const int b   = bh / NH;
    const int h   = bh % NH;
    const int kvh = h / (NH / NKV);
    const int q0  = blockIdx.x * FBQ;
    const int tid = threadIdx.x;
    const int qi  = q0 + tid;

    __shared__ float Ks[FBK][HDP];
    __shared__ float Vs[FBK][HDP];

    float4 qr[16], acc[16];
    const float4* qp = reinterpret_cast<const float4*>(
        g_q + ((size_t)(b * SS + qi) * NH + h) * HD);
#pragma unroll
    for (int i = 0; i < 16; i++) { qr[i] = qp[i]; acc[i] = make_float4(0.f, 0.f, 0.f, 0.f); }

    float m = -FLT_MAX, l = 0.f;

    for (int k0 = 0; k0 < q0 + FBQ; k0 += FBK) {
        for (int idx = tid; idx < FBK * (HD / 4); idx += FBQ) {
            const int row = idx >> 4;
            const int c   = idx & 15;
            const size_t g = ((size_t)(b * SS + k0 + row) * NKV + kvh) * HD + c * 4;
            *reinterpret_cast<float4*>(&Ks[row][c * 4]) = *reinterpret_cast<const float4*>(g_k + g);
            *reinterpret_cast<float4*>(&Vs[row][c * 4]) = *reinterpret_cast<const float4*>(g_v + g);
        }
        __syncthreads();

        const int jmax = (k0 + FBK <= q0) ? FBK : min(FBK, qi - k0 + 1);

#pragma unroll 2
        for (int j = 0; j < jmax; j++) {
            const float4* kr = reinterpret_cast<const float4*>(&Ks[j][0]);
            float s = 0.f;
#pragma unroll
            for (int i = 0; i < 16; i++) {
                float4 kv = kr[i];
                s += qr[i].x * kv.x + qr[i].y * kv.y + qr[i].z * kv.z + qr[i].w * kv.w;
            }
            const float sc = s * SCALE;
            if (sc > m) {
                const float corr = __expf(m - sc);
                l *= corr;
#pragma unroll
                for (int i = 0; i < 16; i++) {
                    acc[i].x *= corr; acc[i].y *= corr;
                    acc[i].z *= corr; acc[i].w *= corr;
                }
                m = sc;
            }
            const float p = __expf(sc - m);
            l += p;
            const float4* vr = reinterpret_cast<const float4*>(&Vs[j][0]);
#pragma unroll
            for (int i = 0; i < 16; i++) {
                float4 vv = vr[i];
                acc[i].x += p * vv.x; acc[i].y += p * vv.y;
                acc[i].z += p * vv.z; acc[i].w += p * vv.w;
            }
        }
        __syncthreads();
    }

    const float inv = 1.f / l;
    float4* op = reinterpret_cast<float4*>(
        g_attn + ((size_t)(b * SS + qi) * NH + h) * HD);
#pragma unroll
    for (int i = 0; i < 16; i++) {
        float4 r = acc[i];
        r.x *= inv; r.y *= inv; r.z *= inv; r.w *= inv;
        op[i] = r;
    }
}

// ------------------------------- launch ---------------------------------------
extern "C" void kernel_launch(void* const* d_in, const int* in_sizes, int n_in,
                              void* d_out, int out_size)
{
    const float* hidden = (const float*)d_in[0];
    const float* cosv   = (const float*)d_in[1];
    const float* sinv   = (const float*)d_in[2];
    const float* Wq     = (const float*)d_in[3];
    const float* Wk     = (const float*)d_in[4];
    const float* Wv     = (const float*)d_in[5];
    const float* Wo     = (const float*)d_in[6];
    const float* qw     = (const float*)d_in[7];
    const float* kw     = (const float*)d_in[8];
    float* out          = (float*)d_out;

    float *pq, *pk, *pv, *pattn;
    cudaGetSymbolAddress((void**)&pq,    g_q);
    cudaGetSymbolAddress((void**)&pk,    g_k);
    cudaGetSymbolAddress((void**)&pv,    g_v);
    cudaGetSymbolAddress((void**)&pattn, g_attn);

    // Fused QKV projections (tensor-core 2xTF32): 24 n-blocks x 32 m-blocks
    gemm_qkv<<<dim3(24, MROWS / TBM), 256>>>(hidden, Wq, Wk, Wv, pq, pk, pv);

    // RMSNorm + RoPE on q and k
    {
        const int warps = MROWS * NH + MROWS * NKV;
        const int threads = warps * 32;
        norm_rope_kernel<<<(threads + 255) / 256, 256>>>(cosv, sinv, qw, kw);
    }

    // causal flash attention
    flash_kernel<<<dim3(SS / FBQ, BB * NH), FBQ>>>();

    // output projection -> d_out
    gemm_tc<<<dim3(HIDD / TBN, MROWS / TBM), 256>>>(pattn, Wo, out, HIDD, NH * HD);
}

// round 7
// speedup vs baseline: 2.0065x; 1.6048x over previous
#include <cuda_runtime.h>
#include <float.h>
#include <stdint.h>

// Problem constants
#define BB   2
#define SS   2048
#define HIDD 2048
#define NH   32
#define NKV  8
#define HD   64
#define MROWS (BB*SS)          // 4096
#define SCALE 0.125f           // HD^-0.5
#define EPS   1e-6f

// ---------------- scratch -----------------------------------------------------
__device__ float g_q[(size_t)MROWS * NH * HD];    // (4096, 2048)
__device__ float g_k[(size_t)MROWS * NKV * HD];   // (4096, 512)
__device__ float g_v[(size_t)MROWS * NKV * HD];   // (4096, 512)
__device__ float g_attn[(size_t)MROWS * NH * HD]; // (4096, 2048)

// ---------------- TF32 helpers ------------------------------------------------
__device__ __forceinline__ float2 split_tf32(float x) {
    uint32_t h;
    asm("cvt.rna.tf32.f32 %0, %1;" : "=r"(h) : "f"(x));
    float r = x - __uint_as_float(h);
    uint32_t l;
    asm("cvt.rna.tf32.f32 %0, %1;" : "=r"(l) : "f"(r));
    return make_float2(__uint_as_float(h), __uint_as_float(l));
}

__device__ __forceinline__ float tf32_hi(float x) {
    uint32_t h;
    asm("cvt.rna.tf32.f32 %0, %1;" : "=r"(h) : "f"(x));
    return __uint_as_float(h);
}

__device__ __forceinline__ void mma_tf32(float c[4],
    float a0, float a1, float a2, float a3, float b0, float b1)
{
    asm volatile(
        "mma.sync.aligned.m16n8k8.row.col.f32.tf32.tf32.f32 "
        "{%0,%1,%2,%3}, {%4,%5,%6,%7}, {%8,%9}, {%0,%1,%2,%3};"
        : "+f"(c[0]), "+f"(c[1]), "+f"(c[2]), "+f"(c[3])
        : "r"(__float_as_uint(a0)), "r"(__float_as_uint(a1)),
          "r"(__float_as_uint(a2)), "r"(__float_as_uint(a3)),
          "r"(__float_as_uint(b0)), "r"(__float_as_uint(b1)));
}

// ---------------- 2xTF32 tensor-core GEMM body:  C = A[M,K] @ B[N,K]^T ---------
#define TBM 128
#define TBN 128
#define TBK 8
#define SPA 12
#define SPB 12

__device__ __forceinline__ void gemm_body(
    const float* __restrict__ A, const float* __restrict__ Bm,
    float* __restrict__ C, int N, int K, int m0, int n0)
{
    __shared__ float2 As2[2][TBM][SPA];   // 24 KB
    __shared__ float  Bs [2][TBN][SPB];   // 12 KB

    const int t    = threadIdx.x;
    const int lane = t & 31;
    const int warp = t >> 5;
    const int wm   = warp & 1;
    const int wn   = warp >> 1;
    const int grp  = lane >> 2;
    const int kc   = lane & 3;

    const int lr = t >> 1;
    const int lq = (t & 1) * 4;
    const float* Ap = A  + (size_t)(m0 + lr) * K + lq;
    const float* Bp = Bm + (size_t)(n0 + lr) * K + lq;

    float acc[4][4][4];
#pragma unroll
    for (int i = 0; i < 4; i++)
#pragma unroll
        for (int j = 0; j < 4; j++)
#pragma unroll
            for (int f = 0; f < 4; f++) acc[i][j][f] = 0.f;

    {
        float4 ra = *reinterpret_cast<const float4*>(Ap);
        float4 rb = *reinterpret_cast<const float4*>(Bp);
        As2[0][lr][lq + 0] = split_tf32(ra.x);
        As2[0][lr][lq + 1] = split_tf32(ra.y);
        As2[0][lr][lq + 2] = split_tf32(ra.z);
        As2[0][lr][lq + 3] = split_tf32(ra.w);
        Bs[0][lr][lq + 0] = tf32_hi(rb.x);
        Bs[0][lr][lq + 1] = tf32_hi(rb.y);
        Bs[0][lr][lq + 2] = tf32_hi(rb.z);
        Bs[0][lr][lq + 3] = tf32_hi(rb.w);
    }
    __syncthreads();

    const int mrow = wm * 64 + grp;
    const int nrow = wn * 32 + grp;
    const int NT   = K / TBK;

#pragma unroll 2
    for (int kt = 0; kt < NT; kt++) {
        const int cur = kt & 1;
        const bool more = (kt + 1 < NT);
        float4 ra, rb;
        if (more) {
            ra = *reinterpret_cast<const float4*>(Ap + (kt + 1) * TBK);
            rb = *reinterpret_cast<const float4*>(Bp + (kt + 1) * TBK);
        }

        float b0[4], b1[4];
#pragma unroll
        for (int nt = 0; nt < 4; nt++) {
            b0[nt] = Bs[cur][nrow + nt * 8][kc];
            b1[nt] = Bs[cur][nrow + nt * 8][kc + 4];
        }
#pragma unroll
        for (int mt = 0; mt < 4; mt++) {
            const int r = mrow + mt * 16;
            float2 a0 = As2[cur][r][kc];
            float2 a1 = As2[cur][r + 8][kc];
            float2 a2 = As2[cur][r][kc + 4];
            float2 a3 = As2[cur][r + 8][kc + 4];
#pragma unroll
            for (int nt = 0; nt < 4; nt++) {
                mma_tf32(acc[mt][nt], a0.x, a1.x, a2.x, a3.x, b0[nt], b1[nt]);
                mma_tf32(acc[mt][nt], a0.y, a1.y, a2.y, a3.y, b0[nt], b1[nt]);
            }
        }

        if (more) {
            const int nxt = cur ^ 1;
            As2[nxt][lr][lq + 0] = split_tf32(ra.x);
            As2[nxt][lr][lq + 1] = split_tf32(ra.y);
            As2[nxt][lr][lq + 2] = split_tf32(ra.z);
            As2[nxt][lr][lq + 3] = split_tf32(ra.w);
            Bs[nxt][lr][lq + 0] = tf32_hi(rb.x);
            Bs[nxt][lr][lq + 1] = tf32_hi(rb.y);
            Bs[nxt][lr][lq + 2] = tf32_hi(rb.z);
            Bs[nxt][lr][lq + 3] = tf32_hi(rb.w);
        }
        __syncthreads();
    }

#pragma unroll
    for (int mt = 0; mt < 4; mt++) {
        const int row = m0 + wm * 64 + mt * 16 + grp;
#pragma unroll
        for (int nt = 0; nt < 4; nt++) {
            const int col = n0 + wn * 32 + nt * 8 + kc * 2;
            *reinterpret_cast<float2*>(C + (size_t)row * N + col) =
                make_float2(acc[mt][nt][0], acc[mt][nt][1]);
            *reinterpret_cast<float2*>(C + (size_t)(row + 8) * N + col) =
                make_float2(acc[mt][nt][2], acc[mt][nt][3]);
        }
    }
}

__global__ __launch_bounds__(256, 2) void gemm_qkv(
    const float* __restrict__ A,
    const float* __restrict__ Wq, const float* __restrict__ Wk,
    const float* __restrict__ Wv,
    float* __restrict__ Cq, float* __restrict__ Ck, float* __restrict__ Cv)
{
    const int bx = blockIdx.x;
    const int m0 = blockIdx.y * TBM;
    const float* Bm; float* C; int N, n0;
    if (bx < 16)      { Bm = Wq; C = Cq; N = NH  * HD; n0 = bx * TBN; }
    else if (bx < 20) { Bm = Wk; C = Ck; N = NKV * HD; n0 = (bx - 16) * TBN; }
    else              { Bm = Wv; C = Cv; N = NKV * HD; n0 = (bx - 20) * TBN; }
    gemm_body(A, Bm, C, N, HIDD, m0, n0);
}

__global__ __launch_bounds__(256, 2) void gemm_tc(
    const float* __restrict__ A, const float* __restrict__ Bm,
    float* __restrict__ C, int N, int K)
{
    gemm_body(A, Bm, C, N, K, blockIdx.y * TBM, blockIdx.x * TBN);
}

// ---------------- RMSNorm + RoPE over q and k head-rows -----------------------
__global__ void norm_rope_kernel(
    const float* __restrict__ cosv, const float* __restrict__ sinv,
    const float* __restrict__ qw,   const float* __restrict__ kw)
{
    const int gid  = blockIdx.x * blockDim.x + threadIdx.x;
    const int wid  = gid >> 5;
    const int lane = gid & 31;
    const int nqr  = MROWS * NH;
    const int ntot = nqr + MROWS * NKV;
    if (wid >= ntot) return;

    float* base;
    int bs;
    const float* w;
    if (wid < nqr) { base = g_q + (size_t)wid * HD;        bs = wid / NH;  w = qw; }
    else { int r = wid - nqr; base = g_k + (size_t)r * HD; bs = r / NKV;   w = kw; }

    float x0 = base[lane];
    float x1 = base[lane + 32];
    float ss = x0 * x0 + x1 * x1;
#pragma unroll
    for (int o = 16; o > 0; o >>= 1) ss += __shfl_xor_sync(0xffffffffu, ss, o);
    const float rinv = rsqrtf(ss * (1.0f / HD) + EPS);

    const float n0 = w[lane]      * (x0 * rinv);
    const float n1 = w[lane + 32] * (x1 * rinv);

    const float c0 = cosv[(size_t)bs * HD + lane];
    const float c1 = cosv[(size_t)bs * HD + lane + 32];
    const float s0 = sinv[(size_t)bs * HD + lane];
    const float s1 = sinv[(size_t)bs * HD + lane + 32];

    base[lane]      = n0 * c0 - n1 * s0;
    base[lane + 32] = n1 * c1 + n0 * s1;
}

// ---------------- tensor-core causal flash attention ---------------------------
// 128 q-rows/block, 8 warps x 16 rows. Per 64-key tile:
//   S = Qhi @ (Khi + Klo)^T   (2xTF32, K-side split)
//   online softmax in m16n8 C-fragment layout (4-lane row groups)
//   P staged tf32 through per-warp SMEM (C-layout -> A-layout)
//   O += P @ (Vhi + Vlo)      (2xTF32, V-side split)
// SMEM strides: K=76 (row access: (12g+kc)%32 distinct), V=72 (col access:
// (8kc+g)%32 distinct), P=76 ((12g+kc)%32 distinct).
#define FBQ 128
#define FBK 64
#define KSP 76
#define VSP 72
#define PSP 76
#define FLASH_SMEM ((2*64*KSP + 2*64*VSP + 128*PSP) * 4)   // 114688 B

__global__ __launch_bounds__(256, 1) void flash_mma_kernel()
{
    const int bh  = blockIdx.y;
    const int b   = bh / NH;
    const int h   = bh % NH;
    const int kvh = h / (NH / NKV);
    const int q0  = blockIdx.x * FBQ;
    const int tid = threadIdx.x;
    const int lane = tid & 31;
    const int w    = tid >> 5;          // 0..7
    const int grp  = lane >> 2;         // 0..7
    const int kc   = lane & 3;          // 0..3

    extern __shared__ float sm[];
    float* Khi = sm;
    float* Klo = Khi + 64 * KSP;
    float* Vhi = Klo + 64 * KSP;
    float* Vlo = Vhi + 64 * VSP;
    float* Ps  = Vlo + 64 * VSP;        // 128 x PSP
    float* Pw  = Ps + (w * 16) * PSP;   // per-warp region

    // Q A-fragments (hi only, pre-scaled by SCALE), rows qrow0 and qrow0+8
    const int qrow0 = q0 + w * 16 + grp;
    const float* Q0 = g_q + ((size_t)(b * SS + qrow0) * NH + h) * HD;
    const float* Q1 = Q0 + (size_t)8 * NH * HD;
    float aQ[8][4];
#pragma unroll
    for (int ks = 0; ks < 8; ks++) {
        aQ[ks][0] = tf32_hi(Q0[ks * 8 + kc]     * SCALE);
        aQ[ks][1] = tf32_hi(Q1[ks * 8 + kc]     * SCALE);
        aQ[ks][2] = tf32_hi(Q0[ks * 8 + kc + 4] * SCALE);
        aQ[ks][3] = tf32_hi(Q1[ks * 8 + kc + 4] * SCALE);
    }

    float c_o[8][4];
#pragma unroll
    for (int nt = 0; nt < 8; nt++)
#pragma unroll
        for (int f = 0; f < 4; f++) c_o[nt][f] = 0.f;

    float m0 = -FLT_MAX, m1 = -FLT_MAX, l0 = 0.f, l1 = 0.f;

    for (int k0 = 0; k0 < q0 + FBQ; k0 += FBK) {
        // -------- load + split K,V tile (64 rows x 64 dims) ------------------
#pragma unroll
        for (int i = 0; i < 4; i++) {
            const int linear = tid + i * 256;        // 0..1023 float4s
            const int row = linear >> 4;
            const int c4  = (linear & 15) << 2;
            const size_t g = ((size_t)(b * SS + k0 + row) * NKV + kvh) * HD + c4;
            float4 kk = *reinterpret_cast<const float4*>(g_k + g);
            float4 vv = *reinterpret_cast<const float4*>(g_v + g);
            float2 sx = split_tf32(kk.x), sy = split_tf32(kk.y),
                   sz = split_tf32(kk.z), sw = split_tf32(kk.w);
            *reinterpret_cast<float4*>(Khi + row * KSP + c4) = make_float4(sx.x, sy.x, sz.x, sw.x);
            *reinterpret_cast<float4*>(Klo + row * KSP + c4) = make_float4(sx.y, sy.y, sz.y, sw.y);
            sx = split_tf32(vv.x); sy = split_tf32(vv.y);
            sz = split_tf32(vv.z); sw = split_tf32(vv.w);
            *reinterpret_cast<float4*>(Vhi + row * VSP + c4) = make_float4(sx.x, sy.x, sz.x, sw.x);
            *reinterpret_cast<float4*>(Vlo + row * VSP + c4) = make_float4(sx.y, sy.y, sz.y, sw.y);
        }
        __syncthreads();

        // -------- S = Q @ K^T (2xTF32) ---------------------------------------
        float c_s[8][4];
#pragma unroll
        for (int nt = 0; nt < 8; nt++)
#pragma unroll
            for (int f = 0; f < 4; f++) c_s[nt][f] = 0.f;

#pragma unroll
        for (int ks = 0; ks < 8; ks++) {
#pragma unroll
            for (int nt = 0; nt < 8; nt++) {
                const int krow = nt * 8 + grp;
                const float bh0 = Khi[krow * KSP + ks * 8 + kc];
                const float bh1 = Khi[krow * KSP + ks * 8 + kc + 4];
                const float bl0 = Klo[krow * KSP + ks * 8 + kc];
                const float bl1 = Klo[krow * KSP + ks * 8 + kc + 4];
                mma_tf32(c_s[nt], aQ[ks][0], aQ[ks][1], aQ[ks][2], aQ[ks][3], bh0, bh1);
                mma_tf32(c_s[nt], aQ[ks][0], aQ[ks][1], aQ[ks][2], aQ[ks][3], bl0, bl1);
            }
        }

        // -------- causal mask (diagonal tiles only) --------------------------
        if (k0 + FBK > q0) {
#pragma unroll
            for (int nt = 0; nt < 8; nt++) {
                const int col = k0 + nt * 8 + kc * 2;
                if (col     > qrow0)     c_s[nt][0] = -FLT_MAX;
                if (col + 1 > qrow0)     c_s[nt][1] = -FLT_MAX;
                if (col     > qrow0 + 8) c_s[nt][2] = -FLT_MAX;
                if (col + 1 > qrow0 + 8) c_s[nt][3] = -FLT_MAX;
            }
        }

        // -------- online softmax in C-fragment layout ------------------------
        float mx0 = -FLT_MAX, mx1 = -FLT_MAX;
#pragma unroll
        for (int nt = 0; nt < 8; nt++) {
            mx0 = fmaxf(mx0, fmaxf(c_s[nt][0], c_s[nt][1]));
            mx1 = fmaxf(mx1, fmaxf(c_s[nt][2], c_s[nt][3]));
        }
        mx0 = fmaxf(mx0, __shfl_xor_sync(0xffffffffu, mx0, 1));
        mx0 = fmaxf(mx0, __shfl_xor_sync(0xffffffffu, mx0, 2));
        mx1 = fmaxf(mx1, __shfl_xor_sync(0xffffffffu, mx1, 1));
        mx1 = fmaxf(mx1, __shfl_xor_sync(0xffffffffu, mx1, 2));

        const float mn0 = fmaxf(m0, mx0);
        const float mn1 = fmaxf(m1, mx1);
        const float cor0 = __expf(m0 - mn0);
        const float cor1 = __expf(m1 - mn1);
        m0 = mn0; m1 = mn1;

        float rs0 = 0.f, rs1 = 0.f;
#pragma unroll
        for (int nt = 0; nt < 8; nt++) {
            c_s[nt][0] = __expf(c_s[nt][0] - mn0);
            c_s[nt][1] = __expf(c_s[nt][1] - mn0);
            c_s[nt][2] = __expf(c_s[nt][2] - mn1);
            c_s[nt][3] = __expf(c_s[nt][3] - mn1);
            rs0 += c_s[nt][0] + c_s[nt][1];
            rs1 += c_s[nt][2] + c_s[nt][3];
        }
        rs0 += __shfl_xor_sync(0xffffffffu, rs0, 1);
        rs0 += __shfl_xor_sync(0xffffffffu, rs0, 2);
        rs1 += __shfl_xor_sync(0xffffffffu, rs1, 1);
        rs1 += __shfl_xor_sync(0xffffffffu, rs1, 2);
        l0 = l0 * cor0 + rs0;
        l1 = l1 * cor1 + rs1;

#pragma unroll
        for (int nt = 0; nt < 8; nt++) {
            c_o[nt][0] *= cor0; c_o[nt][1] *= cor0;
            c_o[nt][2] *= cor1; c_o[nt][3] *= cor1;
        }

        // -------- stage P (tf32) to per-warp SMEM: C-layout -> A-layout ------
#pragma unroll
        for (int nt = 0; nt < 8; nt++) {
            *reinterpret_cast<float2*>(Pw + grp * PSP + nt * 8 + kc * 2) =
                make_float2(tf32_hi(c_s[nt][0]), tf32_hi(c_s[nt][1]));
            *reinterpret_cast<float2*>(Pw + (grp + 8) * PSP + nt * 8 + kc * 2) =
                make_float2(tf32_hi(c_s[nt][2]), tf32_hi(c_s[nt][3]));
        }
        __syncwarp();

        // -------- O += P @ V (2xTF32) ----------------------------------------
#pragma unroll
        for (int ks = 0; ks < 8; ks++) {
            const float a0 = Pw[grp * PSP + ks * 8 + kc];
            const float a1 = Pw[(grp + 8) * PSP + ks * 8 + kc];
            const float a2 = Pw[grp * PSP + ks * 8 + kc + 4];
            const float a3 = Pw[(grp + 8) * PSP + ks * 8 + kc + 4];
#pragma unroll
            for (int nt = 0; nt < 8; nt++) {
                const int d = nt * 8 + grp;
                const float bh0 = Vhi[(ks * 8 + kc) * VSP + d];
                const float bh1 = Vhi[(ks * 8 + kc + 4) * VSP + d];
                const float bl0 = Vlo[(ks * 8 + kc) * VSP + d];
                const float bl1 = Vlo[(ks * 8 + kc + 4) * VSP + d];
                mma_tf32(c_o[nt], a0, a1, a2, a3, bh0, bh1);
                mma_tf32(c_o[nt], a0, a1, a2, a3, bl0, bl1);
            }
        }
        __syncthreads();   // protect K/V/P tiles before next iteration
    }

    // -------- epilogue: normalize and store ----------------------------------
    const float inv0 = 1.f / l0;
    const float inv1 = 1.f / l1;
    float* O0 = g_attn + ((size_t)(b * SS + qrow0) * NH + h) * HD;
    float* O1 = O0 + (size_t)8 * NH * HD;
#pragma unroll
    for (int nt = 0; nt < 8; nt++) {
        *reinterpret_cast<float2*>(O0 + nt * 8 + kc * 2) =
            make_float2(c_o[nt][0] * inv0, c_o[nt][1] * inv0);
        *reinterpret_cast<float2*>(O1 + nt * 8 + kc * 2) =
            make_float2(c_o[nt][2] * inv1, c_o[nt][3] * inv1);
    }
}

// ------------------------------- launch ---------------------------------------
extern "C" void kernel_launch(void* const* d_in, const int* in_sizes, int n_in,
                              void* d_out, int out_size)
{
    const float* hidden = (const float*)d_in[0];
    const float* cosv   = (const float*)d_in[1];
    const float* sinv   = (const float*)d_in[2];
    const float* Wq     = (const float*)d_in[3];
    const float* Wk     = (const float*)d_in[4];
    const float* Wv     = (const float*)d_in[5];
    const float* Wo     = (const float*)d_in[6];
    const float* qw     = (const float*)d_in[7];
    const float* kw     = (const float*)d_in[8];
    float* out          = (float*)d_out;

    float *pq, *pk, *pv, *pattn;
    cudaGetSymbolAddress((void**)&pq,    g_q);
    cudaGetSymbolAddress((void**)&pk,    g_k);
    cudaGetSymbolAddress((void**)&pv,    g_v);
    cudaGetSymbolAddress((void**)&pattn, g_attn);

    // Fused QKV projections (tensor-core 2xTF32)
    gemm_qkv<<<dim3(24, MROWS / TBM), 256>>>(hidden, Wq, Wk, Wv, pq, pk, pv);

    // RMSNorm + RoPE on q and k
    {
        const int warps = MROWS * NH + MROWS * NKV;
        const int threads = warps * 32;
        norm_rope_kernel<<<(threads + 255) / 256, 256>>>(cosv, sinv, qw, kw);
    }

    // tensor-core causal flash attention (dynamic smem 112 KB)
    cudaFuncSetAttribute(flash_mma_kernel,
                         cudaFuncAttributeMaxDynamicSharedMemorySize, FLASH_SMEM);
    flash_mma_kernel<<<dim3(SS / FBQ, BB * NH), 256, FLASH_SMEM>>>();

    // output projection -> d_out
    gemm_tc<<<dim3(HIDD / TBN, MROWS / TBM), 256>>>(pattn, Wo, out, HIDD, NH * HD);
}

// round 8
// speedup vs baseline: 2.1911x; 1.0920x over previous
#include <cuda_runtime.h>
#include <float.h>
#include <stdint.h>

// Problem constants
#define BB   2
#define SS   2048
#define HIDD 2048
#define NH   32
#define NKV  8
#define HD   64
#define MROWS (BB*SS)          // 4096
#define SCALE 0.125f           // HD^-0.5
#define EPS   1e-6f

// ---------------- scratch -----------------------------------------------------
__device__ float  g_q[(size_t)MROWS * NH * HD];      // (4096, 2048)
__device__ float  g_k[(size_t)MROWS * NKV * HD];     // (4096, 512)
__device__ float  g_v[(size_t)MROWS * NKV * HD];     // (4096, 512)
__device__ float2 g_hid2[(size_t)MROWS * HIDD];      // pre-split hidden {hi,lo}
__device__ float2 g_attn2[(size_t)MROWS * NH * HD];  // pre-split attn {hi,lo}
__device__ float  g_wq_hi[(size_t)NH  * HD * HIDD];
__device__ float  g_wk_hi[(size_t)NKV * HD * HIDD];
__device__ float  g_wv_hi[(size_t)NKV * HD * HIDD];
__device__ float  g_wo_hi[(size_t)HIDD * NH * HD];

// ---------------- TF32 helpers ------------------------------------------------
__device__ __forceinline__ float2 split_tf32(float x) {
    uint32_t h;
    asm("cvt.rna.tf32.f32 %0, %1;" : "=r"(h) : "f"(x));
    float r = x - __uint_as_float(h);
    uint32_t l;
    asm("cvt.rna.tf32.f32 %0, %1;" : "=r"(l) : "f"(r));
    return make_float2(__uint_as_float(h), __uint_as_float(l));
}

__device__ __forceinline__ float tf32_hi(float x) {
    uint32_t h;
    asm("cvt.rna.tf32.f32 %0, %1;" : "=r"(h) : "f"(x));
    return __uint_as_float(h);
}

__device__ __forceinline__ void mma_tf32(float c[4],
    float a0, float a1, float a2, float a3, float b0, float b1)
{
    asm volatile(
        "mma.sync.aligned.m16n8k8.row.col.f32.tf32.tf32.f32 "
        "{%0,%1,%2,%3}, {%4,%5,%6,%7}, {%8,%9}, {%0,%1,%2,%3};"
        : "+f"(c[0]), "+f"(c[1]), "+f"(c[2]), "+f"(c[3])
        : "r"(__float_as_uint(a0)), "r"(__float_as_uint(a1)),
          "r"(__float_as_uint(a2)), "r"(__float_as_uint(a3)),
          "r"(__float_as_uint(b0)), "r"(__float_as_uint(b1)));
}

// ---------------- prep passes --------------------------------------------------
__global__ void split_pass4(const float4* __restrict__ src, float4* __restrict__ dst, int n4)
{
    const int i = blockIdx.x * blockDim.x + threadIdx.x;
    if (i >= n4) return;
    float4 v = src[i];
    float2 a = split_tf32(v.x), b = split_tf32(v.y);
    float2 c = split_tf32(v.z), d = split_tf32(v.w);
    dst[i * 2 + 0] = make_float4(a.x, a.y, b.x, b.y);
    dst[i * 2 + 1] = make_float4(c.x, c.y, d.x, d.y);
}

__global__ void hi_pass4(const float4* __restrict__ src, float4* __restrict__ dst, int n4)
{
    const int i = blockIdx.x * blockDim.x + threadIdx.x;
    if (i >= n4) return;
    float4 v = src[i];
    dst[i] = make_float4(tf32_hi(v.x), tf32_hi(v.y), tf32_hi(v.z), tf32_hi(v.w));
}

// ---------------- cp.async 2xTF32 GEMM:  C = A[M,K] @ B[N,K]^T ------------------
// A pre-split float2{hi,lo}; B pre-rounded hi float. Block tile 128x128, TBK=8,
// 4-stage cp.async ring, one barrier per stage, no loader registers/CVTs.
// Strides SPA/SPB=12: (12*grp+kc) mod 32 distinct -> conflict-free LDS.
#define TBK 8
#define NSTAGE 4
#define SPA 12                       // float2 per A row
#define SPB 12                       // float  per B row
#define ASTAGE_F2 (128 * SPA)        // 1536 float2
#define BSTAGE_F  (128 * SPB)        // 1536 float
#define ASTAGE_B  (ASTAGE_F2 * 8)    // 12288 bytes
#define BSTAGE_B  (BSTAGE_F * 4)     // 6144 bytes
#define GEMM_SMEM (NSTAGE * (ASTAGE_B + BSTAGE_B))   // 73728 bytes

__device__ __forceinline__ void cp16(uint32_t dst, const void* src) {
    asm volatile("cp.async.cg.shared.global [%0], [%1], 16;" :: "r"(dst), "l"(src));
}

__device__ __forceinline__ void gemm_body_async(
    const float2* __restrict__ A2, const float* __restrict__ Bh,
    float* __restrict__ C, int N, int K, int m0, int n0)
{
    extern __shared__ float dynsm[];
    float2* Asm = reinterpret_cast<float2*>(dynsm);            // [NSTAGE][128][SPA]
    float*  Bsm = dynsm + NSTAGE * ASTAGE_F2 * 2;              // [NSTAGE][128][SPB]
    const uint32_t aS = (uint32_t)__cvta_generic_to_shared(dynsm);
    const uint32_t bS = aS + NSTAGE * ASTAGE_B;

    const int t    = threadIdx.x;
    const int lane = t & 31;
    const int warp = t >> 5;
    const int wm   = warp & 1;
    const int wn   = warp >> 1;
    const int grp  = lane >> 2;
    const int kc   = lane & 3;

    // loader: 2 A chunks (rows ar, ar+64) + 1 B chunk per stage, 16B each
    const int ar = t >> 2, ac = t & 3;            // A: 4 chunks/row
    const int br = t >> 1, bc = t & 1;            // B: 2 chunks/row
    const float2* Ag0 = A2 + (size_t)(m0 + ar) * K + ac * 2;
    const float2* Ag1 = A2 + (size_t)(m0 + ar + 64) * K + ac * 2;
    const float*  Bg  = Bh + (size_t)(n0 + br) * K + bc * 4;
    const uint32_t Ad0 = aS + (ar * SPA + ac * 2) * 8;
    const uint32_t Ad1 = aS + ((ar + 64) * SPA + ac * 2) * 8;
    const uint32_t Bd  = bS + (br * SPB + bc * 4) * 4;

    float acc[4][4][4];
#pragma unroll
    for (int i = 0; i < 4; i++)
#pragma unroll
        for (int j = 0; j < 4; j++)
#pragma unroll
            for (int f = 0; f < 4; f++) acc[i][j][f] = 0.f;

    const int NT = K / TBK;

    // prologue: fill NSTAGE-1 stages
#pragma unroll
    for (int s = 0; s < NSTAGE - 1; s++) {
        const int koff = s * TBK;
        cp16(Ad0 + s * ASTAGE_B, Ag0 + koff);
        cp16(Ad1 + s * ASTAGE_B, Ag1 + koff);
        cp16(Bd  + s * BSTAGE_B, Bg  + koff);
        asm volatile("cp.async.commit_group;" ::: "memory");
    }

    const int mrow = wm * 64 + grp;
    const int nrow = wn * 32 + grp;

#pragma unroll 4
    for (int kt = 0; kt < NT; kt++) {
        asm volatile("cp.async.wait_group %0;" :: "n"(NSTAGE - 2) : "memory");
        __syncthreads();

        // issue stage kt+NSTAGE-1 (overwrites stage consumed at kt-1; barrier above protects)
        const int kn = kt + NSTAGE - 1;
        if (kn < NT) {
            const int s = kn & (NSTAGE - 1);
            const int koff = kn * TBK;
            cp16(Ad0 + s * ASTAGE_B, Ag0 + koff);
            cp16(Ad1 + s * ASTAGE_B, Ag1 + koff);
            cp16(Bd  + s * BSTAGE_B, Bg  + koff);
        }
        asm volatile("cp.async.commit_group;" ::: "memory");

        // compute on stage kt
        const int st = kt & (NSTAGE - 1);
        const float2* As  = Asm + st * ASTAGE_F2;
        const float*  Bs2 = Bsm + st * BSTAGE_F;

        float b0[4], b1[4];
#pragma unroll
        for (int nt = 0; nt < 4; nt++) {
            b0[nt] = Bs2[(nrow + nt * 8) * SPB + kc];
            b1[nt] = Bs2[(nrow + nt * 8) * SPB + kc + 4];
        }
#pragma unroll
        for (int mt = 0; mt < 4; mt++) {
            const int r = mrow + mt * 16;
            float2 a0 = As[r * SPA + kc];
            float2 a1 = As[(r + 8) * SPA + kc];
            float2 a2 = As[r * SPA + kc + 4];
            float2 a3 = As[(r + 8) * SPA + kc + 4];
#pragma unroll
            for (int nt = 0; nt < 4; nt++) {
                mma_tf32(acc[mt][nt], a0.x, a1.x, a2.x, a3.x, b0[nt], b1[nt]);
                mma_tf32(acc[mt][nt], a0.y, a1.y, a2.y, a3.y, b0[nt], b1[nt]);
            }
        }
    }

    // epilogue
#pragma unroll
    for (int mt = 0; mt < 4; mt++) {
        const int row = m0 + wm * 64 + mt * 16 + grp;
#pragma unroll
        for (int nt = 0; nt < 4; nt++) {
            const int col = n0 + wn * 32 + nt * 8 + kc * 2;
            *reinterpret_cast<float2*>(C + (size_t)row * N + col) =
                make_float2(acc[mt][nt][0], acc[mt][nt][1]);
            *reinterpret_cast<float2*>(C + (size_t)(row + 8) * N + col) =
                make_float2(acc[mt][nt][2], acc[mt][nt][3]);
        }
    }
}

__global__ __launch_bounds__(256, 2) void gemm_qkv_async(
    const float2* __restrict__ A2,
    const float* __restrict__ Wqh, const float* __restrict__ Wkh,
    const float* __restrict__ Wvh,
    float* __restrict__ Cq, float* __restrict__ Ck, float* __restrict__ Cv)
{
    const int bx = blockIdx.x;                // 0..23
    const int m0 = blockIdx.y * 128;
    const float* Bh; float* C; int N, n0;
    if (bx < 16)      { Bh = Wqh; C = Cq; N = NH  * HD; n0 = bx * 128; }
    else if (bx < 20) { Bh = Wkh; C = Ck; N = NKV * HD; n0 = (bx - 16) * 128; }
    else              { Bh = Wvh; C = Cv; N = NKV * HD; n0 = (bx - 20) * 128; }
    gemm_body_async(A2, Bh, C, N, HIDD, m0, n0);
}

__global__ __launch_bounds__(256, 2) void gemm_o_async(
    const float2* __restrict__ A2, const float* __restrict__ Bh,
    float* __restrict__ C, int N, int K)
{
    gemm_body_async(A2, Bh, C, N, K, blockIdx.y * 128, blockIdx.x * 128);
}

// ---------------- RMSNorm + RoPE over q and k head-rows -----------------------
__global__ void norm_rope_kernel(
    const float* __restrict__ cosv, const float* __restrict__ sinv,
    const float* __restrict__ qw,   const float* __restrict__ kw)
{
    const int gid  = blockIdx.x * blockDim.x + threadIdx.x;
    const int wid  = gid >> 5;
    const int lane = gid & 31;
    const int nqr  = MROWS * NH;
    const int ntot = nqr + MROWS * NKV;
    if (wid >= ntot) return;

    float* base;
    int bs;
    const float* w;
    if (wid < nqr) { base = g_q + (size_t)wid * HD;        bs = wid / NH;  w = qw; }
    else { int r = wid - nqr; base = g_k + (size_t)r * HD; bs = r / NKV;   w = kw; }

    float x0 = base[lane];
    float x1 = base[lane + 32];
    float ss = x0 * x0 + x1 * x1;
#pragma unroll
    for (int o = 16; o > 0; o >>= 1) ss += __shfl_xor_sync(0xffffffffu, ss, o);
    const float rinv = rsqrtf(ss * (1.0f / HD) + EPS);

    const float n0 = w[lane]      * (x0 * rinv);
    const float n1 = w[lane + 32] * (x1 * rinv);

    const float c0 = cosv[(size_t)bs * HD + lane];
    const float c1 = cosv[(size_t)bs * HD + lane + 32];
    const float s0 = sinv[(size_t)bs * HD + lane];
    const float s1 = sinv[(size_t)bs * HD + lane + 32];

    base[lane]      = n0 * c0 - n1 * s0;
    base[lane + 32] = n1 * c1 + n0 * s1;
}

// ---------------- tensor-core causal flash attention ---------------------------
#define FBQ 128
#define FBK 64
#define KSP 76
#define VSP 72
#define PSP 76
#define FLASH_SMEM ((2*64*KSP + 2*64*VSP + 128*PSP) * 4)   // 114688 B

__global__ __launch_bounds__(256, 1) void flash_mma_kernel()
{
    const int bh  = blockIdx.y;
    const int b   = bh / NH;
    const int h   = bh % NH;
    const int kvh = h / (NH / NKV);
    const int q0  = blockIdx.x * FBQ;
    const int tid = threadIdx.x;
    const int lane = tid & 31;
    const int w    = tid >> 5;
    const int grp  = lane >> 2;
    const int kc   = lane & 3;

    extern __shared__ float sm[];
    float* Khi = sm;
    float* Klo = Khi + 64 * KSP;
    float* Vhi = Klo + 64 * KSP;
    float* Vlo = Vhi + 64 * VSP;
    float* Ps  = Vlo + 64 * VSP;
    float* Pw  = Ps + (w * 16) * PSP;

    const int qrow0 = q0 + w * 16 + grp;
    const float* Q0 = g_q + ((size_t)(b * SS + qrow0) * NH + h) * HD;
    const float* Q1 = Q0 + (size_t)8 * NH * HD;
    float aQ[8][4];
#pragma unroll
    for (int ks = 0; ks < 8; ks++) {
        aQ[ks][0] = tf32_hi(Q0[ks * 8 + kc]     * SCALE);
        aQ[ks][1] = tf32_hi(Q1[ks * 8 + kc]     * SCALE);
        aQ[ks][2] = tf32_hi(Q0[ks * 8 + kc + 4] * SCALE);
        aQ[ks][3] = tf32_hi(Q1[ks * 8 + kc + 4] * SCALE);
    }

    float c_o[8][4];
#pragma unroll
    for (int nt = 0; nt < 8; nt++)
#pragma unroll
        for (int f = 0; f < 4; f++) c_o[nt][f] = 0.f;

    float m0 = -FLT_MAX, m1 = -FLT_MAX, l0 = 0.f, l1 = 0.f;

    for (int k0 = 0; k0 < q0 + FBQ; k0 += FBK) {
#pragma unroll
        for (int i = 0; i < 4; i++) {
            const int linear = tid + i * 256;
            const int row = linear >> 4;
            const int c4  = (linear & 15) << 2;
            const size_t g = ((size_t)(b * SS + k0 + row) * NKV + kvh) * HD + c4;
            float4 kk = *reinterpret_cast<const float4*>(g_k + g);
            float4 vv = *reinterpret_cast<const float4*>(g_v + g);
            float2 sx = split_tf32(kk.x), sy = split_tf32(kk.y),
                   sz = split_tf32(kk.z), sw = split_tf32(kk.w);
            *reinterpret_cast<float4*>(Khi + row * KSP + c4) = make_float4(sx.x, sy.x, sz.x, sw.x);
            *reinterpret_cast<float4*>(Klo + row * KSP + c4) = make_float4(sx.y, sy.y, sz.y, sw.y);
            sx = split_tf32(vv.x); sy = split_tf32(vv.y);
            sz = split_tf32(vv.z); sw = split_tf32(vv.w);
            *reinterpret_cast<float4*>(Vhi + row * VSP + c4) = make_float4(sx.x, sy.x, sz.x, sw.x);
            *reinterpret_cast<float4*>(Vlo + row * VSP + c4) = make_float4(sx.y, sy.y, sz.y, sw.y);
        }
        __syncthreads();

        float c_s[8][4];
#pragma unroll
        for (int nt = 0; nt < 8; nt++)
#pragma unroll
            for (int f = 0; f < 4; f++) c_s[nt][f] = 0.f;

#pragma unroll
        for (int ks = 0; ks < 8; ks++) {
#pragma unroll
            for (int nt = 0; nt < 8; nt++) {
                const int krow = nt * 8 + grp;
                const float bh0 = Khi[krow * KSP + ks * 8 + kc];
                const float bh1 = Khi[krow * KSP + ks * 8 + kc + 4];
                const float bl0 = Klo[krow * KSP + ks * 8 + kc];
                const float bl1 = Klo[krow * KSP + ks * 8 + kc + 4];
                mma_tf32(c_s[nt], aQ[ks][0], aQ[ks][1], aQ[ks][2], aQ[ks][3], bh0, bh1);
                mma_tf32(c_s[nt], aQ[ks][0], aQ[ks][1], aQ[ks][2], aQ[ks][3], bl0, bl1);
            }
        }

        if (k0 + FBK > q0) {
#pragma unroll
            for (int nt = 0; nt < 8; nt++) {
                const int col = k0 + nt * 8 + kc * 2;
                if (col     > qrow0)     c_s[nt][0] = -FLT_MAX;
                if (col + 1 > qrow0)     c_s[nt][1] = -FLT_MAX;
                if (col     > qrow0 + 8) c_s[nt][2] = -FLT_MAX;
                if (col + 1 > qrow0 + 8) c_s[nt][3] = -FLT_MAX;
            }
        }

        float mx0 = -FLT_MAX, mx1 = -FLT_MAX;
#pragma unroll
        for (int nt = 0; nt < 8; nt++) {
            mx0 = fmaxf(mx0, fmaxf(c_s[nt][0], c_s[nt][1]));
            mx1 = fmaxf(mx1, fmaxf(c_s[nt][2], c_s[nt][3]));
        }
        mx0 = fmaxf(mx0, __shfl_xor_sync(0xffffffffu, mx0, 1));
        mx0 = fmaxf(mx0, __shfl_xor_sync(0xffffffffu, mx0, 2));
        mx1 = fmaxf(mx1, __shfl_xor_sync(0xffffffffu, mx1, 1));
        mx1 = fmaxf(mx1, __shfl_xor_sync(0xffffffffu, mx1, 2));

        const float mn0 = fmaxf(m0, mx0);
        const float mn1 = fmaxf(m1, mx1);
        const float cor0 = __expf(m0 - mn0);
        const float cor1 = __expf(m1 - mn1);
        m0 = mn0; m1 = mn1;

        float rs0 = 0.f, rs1 = 0.f;
#pragma unroll
        for (int nt = 0; nt < 8; nt++) {
            c_s[nt][0] = __expf(c_s[nt][0] - mn0);
            c_s[nt][1] = __expf(c_s[nt][1] - mn0);
            c_s[nt][2] = __expf(c_s[nt][2] - mn1);
            c_s[nt][3] = __expf(c_s[nt][3] - mn1);
            rs0 += c_s[nt][0] + c_s[nt][1];
            rs1 += c_s[nt][2] + c_s[nt][3];
        }
        rs0 += __shfl_xor_sync(0xffffffffu, rs0, 1);
        rs0 += __shfl_xor_sync(0xffffffffu, rs0, 2);
        rs1 += __shfl_xor_sync(0xffffffffu, rs1, 1);
        rs1 += __shfl_xor_sync(0xffffffffu, rs1, 2);
        l0 = l0 * cor0 + rs0;
        l1 = l1 * cor1 + rs1;

#pragma unroll
        for (int nt = 0; nt < 8; nt++) {
            c_o[nt][0] *= cor0; c_o[nt][1] *= cor0;
            c_o[nt][2] *= cor1; c_o[nt][3] *= cor1;
        }

#pragma unroll
        for (int nt = 0; nt < 8; nt++) {
            *reinterpret_cast<float2*>(Pw + grp * PSP + nt * 8 + kc * 2) =
                make_float2(tf32_hi(c_s[nt][0]), tf32_hi(c_s[nt][1]));
            *reinterpret_cast<float2*>(Pw + (grp + 8) * PSP + nt * 8 + kc * 2) =
                make_float2(tf32_hi(c_s[nt][2]), tf32_hi(c_s[nt][3]));
        }
        __syncwarp();

#pragma unroll
        for (int ks = 0; ks < 8; ks++) {
            const float a0 = Pw[grp * PSP + ks * 8 + kc];
            const float a1 = Pw[(grp + 8) * PSP + ks * 8 + kc];
            const float a2 = Pw[grp * PSP + ks * 8 + kc + 4];
            const float a3 = Pw[(grp + 8) * PSP + ks * 8 + kc + 4];
#pragma unroll
            for (int nt = 0; nt < 8; nt++) {
                const int d = nt * 8 + grp;
                const float bh0 = Vhi[(ks * 8 + kc) * VSP + d];
                const float bh1 = Vhi[(ks * 8 + kc + 4) * VSP + d];
                const float bl0 = Vlo[(ks * 8 + kc) * VSP + d];
                const float bl1 = Vlo[(ks * 8 + kc + 4) * VSP + d];
                mma_tf32(c_o[nt], a0, a1, a2, a3, bh0, bh1);
                mma_tf32(c_o[nt], a0, a1, a2, a3, bl0, bl1);
            }
        }
        __syncthreads();
    }

    // epilogue: normalize and store PRE-SPLIT for the O-projection
    const float inv0 = 1.f / l0;
    const float inv1 = 1.f / l1;
    float2* O20 = g_attn2 + ((size_t)(b * SS + qrow0) * NH + h) * HD;
    float2* O21 = O20 + (size_t)8 * NH * HD;
#pragma unroll
    for (int nt = 0; nt < 8; nt++) {
        float2 s0 = split_tf32(c_o[nt][0] * inv0);
        float2 s1 = split_tf32(c_o[nt][1] * inv0);
        *reinterpret_cast<float4*>(O20 + nt * 8 + kc * 2) = make_float4(s0.x, s0.y, s1.x, s1.y);
        float2 s2 = split_tf32(c_o[nt][2] * inv1);
        float2 s3 = split_tf32(c_o[nt][3] * inv1);
        *reinterpret_cast<float4*>(O21 + nt * 8 + kc * 2) = make_float4(s2.x, s2.y, s3.x, s3.y);
    }
}

// ------------------------------- launch ---------------------------------------
extern "C" void kernel_launch(void* const* d_in, const int* in_sizes, int n_in,
                              void* d_out, int out_size)
{
    const float* hidden = (const float*)d_in[0];
    const float* cosv   = (const float*)d_in[1];
    const float* sinv   = (const float*)d_in[2];
    const float* Wq     = (const float*)d_in[3];
    const float* Wk     = (const float*)d_in[4];
    const float* Wv     = (const float*)d_in[5];
    const float* Wo     = (const float*)d_in[6];
    const float* qw     = (const float*)d_in[7];
    const float* kw     = (const float*)d_in[8];
    float* out          = (float*)d_out;

    float *pq, *pk, *pv;
    float2 *phid2, *pattn2;
    float *pwq, *pwk, *pwv, *pwo;
    cudaGetSymbolAddress((void**)&pq,     g_q);
    cudaGetSymbolAddress((void**)&pk,     g_k);
    cudaGetSymbolAddress((void**)&pv,     g_v);
    cudaGetSymbolAddress((void**)&phid2,  g_hid2);
    cudaGetSymbolAddress((void**)&pattn2, g_attn2);
    cudaGetSymbolAddress((void**)&pwq,    g_wq_hi);
    cudaGetSymbolAddress((void**)&pwk,    g_wk_hi);
    cudaGetSymbolAddress((void**)&pwv,    g_wv_hi);
    cudaGetSymbolAddress((void**)&pwo,    g_wo_hi);

    cudaFuncSetAttribute(gemm_qkv_async, cudaFuncAttributeMaxDynamicSharedMemorySize, GEMM_SMEM);
    cudaFuncSetAttribute(gemm_o_async,   cudaFuncAttributeMaxDynamicSharedMemorySize, GEMM_SMEM);
    cudaFuncSetAttribute(flash_mma_kernel, cudaFuncAttributeMaxDynamicSharedMemorySize, FLASH_SMEM);

    // prep: split hidden, round weights to tf32-hi
    {
        const int nh4 = MROWS * HIDD / 4;
        split_pass4<<<(nh4 + 255) / 256, 256>>>((const float4*)hidden, (float4*)phid2, nh4);
        const int nq4 = NH * HD * HIDD / 4;
        const int nk4 = NKV * HD * HIDD / 4;
        hi_pass4<<<(nq4 + 255) / 256, 256>>>((const float4*)Wq, (float4*)pwq, nq4);
        hi_pass4<<<(nk4 + 255) / 256, 256>>>((const float4*)Wk, (float4*)pwk, nk4);
        hi_pass4<<<(nk4 + 255) / 256, 256>>>((const float4*)Wv, (float4*)pwv, nk4);
        hi_pass4<<<(nq4 + 255) / 256, 256>>>((const float4*)Wo, (float4*)pwo, nq4);
    }

    // Fused QKV projections (cp.async 2xTF32)
    gemm_qkv_async<<<dim3(24, MROWS / 128), 256, GEMM_SMEM>>>(phid2, pwq, pwk, pwv, pq, pk, pv);

    // RMSNorm + RoPE on q and k
    {
        const int warps = MROWS * NH + MROWS * NKV;
        const int threads = warps * 32;
        norm_rope_kernel<<<(threads + 255) / 256, 256>>>(cosv, sinv, qw, kw);
    }

    // tensor-core causal flash attention
    flash_mma_kernel<<<dim3(SS / FBQ, BB * NH), 256, FLASH_SMEM>>>();

    // output projection -> d_out
    gemm_o_async<<<dim3(HIDD / 128, MROWS / 128), 256, GEMM_SMEM>>>(pattn2, pwo, out, HIDD, NH * HD);
}

// round 9
// speedup vs baseline: 2.5101x; 1.1456x over previous
#include <cuda_runtime.h>
#include <cuda_bf16.h>
#include <float.h>
#include <stdint.h>

// Problem constants
#define BB   2
#define SS   2048
#define HIDD 2048
#define NH   32
#define NKV  8
#define HD   64
#define MROWS (BB*SS)          // 4096
#define SCALE 0.125f           // HD^-0.5
#define EPS   1e-6f

// ---------------- scratch -----------------------------------------------------
__device__ float g_q[(size_t)MROWS * NH * HD];
__device__ float g_k[(size_t)MROWS * NKV * HD];
__device__ float g_v[(size_t)MROWS * NKV * HD];

__device__ __nv_bfloat16 g_hid_hi[(size_t)MROWS * HIDD];
__device__ __nv_bfloat16 g_hid_lo[(size_t)MROWS * HIDD];
__device__ __nv_bfloat16 g_attn_hi[(size_t)MROWS * NH * HD];
__device__ __nv_bfloat16 g_attn_lo[(size_t)MROWS * NH * HD];
__device__ __nv_bfloat16 g_wq_hi[(size_t)NH  * HD * HIDD];
__device__ __nv_bfloat16 g_wq_lo[(size_t)NH  * HD * HIDD];
__device__ __nv_bfloat16 g_wk_hi[(size_t)NKV * HD * HIDD];
__device__ __nv_bfloat16 g_wk_lo[(size_t)NKV * HD * HIDD];
__device__ __nv_bfloat16 g_wv_hi[(size_t)NKV * HD * HIDD];
__device__ __nv_bfloat16 g_wv_lo[(size_t)NKV * HD * HIDD];
__device__ __nv_bfloat16 g_wo_hi[(size_t)HIDD * NH * HD];
__device__ __nv_bfloat16 g_wo_lo[(size_t)HIDD * NH * HD];

// ---------------- helpers ------------------------------------------------------
__device__ __forceinline__ float2 split_tf32(float x) {
    uint32_t h;
    asm("cvt.rna.tf32.f32 %0, %1;" : "=r"(h) : "f"(x));
    float r = x - __uint_as_float(h);
    uint32_t l;
    asm("cvt.rna.tf32.f32 %0, %1;" : "=r"(l) : "f"(r));
    return make_float2(__uint_as_float(h), __uint_as_float(l));
}

__device__ __forceinline__ float tf32_hi(float x) {
    uint32_t h;
    asm("cvt.rna.tf32.f32 %0, %1;" : "=r"(h) : "f"(x));
    return __uint_as_float(h);
}

__device__ __forceinline__ void mma_tf32(float c[4],
    float a0, float a1, float a2, float a3, float b0, float b1)
{
    asm volatile(
        "mma.sync.aligned.m16n8k8.row.col.f32.tf32.tf32.f32 "
        "{%0,%1,%2,%3}, {%4,%5,%6,%7}, {%8,%9}, {%0,%1,%2,%3};"
        : "+f"(c[0]), "+f"(c[1]), "+f"(c[2]), "+f"(c[3])
        : "r"(__float_as_uint(a0)), "r"(__float_as_uint(a1)),
          "r"(__float_as_uint(a2)), "r"(__float_as_uint(a3)),
          "r"(__float_as_uint(b0)), "r"(__float_as_uint(b1)));
}

__device__ __forceinline__ void mma_bf16(float c[4],
    uint32_t a0, uint32_t a1, uint32_t a2, uint32_t a3,
    uint32_t b0, uint32_t b1)
{
    asm volatile(
        "mma.sync.aligned.m16n8k16.row.col.f32.bf16.bf16.f32 "
        "{%0,%1,%2,%3}, {%4,%5,%6,%7}, {%8,%9}, {%0,%1,%2,%3};"
        : "+f"(c[0]), "+f"(c[1]), "+f"(c[2]), "+f"(c[3])
        : "r"(a0), "r"(a1), "r"(a2), "r"(a3), "r"(b0), "r"(b1));
}

// ---------------- prep: split fp32 -> bf16 {hi, lo} ----------------------------
__global__ void split_bf16_pass(const float4* __restrict__ src,
                                __nv_bfloat162* __restrict__ hi,
                                __nv_bfloat162* __restrict__ lo, int n4)
{
    const int i = blockIdx.x * blockDim.x + threadIdx.x;
    if (i >= n4) return;
    float4 v = src[i];
    __nv_bfloat16 h0 = __float2bfloat16_rn(v.x);
    __nv_bfloat16 h1 = __float2bfloat16_rn(v.y);
    __nv_bfloat16 h2 = __float2bfloat16_rn(v.z);
    __nv_bfloat16 h3 = __float2bfloat16_rn(v.w);
    __nv_bfloat16 l0 = __float2bfloat16_rn(v.x - __bfloat162float(h0));
    __nv_bfloat16 l1 = __float2bfloat16_rn(v.y - __bfloat162float(h1));
    __nv_bfloat16 l2 = __float2bfloat16_rn(v.z - __bfloat162float(h2));
    __nv_bfloat16 l3 = __float2bfloat16_rn(v.w - __bfloat162float(h3));
    hi[i * 2 + 0] = __nv_bfloat162(h0, h1);
    hi[i * 2 + 1] = __nv_bfloat162(h2, h3);
    lo[i * 2 + 0] = __nv_bfloat162(l0, l1);
    lo[i * 2 + 1] = __nv_bfloat162(l2, l3);
}

// ---------------- bf16x3 cp.async GEMM:  C = A[M,K] @ B[N,K]^T -----------------
// Block tile 128x128, TBK=16, 4-stage cp.async ring.
// SMEM rows: 16 bf16 data in 12-word (48B) stride rows -> word index
// (12*row + kc) mod 32 distinct over the warp: conflict-free LDS.32.
// 3 mma per k16: Ahi*Bhi + Alo*Bhi + Ahi*Blo.
#define TBK 16
#define NSTAGE 4
#define RSW 12                        // 32-bit words per SMEM row
#define TW  (128 * RSW)               // words per tile-split (1536)
#define STW (4 * TW)                  // words per stage (Ahi|Alo|Bhi|Blo)
#define STB (STW * 4)                 // 24576 bytes per stage
#define GEMM_SMEM (NSTAGE * STB)      // 98304 bytes

__device__ __forceinline__ void cp16(uint32_t dst, const void* src) {
    asm volatile("cp.async.cg.shared.global [%0], [%1], 16;" :: "r"(dst), "l"(src));
}

__device__ __forceinline__ void gemm_body_bf16(
    const __nv_bfloat16* __restrict__ Ahi, const __nv_bfloat16* __restrict__ Alo,
    const __nv_bfloat16* __restrict__ Bhi, const __nv_bfloat16* __restrict__ Blo,
    float* __restrict__ C, int N, int K, int m0, int n0)
{
    extern __shared__ uint32_t smw[];
    const uint32_t sbase = (uint32_t)__cvta_generic_to_shared(smw);

    const int t    = threadIdx.x;
    const int lane = t & 31;
    const int warp = t >> 5;
    const int wm   = warp & 1;
    const int wn   = warp >> 1;
    const int grp  = lane >> 2;
    const int kc   = lane & 3;

    // loader: one 16B chunk per tile-split per thread
    const int lrow = t >> 1;
    const int lhalf = t & 1;                   // 0 or 1 (8 bf16 each)
    const size_t gA = (size_t)(m0 + lrow) * K + lhalf * 8;
    const size_t gB = (size_t)(n0 + lrow) * K + lhalf * 8;
    const uint32_t dOff = lrow * 48 + lhalf * 16;

    float acc[4][4][4];
#pragma unroll
    for (int i = 0; i < 4; i++)
#pragma unroll
        for (int j = 0; j < 4; j++)
#pragma unroll
            for (int f = 0; f < 4; f++) acc[i][j][f] = 0.f;

    const int NT = K / TBK;

#pragma unroll
    for (int s = 0; s < NSTAGE - 1; s++) {
        const int koff = s * TBK;
        const uint32_t sb = sbase + s * STB;
        cp16(sb + dOff,              Ahi + gA + koff);
        cp16(sb + TW * 4 + dOff,     Alo + gA + koff);
        cp16(sb + 2 * TW * 4 + dOff, Bhi + gB + koff);
        cp16(sb + 3 * TW * 4 + dOff, Blo + gB + koff);
        asm volatile("cp.async.commit_group;" ::: "memory");
    }

    const int mrow = wm * 64 + grp;
    const int nrow = wn * 32 + grp;

#pragma unroll 4
    for (int kt = 0; kt < NT; kt++) {
        asm volatile("cp.async.wait_group %0;" :: "n"(NSTAGE - 2) : "memory");
        __syncthreads();

        const int kn = kt + NSTAGE - 1;
        if (kn < NT) {
            const int s = kn & (NSTAGE - 1);
            const int koff = kn * TBK;
            const uint32_t sb = sbase + s * STB;
            cp16(sb + dOff,              Ahi + gA + koff);
            cp16(sb + TW * 4 + dOff,     Alo + gA + koff);
            cp16(sb + 2 * TW * 4 + dOff, Bhi + gB + koff);
            cp16(sb + 3 * TW * 4 + dOff, Blo + gB + koff);
        }
        asm volatile("cp.async.commit_group;" ::: "memory");

        const int st = kt & (NSTAGE - 1);
        const uint32_t* Ah = smw + st * STW;
        const uint32_t* Al = Ah + TW;
        const uint32_t* Bh = Al + TW;
        const uint32_t* Bl = Bh + TW;

        uint32_t bh[4][2], bl[4][2];
#pragma unroll
        for (int nt = 0; nt < 4; nt++) {
            const int r = (nrow + nt * 8) * RSW;
            bh[nt][0] = Bh[r + kc]; bh[nt][1] = Bh[r + kc + 4];
            bl[nt][0] = Bl[r + kc]; bl[nt][1] = Bl[r + kc + 4];
        }
#pragma unroll
        for (int mt = 0; mt < 4; mt++) {
            const int r0 = (mrow + mt * 16) * RSW;
            const int r1 = (mrow + mt * 16 + 8) * RSW;
            uint32_t ah0 = Ah[r0 + kc], ah1 = Ah[r1 + kc];
            uint32_t ah2 = Ah[r0 + kc + 4], ah3 = Ah[r1 + kc + 4];
            uint32_t al0 = Al[r0 + kc], al1 = Al[r1 + kc];
            uint32_t al2 = Al[r0 + kc + 4], al3 = Al[r1 + kc + 4];
#pragma unroll
            for (int nt = 0; nt < 4; nt++) {
                mma_bf16(acc[mt][nt], ah0, ah1, ah2, ah3, bh[nt][0], bh[nt][1]);
                mma_bf16(acc[mt][nt], al0, al1, al2, al3, bh[nt][0], bh[nt][1]);
                mma_bf16(acc[mt][nt], ah0, ah1, ah2, ah3, bl[nt][0], bl[nt][1]);
            }
        }
    }

    // epilogue
#pragma unroll
    for (int mt = 0; mt < 4; mt++) {
        const int row = m0 + wm * 64 + mt * 16 + grp;
#pragma unroll
        for (int nt = 0; nt < 4; nt++) {
            const int col = n0 + wn * 32 + nt * 8 + kc * 2;
            *reinterpret_cast<float2*>(C + (size_t)row * N + col) =
                make_float2(acc[mt][nt][0], acc[mt][nt][1]);
            *reinterpret_cast<float2*>(C + (size_t)(row + 8) * N + col) =
                make_float2(acc[mt][nt][2], acc[mt][nt][3]);
        }
    }
}

__global__ __launch_bounds__(256, 2) void gemm_qkv_bf16()
{
    const int bx = blockIdx.x;                // 0..23
    const int m0 = blockIdx.y * 128;
    const __nv_bfloat16 *Bh, *Bl; float* C; int N, n0;
    if (bx < 16)      { Bh = g_wq_hi; Bl = g_wq_lo; C = g_q; N = NH  * HD; n0 = bx * 128; }
    else if (bx < 20) { Bh = g_wk_hi; Bl = g_wk_lo; C = g_k; N = NKV * HD; n0 = (bx - 16) * 128; }
    else              { Bh = g_wv_hi; Bl = g_wv_lo; C = g_v; N = NKV * HD; n0 = (bx - 20) * 128; }
    gemm_body_bf16(g_hid_hi, g_hid_lo, Bh, Bl, C, N, HIDD, m0, n0);
}

__global__ __launch_bounds__(256, 2) void gemm_o_bf16(float* __restrict__ out)
{
    gemm_body_bf16(g_attn_hi, g_attn_lo, g_wo_hi, g_wo_lo,
                   out, HIDD, NH * HD, blockIdx.y * 128, blockIdx.x * 128);
}

// ---------------- RMSNorm + RoPE over q and k head-rows -----------------------
__global__ void norm_rope_kernel(
    const float* __restrict__ cosv, const float* __restrict__ sinv,
    const float* __restrict__ qw,   const float* __restrict__ kw)
{
    const int gid  = blockIdx.x * blockDim.x + threadIdx.x;
    const int wid  = gid >> 5;
    const int lane = gid & 31;
    const int nqr  = MROWS * NH;
    const int ntot = nqr + MROWS * NKV;
    if (wid >= ntot) return;

    float* base;
    int bs;
    const float* w;
    if (wid < nqr) { base = g_q + (size_t)wid * HD;        bs = wid / NH;  w = qw; }
    else { int r = wid - nqr; base = g_k + (size_t)r * HD; bs = r / NKV;   w = kw; }

    float x0 = base[lane];
    float x1 = base[lane + 32];
    float ss = x0 * x0 + x1 * x1;
#pragma unroll
    for (int o = 16; o > 0; o >>= 1) ss += __shfl_xor_sync(0xffffffffu, ss, o);
    const float rinv = rsqrtf(ss * (1.0f / HD) + EPS);

    const float n0 = w[lane]      * (x0 * rinv);
    const float n1 = w[lane + 32] * (x1 * rinv);

    const float c0 = cosv[(size_t)bs * HD + lane];
    const float c1 = cosv[(size_t)bs * HD + lane + 32];
    const float s0 = sinv[(size_t)bs * HD + lane];
    const float s1 = sinv[(size_t)bs * HD + lane + 32];

    base[lane]      = n0 * c0 - n1 * s0;
    base[lane + 32] = n1 * c1 + n0 * s1;
}

// ---------------- tensor-core causal flash attention (2xTF32) ------------------
#define FBQ 128
#define FBK 64
#define KSP 76
#define VSP 72
#define PSP 76
#define FLASH_SMEM ((2*64*KSP + 2*64*VSP + 128*PSP) * 4)   // 114688 B

__global__ __launch_bounds__(256, 1) void flash_mma_kernel()
{
    const int bh  = blockIdx.y;
    const int b   = bh / NH;
    const int h   = bh % NH;
    const int kvh = h / (NH / NKV);
    const int q0  = blockIdx.x * FBQ;
    const int tid = threadIdx.x;
    const int lane = tid & 31;
    const int w    = tid >> 5;
    const int grp  = lane >> 2;
    const int kc   = lane & 3;

    extern __shared__ float sm[];
    float* Khi = sm;
    float* Klo = Khi + 64 * KSP;
    float* Vhi = Klo + 64 * KSP;
    float* Vlo = Vhi + 64 * VSP;
    float* Ps  = Vlo + 64 * VSP;
    float* Pw  = Ps + (w * 16) * PSP;

    const int qrow0 = q0 + w * 16 + grp;
    const float* Q0 = g_q + ((size_t)(b * SS + qrow0) * NH + h) * HD;
    const float* Q1 = Q0 + (size_t)8 * NH * HD;
    float aQ[8][4];
#pragma unroll
    for (int ks = 0; ks < 8; ks++) {
        aQ[ks][0] = tf32_hi(Q0[ks * 8 + kc]     * SCALE);
        aQ[ks][1] = tf32_hi(Q1[ks * 8 + kc]     * SCALE);
        aQ[ks][2] = tf32_hi(Q0[ks * 8 + kc + 4] * SCALE);
        aQ[ks][3] = tf32_hi(Q1[ks * 8 + kc + 4] * SCALE);
    }

    float c_o[8][4];
#pragma unroll
    for (int nt = 0; nt < 8; nt++)
#pragma unroll
        for (int f = 0; f < 4; f++) c_o[nt][f] = 0.f;

    float m0 = -FLT_MAX, m1 = -FLT_MAX, l0 = 0.f, l1 = 0.f;

    for (int k0 = 0; k0 < q0 + FBQ; k0 += FBK) {
#pragma unroll
        for (int i = 0; i < 4; i++) {
            const int linear = tid + i * 256;
            const int row = linear >> 4;
            const int c4  = (linear & 15) << 2;
            const size_t g = ((size_t)(b * SS + k0 + row) * NKV + kvh) * HD + c4;
            float4 kk = *reinterpret_cast<const float4*>(g_k + g);
            float4 vv = *reinterpret_cast<const float4*>(g_v + g);
            float2 sx = split_tf32(kk.x), sy = split_tf32(kk.y),
                   sz = split_tf32(kk.z), sw = split_tf32(kk.w);
            *reinterpret_cast<float4*>(Khi + row * KSP + c4) = make_float4(sx.x, sy.x, sz.x, sw.x);
            *reinterpret_cast<float4*>(Klo + row * KSP + c4) = make_float4(sx.y, sy.y, sz.y, sw.y);
            sx = split_tf32(vv.x); sy = split_tf32(vv.y);
            sz = split_tf32(vv.z); sw = split_tf32(vv.w);
            *reinterpret_cast<float4*>(Vhi + row * VSP + c4) = make_float4(sx.x, sy.x, sz.x, sw.x);
            *reinterpret_cast<float4*>(Vlo + row * VSP + c4) = make_float4(sx.y, sy.y, sz.y, sw.y);
        }
        __syncthreads();

        float c_s[8][4];
#pragma unroll
        for (int nt = 0; nt < 8; nt++)
#pragma unroll
            for (int f = 0; f < 4; f++) c_s[nt][f] = 0.f;

#pragma unroll
        for (int ks = 0; ks < 8; ks++) {
#pragma unroll
            for (int nt = 0; nt < 8; nt++) {
                const int krow = nt * 8 + grp;
                const float bh0 = Khi[krow * KSP + ks * 8 + kc];
                const float bh1 = Khi[krow * KSP + ks * 8 + kc + 4];
                const float bl0 = Klo[krow * KSP + ks * 8 + kc];
                const float bl1 = Klo[krow * KSP + ks * 8 + kc + 4];
                mma_tf32(c_s[nt], aQ[ks][0], aQ[ks][1], aQ[ks][2], aQ[ks][3], bh0, bh1);
                mma_tf32(c_s[nt], aQ[ks][0], aQ[ks][1], aQ[ks][2], aQ[ks][3], bl0, bl1);
            }
        }

        if (k0 + FBK > q0) {
#pragma unroll
            for (int nt = 0; nt < 8; nt++) {
                const int col = k0 + nt * 8 + kc * 2;
                if (col     > qrow0)     c_s[nt][0] = -FLT_MAX;
                if (col + 1 > qrow0)     c_s[nt][1] = -FLT_MAX;
                if (col     > qrow0 + 8) c_s[nt][2] = -FLT_MAX;
                if (col + 1 > qrow0 + 8) c_s[nt][3] = -FLT_MAX;
            }
        }

        float mx0 = -FLT_MAX, mx1 = -FLT_MAX;
#pragma unroll
        for (int nt = 0; nt < 8; nt++) {
            mx0 = fmaxf(mx0, fmaxf(c_s[nt][0], c_s[nt][1]));
            mx1 = fmaxf(mx1, fmaxf(c_s[nt][2], c_s[nt][3]));
        }
        mx0 = fmaxf(mx0, __shfl_xor_sync(0xffffffffu, mx0, 1));
        mx0 = fmaxf(mx0, __shfl_xor_sync(0xffffffffu, mx0, 2));
        mx1 = fmaxf(mx1, __shfl_xor_sync(0xffffffffu, mx1, 1));
        mx1 = fmaxf(mx1, __shfl_xor_sync(0xffffffffu, mx1, 2));

        const float mn0 = fmaxf(m0, mx0);
        const float mn1 = fmaxf(m1, mx1);
        const float cor0 = __expf(m0 - mn0);
        const float cor1 = __expf(m1 - mn1);
        m0 = mn0; m1 = mn1;

        float rs0 = 0.f, rs1 = 0.f;
#pragma unroll
        for (int nt = 0; nt < 8; nt++) {
            c_s[nt][0] = __expf(c_s[nt][0] - mn0);
            c_s[nt][1] = __expf(c_s[nt][1] - mn0);
            c_s[nt][2] = __expf(c_s[nt][2] - mn1);
            c_s[nt][3] = __expf(c_s[nt][3] - mn1);
            rs0 += c_s[nt][0] + c_s[nt][1];
            rs1 += c_s[nt][2] + c_s[nt][3];
        }
        rs0 += __shfl_xor_sync(0xffffffffu, rs0, 1);
        rs0 += __shfl_xor_sync(0xffffffffu, rs0, 2);
        rs1 += __shfl_xor_sync(0xffffffffu, rs1, 1);
        rs1 += __shfl_xor_sync(0xffffffffu, rs1, 2);
        l0 = l0 * cor0 + rs0;
        l1 = l1 * cor1 + rs1;

#pragma unroll
        for (int nt = 0; nt < 8; nt++) {
            c_o[nt][0] *= cor0; c_o[nt][1] *= cor0;
            c_o[nt][2] *= cor1; c_o[nt][3] *= cor1;
        }

#pragma unroll
        for (int nt = 0; nt < 8; nt++) {
            *reinterpret_cast<float2*>(Pw + grp * PSP + nt * 8 + kc * 2) =
                make_float2(tf32_hi(c_s[nt][0]), tf32_hi(c_s[nt][1]));
            *reinterpret_cast<float2*>(Pw + (grp + 8) * PSP + nt * 8 + kc * 2) =
                make_float2(tf32_hi(c_s[nt][2]), tf32_hi(c_s[nt][3]));
        }
        __syncwarp();

#pragma unroll
        for (int ks = 0; ks < 8; ks++) {
            const float a0 = Pw[grp * PSP + ks * 8 + kc];
            const float a1 = Pw[(grp + 8) * PSP + ks * 8 + kc];
            const float a2 = Pw[grp * PSP + ks * 8 + kc + 4];
            const float a3 = Pw[(grp + 8) * PSP + ks * 8 + kc + 4];
#pragma unroll
            for (int nt = 0; nt < 8; nt++) {
                const int d = nt * 8 + grp;
                const float bh0 = Vhi[(ks * 8 + kc) * VSP + d];
                const float bh1 = Vhi[(ks * 8 + kc + 4) * VSP + d];
                const float bl0 = Vlo[(ks * 8 + kc) * VSP + d];
                const float bl1 = Vlo[(ks * 8 + kc + 4) * VSP + d];
                mma_tf32(c_o[nt], a0, a1, a2, a3, bh0, bh1);
                mma_tf32(c_o[nt], a0, a1, a2, a3, bl0, bl1);
            }
        }
        __syncthreads();
    }

    // epilogue: normalize and store as bf16 {hi, lo} for the O-projection
    const float inv0 = 1.f / l0;
    const float inv1 = 1.f / l1;
    const size_t off0 = ((size_t)(b * SS + qrow0) * NH + h) * HD;
    const size_t off1 = off0 + (size_t)8 * NH * HD;
#pragma unroll
    for (int nt = 0; nt < 8; nt++) {
        const int c = nt * 8 + kc * 2;
        float v0 = c_o[nt][0] * inv0, v1 = c_o[nt][1] * inv0;
        __nv_bfloat16 h0 = __float2bfloat16_rn(v0);
        __nv_bfloat16 h1 = __float2bfloat16_rn(v1);
        *reinterpret_cast<__nv_bfloat162*>(g_attn_hi + off0 + c) = __nv_bfloat162(h0, h1);
        *reinterpret_cast<__nv_bfloat162*>(g_attn_lo + off0 + c) = __nv_bfloat162(
            __float2bfloat16_rn(v0 - __bfloat162float(h0)),
            __float2bfloat16_rn(v1 - __bfloat162float(h1)));
        float v2 = c_o[nt][2] * inv1, v3 = c_o[nt][3] * inv1;
        __nv_bfloat16 h2 = __float2bfloat16_rn(v2);
        __nv_bfloat16 h3 = __float2bfloat16_rn(v3);
        *reinterpret_cast<__nv_bfloat162*>(g_attn_hi + off1 + c) = __nv_bfloat162(h2, h3);
        *reinterpret_cast<__nv_bfloat162*>(g_attn_lo + off1 + c) = __nv_bfloat162(
            __float2bfloat16_rn(v2 - __bfloat162float(h2)),
            __float2bfloat16_rn(v3 - __bfloat162float(h3)));
    }
}

// ------------------------------- launch ---------------------------------------
extern "C" void kernel_launch(void* const* d_in, const int* in_sizes, int n_in,
                              void* d_out, int out_size)
{
    const float* hidden = (const float*)d_in[0];
    const float* cosv   = (const float*)d_in[1];
    const float* sinv   = (const float*)d_in[2];
    const float* Wq     = (const float*)d_in[3];
    const float* Wk     = (const float*)d_in[4];
    const float* Wv     = (const float*)d_in[5];
    const float* Wo     = (const float*)d_in[6];
    const float* qw     = (const float*)d_in[7];
    const float* kw     = (const float*)d_in[8];
    float* out          = (float*)d_out;

    __nv_bfloat162 *phh, *phl, *pqh, *pql, *pkh, *pkl, *pvh, *pvl, *poh, *pol;
    cudaGetSymbolAddress((void**)&phh, g_hid_hi);
    cudaGetSymbolAddress((void**)&phl, g_hid_lo);
    cudaGetSymbolAddress((void**)&pqh, g_wq_hi);
    cudaGetSymbolAddress((void**)&pql, g_wq_lo);
    cudaGetSymbolAddress((void**)&pkh, g_wk_hi);
    cudaGetSymbolAddress((void**)&pkl, g_wk_lo);
    cudaGetSymbolAddress((void**)&pvh, g_wv_hi);
    cudaGetSymbolAddress((void**)&pvl, g_wv_lo);
    cudaGetSymbolAddress((void**)&poh, g_wo_hi);
    cudaGetSymbolAddress((void**)&pol, g_wo_lo);

    cudaFuncSetAttribute(gemm_qkv_bf16, cudaFuncAttributeMaxDynamicSharedMemorySize, GEMM_SMEM);
    cudaFuncSetAttribute(gemm_o_bf16,   cudaFuncAttributeMaxDynamicSharedMemorySize, GEMM_SMEM);
    cudaFuncSetAttribute(flash_mma_kernel, cudaFuncAttributeMaxDynamicSharedMemorySize, FLASH_SMEM);

    // prep: split inputs/weights to bf16 hi/lo
    {
        const int nh4 = MROWS * HIDD / 4;
        split_bf16_pass<<<(nh4 + 255) / 256, 256>>>((const float4*)hidden, phh, phl, nh4);
        const int nq4 = NH * HD * HIDD / 4;
        const int nk4 = NKV * HD * HIDD / 4;
        split_bf16_pass<<<(nq4 + 255) / 256, 256>>>((const float4*)Wq, pqh, pql, nq4);
        split_bf16_pass<<<(nk4 + 255) / 256, 256>>>((const float4*)Wk, pkh, pkl, nk4);
        split_bf16_pass<<<(nk4 + 255) / 256, 256>>>((const float4*)Wv, pvh, pvl, nk4);
        split_bf16_pass<<<(nq4 + 255) / 256, 256>>>((const float4*)Wo, poh, pol, nq4);
    }

    // Fused QKV projections (bf16x3 tensor core)
    gemm_qkv_bf16<<<dim3(24, MROWS / 128), 256, GEMM_SMEM>>>();

    // RMSNorm + RoPE on q and k
    {
        const int warps = MROWS * NH + MROWS * NKV;
        const int threads = warps * 32;
        norm_rope_kernel<<<(threads + 255) / 256, 256>>>(cosv, sinv, qw, kw);
    }

    // tensor-core causal flash attention
    flash_mma_kernel<<<dim3(SS / FBQ, BB * NH), 256, FLASH_SMEM>>>();

    // output projection -> d_out
    gemm_o_bf16<<<dim3(HIDD / 128, MROWS / 128), 256, GEMM_SMEM>>>(out);
}

// round 12
// speedup vs baseline: 2.8429x; 1.1326x over previous
#include <cuda_runtime.h>
#include <cuda_bf16.h>
#include <float.h>
#include <stdint.h>

// Problem constants
#define BB   2
#define SS   2048
#define HIDD 2048
#define NH   32
#define NKV  8
#define HD   64
#define MROWS (BB*SS)          // 4096
#define SCALE 0.125f           // HD^-0.5
#define EPS   1e-6f

// ---------------- scratch -----------------------------------------------------
__device__ float g_q[(size_t)MROWS * NH * HD];
__device__ float g_k[(size_t)MROWS * NKV * HD];
__device__ float g_v[(size_t)MROWS * NKV * HD];

__device__ __align__(16) __nv_bfloat16 g_hid_hi[(size_t)MROWS * HIDD];
__device__ __align__(16) __nv_bfloat16 g_hid_lo[(size_t)MROWS * HIDD];
__device__ __align__(16) __nv_bfloat16 g_attn_hi[(size_t)MROWS * NH * HD];
__device__ __align__(16) __nv_bfloat16 g_attn_lo[(size_t)MROWS * NH * HD];
__device__ __align__(16) __nv_bfloat16 g_wq_hi[(size_t)NH  * HD * HIDD];
__device__ __align__(16) __nv_bfloat16 g_wq_lo[(size_t)NH  * HD * HIDD];
__device__ __align__(16) __nv_bfloat16 g_wk_hi[(size_t)NKV * HD * HIDD];
__device__ __align__(16) __nv_bfloat16 g_wk_lo[(size_t)NKV * HD * HIDD];
__device__ __align__(16) __nv_bfloat16 g_wv_hi[(size_t)NKV * HD * HIDD];
__device__ __align__(16) __nv_bfloat16 g_wv_lo[(size_t)NKV * HD * HIDD];
__device__ __align__(16) __nv_bfloat16 g_wo_hi[(size_t)HIDD * NH * HD];
__device__ __align__(16) __nv_bfloat16 g_wo_lo[(size_t)HIDD * NH * HD];

// flash operands: K (post-rope) bf16 hi/lo in [b][kvh][key][d];
// V^T bf16 hi/lo in [b][kvh][d][key]
__device__ __align__(16) __nv_bfloat16 g_fk_hi[(size_t)BB * NKV * SS * HD];
__device__ __align__(16) __nv_bfloat16 g_fk_lo[(size_t)BB * NKV * SS * HD];
__device__ __align__(16) __nv_bfloat16 g_vT_hi[(size_t)BB * NKV * HD * SS];
__device__ __align__(16) __nv_bfloat16 g_vT_lo[(size_t)BB * NKV * HD * SS];

// ---------------- helpers ------------------------------------------------------
__device__ __forceinline__ uint32_t packbf(float x, float y) {
    __nv_bfloat162 t = __floats2bfloat162_rn(x, y);
    return *reinterpret_cast<uint32_t*>(&t);
}
__device__ __forceinline__ uint32_t packlo(float x, float y, uint32_t hi) {
    __nv_bfloat162 h = *reinterpret_cast<__nv_bfloat162*>(&hi);
    return packbf(x - __bfloat162float(h.x), y - __bfloat162float(h.y));
}

__device__ __forceinline__ void mma_bf16(float c[4],
    uint32_t a0, uint32_t a1, uint32_t a2, uint32_t a3,
    uint32_t b0, uint32_t b1)
{
    asm volatile(
        "mma.sync.aligned.m16n8k16.row.col.f32.bf16.bf16.f32 "
        "{%0,%1,%2,%3}, {%4,%5,%6,%7}, {%8,%9}, {%0,%1,%2,%3};"
        : "+f"(c[0]), "+f"(c[1]), "+f"(c[2]), "+f"(c[3])
        : "r"(a0), "r"(a1), "r"(a2), "r"(a3), "r"(b0), "r"(b1));
}

__device__ __forceinline__ void cp16(uint32_t dst, const void* src) {
    asm volatile("cp.async.cg.shared.global [%0], [%1], 16;" :: "r"(dst), "l"(src));
}

// ---------------- prep: split fp32 -> bf16 {hi, lo} ----------------------------
__global__ void split_bf16_pass(const float4* __restrict__ src,
                                __nv_bfloat162* __restrict__ hi,
                                __nv_bfloat162* __restrict__ lo, int n4)
{
    const int i = blockIdx.x * blockDim.x + threadIdx.x;
    if (i >= n4) return;
    float4 v = src[i];
    __nv_bfloat16 h0 = __float2bfloat16_rn(v.x);
    __nv_bfloat16 h1 = __float2bfloat16_rn(v.y);
    __nv_bfloat16 h2 = __float2bfloat16_rn(v.z);
    __nv_bfloat16 h3 = __float2bfloat16_rn(v.w);
    hi[i * 2 + 0] = __nv_bfloat162(h0, h1);
    hi[i * 2 + 1] = __nv_bfloat162(h2, h3);
    lo[i * 2 + 0] = __nv_bfloat162(
        __float2bfloat16_rn(v.x - __bfloat162float(h0)),
        __float2bfloat16_rn(v.y - __bfloat162float(h1)));
    lo[i * 2 + 1] = __nv_bfloat162(
        __float2bfloat16_rn(v.z - __bfloat162float(h2)),
        __float2bfloat16_rn(v.w - __bfloat162float(h3)));
}

// ---------------- bf16x3 cp.async GEMM (unchanged from R9) ---------------------
#define TBK 16
#define NSTAGE 4
#define RSW 12
#define TW  (128 * RSW)
#define STW (4 * TW)
#define STB (STW * 4)
#define GEMM_SMEM (NSTAGE * STB)

__device__ __forceinline__ void gemm_body_bf16(
    const __nv_bfloat16* __restrict__ Ahi, const __nv_bfloat16* __restrict__ Alo,
    const __nv_bfloat16* __restrict__ Bhi, const __nv_bfloat16* __restrict__ Blo,
    float* __restrict__ C, int N, int K, int m0, int n0)
{
    extern __shared__ uint32_t smw[];
    const uint32_t sbase = (uint32_t)__cvta_generic_to_shared(smw);

    const int t    = threadIdx.x;
    const int lane = t & 31;
    const int warp = t >> 5;
    const int wm   = warp & 1;
    const int wn   = warp >> 1;
    const int grp  = lane >> 2;
    const int kc   = lane & 3;

    const int lrow = t >> 1;
    const int lhalf = t & 1;
    const size_t gA = (size_t)(m0 + lrow) * K + lhalf * 8;
    const size_t gB = (size_t)(n0 + lrow) * K + lhalf * 8;
    const uint32_t dOff = lrow * 48 + lhalf * 16;

    float acc[4][4][4];
#pragma unroll
    for (int i = 0; i < 4; i++)
#pragma unroll
        for (int j = 0; j < 4; j++)
#pragma unroll
            for (int f = 0; f < 4; f++) acc[i][j][f] = 0.f;

    const int NT = K / TBK;

#pragma unroll
    for (int s = 0; s < NSTAGE - 1; s++) {
        const int koff = s * TBK;
        const uint32_t sb = sbase + s * STB;
        cp16(sb + dOff,              Ahi + gA + koff);
        cp16(sb + TW * 4 + dOff,     Alo + gA + koff);
        cp16(sb + 2 * TW * 4 + dOff, Bhi + gB + koff);
        cp16(sb + 3 * TW * 4 + dOff, Blo + gB + koff);
        asm volatile("cp.async.commit_group;" ::: "memory");
    }

    const int mrow = wm * 64 + grp;
    const int nrow = wn * 32 + grp;

#pragma unroll 4
    for (int kt = 0; kt < NT; kt++) {
        asm volatile("cp.async.wait_group %0;" :: "n"(NSTAGE - 2) : "memory");
        __syncthreads();

        const int kn = kt + NSTAGE - 1;
        if (kn < NT) {
            const int s = kn & (NSTAGE - 1);
            const int koff = kn * TBK;
            const uint32_t sb = sbase + s * STB;
            cp16(sb + dOff,              Ahi + gA + koff);
            cp16(sb + TW * 4 + dOff,     Alo + gA + koff);
            cp16(sb + 2 * TW * 4 + dOff, Bhi + gB + koff);
            cp16(sb + 3 * TW * 4 + dOff, Blo + gB + koff);
        }
        asm volatile("cp.async.commit_group;" ::: "memory");

        const int st = kt & (NSTAGE - 1);
        const uint32_t* Ah = smw + st * STW;
        const uint32_t* Al = Ah + TW;
        const uint32_t* Bh = Al + TW;
        const uint32_t* Bl = Bh + TW;

        uint32_t bh[4][2], bl[4][2];
#pragma unroll
        for (int nt = 0; nt < 4; nt++) {
            const int r = (nrow + nt * 8) * RSW;
            bh[nt][0] = Bh[r + kc]; bh[nt][1] = Bh[r + kc + 4];
            bl[nt][0] = Bl[r + kc]; bl[nt][1] = Bl[r + kc + 4];
        }
#pragma unroll
        for (int mt = 0; mt < 4; mt++) {
            const int r0 = (mrow + mt * 16) * RSW;
            const int r1 = (mrow + mt * 16 + 8) * RSW;
            uint32_t ah0 = Ah[r0 + kc], ah1 = Ah[r1 + kc];
            uint32_t ah2 = Ah[r0 + kc + 4], ah3 = Ah[r1 + kc + 4];
            uint32_t al0 = Al[r0 + kc], al1 = Al[r1 + kc];
            uint32_t al2 = Al[r0 + kc + 4], al3 = Al[r1 + kc + 4];
#pragma unroll
            for (int nt = 0; nt < 4; nt++) {
                mma_bf16(acc[mt][nt], ah0, ah1, ah2, ah3, bh[nt][0], bh[nt][1]);
                mma_bf16(acc[mt][nt], al0, al1, al2, al3, bh[nt][0], bh[nt][1]);
                mma_bf16(acc[mt][nt], ah0, ah1, ah2, ah3, bl[nt][0], bl[nt][1]);
            }
        }
    }

#pragma unroll
    for (int mt = 0; mt < 4; mt++) {
        const int row = m0 + wm * 64 + mt * 16 + grp;
#pragma unroll
        for (int nt = 0; nt < 4; nt++) {
            const int col = n0 + wn * 32 + nt * 8 + kc * 2;
            *reinterpret_cast<float2*>(C + (size_t)row * N + col) =
                make_float2(acc[mt][nt][0], acc[mt][nt][1]);
            *reinterpret_cast<float2*>(C + (size_t)(row + 8) * N + col) =
                make_float2(acc[mt][nt][2], acc[mt][nt][3]);
        }
    }
}

__global__ __launch_bounds__(256, 2) void gemm_qkv_bf16()
{
    const int bx = blockIdx.x;
    const int m0 = blockIdx.y * 128;
    const __nv_bfloat16 *Bh, *Bl; float* C; int N, n0;
    if (bx < 16)      { Bh = g_wq_hi; Bl = g_wq_lo; C = g_q; N = NH  * HD; n0 = bx * 128; }
    else if (bx < 20) { Bh = g_wk_hi; Bl = g_wk_lo; C = g_k; N = NKV * HD; n0 = (bx - 16) * 128; }
    else              { Bh = g_wv_hi; Bl = g_wv_lo; C = g_v; N = NKV * HD; n0 = (bx - 20) * 128; }
    gemm_body_bf16(g_hid_hi, g_hid_lo, Bh, Bl, C, N, HIDD, m0, n0);
}

__global__ __launch_bounds__(256, 2) void gemm_o_bf16(float* __restrict__ out)
{
    gemm_body_bf16(g_attn_hi, g_attn_lo, g_wo_hi, g_wo_lo,
                   out, HIDD, NH * HD, blockIdx.y * 128, blockIdx.x * 128);
}

// ---------------- RMSNorm + RoPE: q in-place f32; k -> bf16 hi/lo --------------
__global__ void norm_rope_kernel(
    const float* __restrict__ cosv, const float* __restrict__ sinv,
    const float* __restrict__ qw,   const float* __restrict__ kw)
{
    const int gid  = blockIdx.x * blockDim.x + threadIdx.x;
    const int wid  = gid >> 5;
    const int lane = gid & 31;
    const int nqr  = MROWS * NH;
    const int ntot = nqr + MROWS * NKV;
    if (wid >= ntot) return;

    const bool isq = (wid < nqr);
    float* base;
    int bs, kvh = 0;
    const float* w;
    if (isq) { base = g_q + (size_t)wid * HD;  bs = wid / NH; w = qw; }
    else {
        int r = wid - nqr;
        base = g_k + (size_t)r * HD;
        bs = r / NKV; kvh = r % NKV; w = kw;
    }

    float x0 = base[lane];
    float x1 = base[lane + 32];
    float ss = x0 * x0 + x1 * x1;
#pragma unroll
    for (int o = 16; o > 0; o >>= 1) ss += __shfl_xor_sync(0xffffffffu, ss, o);
    const float rinv = rsqrtf(ss * (1.0f / HD) + EPS);

    const float n0 = w[lane]      * (x0 * rinv);
    const float n1 = w[lane + 32] * (x1 * rinv);

    const float c0 = cosv[(size_t)bs * HD + lane];
    const float c1 = cosv[(size_t)bs * HD + lane + 32];
    const float s0 = sinv[(size_t)bs * HD + lane];
    const float s1 = sinv[(size_t)bs * HD + lane + 32];

    const float o0 = n0 * c0 - n1 * s0;
    const float o1 = n1 * c1 + n0 * s1;

    if (isq) {
        base[lane]      = o0;
        base[lane + 32] = o1;
    } else {
        const int b_  = bs >> 11;          // / SS
        const int key = bs & (SS - 1);
        const size_t o = (((size_t)b_ * NKV + kvh) * SS + key) * HD;
        __nv_bfloat16 h0 = __float2bfloat16_rn(o0);
        __nv_bfloat16 h1 = __float2bfloat16_rn(o1);
        g_fk_hi[o + lane]      = h0;
        g_fk_hi[o + lane + 32] = h1;
        g_fk_lo[o + lane]      = __float2bfloat16_rn(o0 - __bfloat162float(h0));
        g_fk_lo[o + lane + 32] = __float2bfloat16_rn(o1 - __bfloat162float(h1));
    }
}

// ---------------- V transpose: f32 [b][key][kvh][d] -> bf16 [b][kvh][d][key] ---
// ts row stride 68 floats (multiple of 4) so &ts[row][c4] is 16B-aligned for
// the float4 stores (stride 65 was the R10 misaligned-address crash).
__global__ void v_transpose_kernel()
{
    __shared__ float ts[64][68];
    const int bk = blockIdx.y;             // b*NKV + kvh
    const int k0 = blockIdx.x * 64;
    const int b  = bk / NKV, kvh = bk % NKV;
    const int t  = threadIdx.x;

#pragma unroll
    for (int i = 0; i < 4; i++) {
        const int idx = t + i * 256;       // 0..1023 float4s
        const int row = idx >> 4;          // key 0..63
        const int c4  = (idx & 15) * 4;
        *reinterpret_cast<float4*>(&ts[row][c4]) =
            *reinterpret_cast<const float4*>(
                g_v + ((size_t)(b * SS + k0 + row) * NKV + kvh) * HD + c4);
    }
    __syncthreads();

    const int d  = t >> 2;
    const int kb = (t & 3) * 16;
    const size_t off = ((size_t)bk * HD + d) * SS + k0 + kb;
    uint32_t hi[8], lo[8];
#pragma unroll
    for (int j = 0; j < 8; j++) {
        const float v0 = ts[kb + 2 * j][d];
        const float v1 = ts[kb + 2 * j + 1][d];
        hi[j] = packbf(v0, v1);
        lo[j] = packlo(v0, v1, hi[j]);
    }
    reinterpret_cast<uint4*>(g_vT_hi + off)[0] = make_uint4(hi[0], hi[1], hi[2], hi[3]);
    reinterpret_cast<uint4*>(g_vT_hi + off)[1] = make_uint4(hi[4], hi[5], hi[6], hi[7]);
    reinterpret_cast<uint4*>(g_vT_lo + off)[0] = make_uint4(lo[0], lo[1], lo[2], lo[3]);
    reinterpret_cast<uint4*>(g_vT_lo + off)[1] = make_uint4(lo[4], lo[5], lo[6], lo[7]);
}

// ---------------- bf16 tensor-core causal flash attention ----------------------
// 128 q-rows/block, 8 warps x 16 rows, 64-key tiles.
// S = (Qh+Ql)(Kh+Kl)^T 3-term bf16; P = exp(S-m) repacked IN REGISTERS
// (C-frag -> A-frag is the identity for m16n8k16); O += (Ph+Pl)(Vh+Vl) 3-term.
// SMEM rows stride 36 words: (36g+kc) mod 32 = (4g+kc) -> conflict-free.
#define FBQ 128
#define FKW 36
#define FLASH_SMEM (4 * 64 * FKW * 4)    // 36864 B

__global__ __launch_bounds__(256, 2) void flash_mma_kernel()
{
    const int bh  = blockIdx.y;
    const int b   = bh / NH;
    const int h   = bh % NH;
    const int kvh = h / (NH / NKV);
    const int q0  = blockIdx.x * FBQ;
    const int tid = threadIdx.x;
    const int lane = tid & 31;
    const int w    = tid >> 5;
    const int grp  = lane >> 2;
    const int kc   = lane & 3;

    extern __shared__ uint32_t fsm[];
    const uint32_t* Kh = fsm;
    const uint32_t* Kl = Kh + 64 * FKW;
    const uint32_t* Vh = Kl + 64 * FKW;
    const uint32_t* Vl = Vh + 64 * FKW;
    const uint32_t sb = (uint32_t)__cvta_generic_to_shared(fsm);

    const size_t kvb = (size_t)b * NKV + kvh;
    const __nv_bfloat16* gKh = g_fk_hi + kvb * SS * HD;
    const __nv_bfloat16* gKl = g_fk_lo + kvb * SS * HD;
    const __nv_bfloat16* gVh = g_vT_hi + kvb * HD * SS;
    const __nv_bfloat16* gVl = g_vT_lo + kvb * HD * SS;

    // Q fragments (bf16 hi/lo, pre-scaled)
    const int qrow0 = q0 + w * 16 + grp;
    const float* Q0 = g_q + ((size_t)(b * SS + qrow0) * NH + h) * HD;
    const float* Q1 = Q0 + (size_t)8 * NH * HD;
    uint32_t aQh[4][4], aQl[4][4];
#pragma unroll
    for (int ks = 0; ks < 4; ks++) {
#pragma unroll
        for (int p = 0; p < 4; p++) {
            const float* Qr = (p & 1) ? Q1 : Q0;
            const int d = ks * 16 + ((p >> 1) ? 8 : 0) + kc * 2;
            float2 v = *reinterpret_cast<const float2*>(Qr + d);
            v.x *= SCALE; v.y *= SCALE;
            aQh[ks][p] = packbf(v.x, v.y);
            aQl[ks][p] = packlo(v.x, v.y, aQh[ks][p]);
        }
    }

    float c_o[8][4];
#pragma unroll
    for (int nt = 0; nt < 8; nt++)
#pragma unroll
        for (int f = 0; f < 4; f++) c_o[nt][f] = 0.f;

    float m0 = -FLT_MAX, m1 = -FLT_MAX, l0 = 0.f, l1 = 0.f;

    for (int k0 = 0; k0 < q0 + FBQ; k0 += 64) {
        // ---- load K/V tile: 4 regions x 512 16B chunks, 2 per thread each ----
#pragma unroll
        for (int r = 0; r < 2; r++) {
            const int idx = tid + r * 256;     // 0..511
            const int row = idx >> 3;          // key (K) / d (V^T)
            const int ch  = idx & 7;
            const uint32_t doff = row * 144 + ch * 16;
            cp16(sb + doff,                 gKh + (size_t)(k0 + row) * HD + ch * 8);
            cp16(sb + 64*144 + doff,        gKl + (size_t)(k0 + row) * HD + ch * 8);
            cp16(sb + 2*64*144 + doff,      gVh + (size_t)row * SS + k0 + ch * 8);
            cp16(sb + 3*64*144 + doff,      gVl + (size_t)row * SS + k0 + ch * 8);
        }
        asm volatile("cp.async.commit_group;" ::: "memory");
        asm volatile("cp.async.wait_group 0;" ::: "memory");
        __syncthreads();

        // ---- S = Q @ K^T (bf16x3) ----
        float c_s[8][4];
#pragma unroll
        for (int nt = 0; nt < 8; nt++)
#pragma unroll
            for (int f = 0; f < 4; f++) c_s[nt][f] = 0.f;

#pragma unroll
        for (int ks = 0; ks < 4; ks++) {
#pragma unroll
            for (int nt = 0; nt < 8; nt++) {
                const uint32_t* kr  = Kh + (nt * 8 + grp) * FKW + ks * 8;
                const uint32_t* krl = Kl + (nt * 8 + grp) * FKW + ks * 8;
                const uint32_t bh0 = kr[kc],  bh1 = kr[kc + 4];
                const uint32_t bl0 = krl[kc], bl1 = krl[kc + 4];
                mma_bf16(c_s[nt], aQh[ks][0], aQh[ks][1], aQh[ks][2], aQh[ks][3], bh0, bh1);
                mma_bf16(c_s[nt], aQl[ks][0], aQl[ks][1], aQl[ks][2], aQl[ks][3], bh0, bh1);
                mma_bf16(c_s[nt], aQh[ks][0], aQh[ks][1], aQh[ks][2], aQh[ks][3], bl0, bl1);
            }
        }

        // ---- causal mask (diagonal tiles only) ----
        if (k0 + 64 > q0) {
#pragma unroll
            for (int nt = 0; nt < 8; nt++) {
                const int col = k0 + nt * 8 + kc * 2;
                if (col     > qrow0)     c_s[nt][0] = -FLT_MAX;
                if (col + 1 > qrow0)     c_s[nt][1] = -FLT_MAX;
                if (col     > qrow0 + 8) c_s[nt][2] = -FLT_MAX;
                if (col + 1 > qrow0 + 8) c_s[nt][3] = -FLT_MAX;
            }
        }

        // ---- online softmax ----
        float mx0 = -FLT_MAX, mx1 = -FLT_MAX;
#pragma unroll
        for (int nt = 0; nt < 8; nt++) {
            mx0 = fmaxf(mx0, fmaxf(c_s[nt][0], c_s[nt][1]));
            mx1 = fmaxf(mx1, fmaxf(c_s[nt][2], c_s[nt][3]));
        }
        mx0 = fmaxf(mx0, __shfl_xor_sync(0xffffffffu, mx0, 1));
        mx0 = fmaxf(mx0, __shfl_xor_sync(0xffffffffu, mx0, 2));
        mx1 = fmaxf(mx1, __shfl_xor_sync(0xffffffffu, mx1, 1));
        mx1 = fmaxf(mx1, __shfl_xor_sync(0xffffffffu, mx1, 2));

        const float mn0 = fmaxf(m0, mx0);
        const float mn1 = fmaxf(m1, mx1);
        const float cor0 = __expf(m0 - mn0);
        const float cor1 = __expf(m1 - mn1);
        m0 = mn0; m1 = mn1;

        float rs0 = 0.f, rs1 = 0.f;
#pragma unroll
        for (int nt = 0; nt < 8; nt++) {
            c_s[nt][0] = __expf(c_s[nt][0] - mn0);
            c_s[nt][1] = __expf(c_s[nt][1] - mn0);
            c_s[nt][2] = __expf(c_s[nt][2] - mn1);
            c_s[nt][3] = __expf(c_s[nt][3] - mn1);
            rs0 += c_s[nt][0] + c_s[nt][1];
            rs1 += c_s[nt][2] + c_s[nt][3];
        }
        rs0 += __shfl_xor_sync(0xffffffffu, rs0, 1);
        rs0 += __shfl_xor_sync(0xffffffffu, rs0, 2);
        rs1 += __shfl_xor_sync(0xffffffffu, rs1, 1);
        rs1 += __shfl_xor_sync(0xffffffffu, rs1, 2);
        l0 = l0 * cor0 + rs0;
        l1 = l1 * cor1 + rs1;

#pragma unroll
        for (int nt = 0; nt < 8; nt++) {
            c_o[nt][0] *= cor0; c_o[nt][1] *= cor0;
            c_o[nt][2] *= cor1; c_o[nt][3] *= cor1;
        }

        // ---- O += P @ V (bf16x3): C-frag -> A-frag repack is register-local ---
#pragma unroll
        for (int ks = 0; ks < 4; ks++) {
            const uint32_t p0 = packbf(c_s[2*ks][0],   c_s[2*ks][1]);
            const uint32_t p1 = packbf(c_s[2*ks][2],   c_s[2*ks][3]);
            const uint32_t p2 = packbf(c_s[2*ks+1][0], c_s[2*ks+1][1]);
            const uint32_t p3 = packbf(c_s[2*ks+1][2], c_s[2*ks+1][3]);
            const uint32_t q0l = packlo(c_s[2*ks][0],   c_s[2*ks][1],   p0);
            const uint32_t q1l = packlo(c_s[2*ks][2],   c_s[2*ks][3],   p1);
            const uint32_t q2l = packlo(c_s[2*ks+1][0], c_s[2*ks+1][1], p2);
            const uint32_t q3l = packlo(c_s[2*ks+1][2], c_s[2*ks+1][3], p3);
#pragma unroll
            for (int nt = 0; nt < 8; nt++) {
                const uint32_t* vr  = Vh + (nt * 8 + grp) * FKW + ks * 8;
                const uint32_t* vrl = Vl + (nt * 8 + grp) * FKW + ks * 8;
                const uint32_t bh0 = vr[kc],  bh1 = vr[kc + 4];
                const uint32_t bl0 = vrl[kc], bl1 = vrl[kc + 4];
                mma_bf16(c_o[nt], p0, p1, p2, p3, bh0, bh1);
                mma_bf16(c_o[nt], q0l, q1l, q2l, q3l, bh0, bh1);
                mma_bf16(c_o[nt], p0, p1, p2, p3, bl0, bl1);
            }
        }
        __syncthreads();    // all warps done with tile before next overwrite
    }

    // ---- epilogue: normalize and store bf16 {hi,lo} for O-projection ----
    const float inv0 = 1.f / l0;
    const float inv1 = 1.f / l1;
    const size_t off0 = ((size_t)(b * SS + qrow0) * NH + h) * HD;
    const size_t off1 = off0 + (size_t)8 * NH * HD;
#pragma unroll
    for (int nt = 0; nt < 8; nt++) {
        const int c = nt * 8 + kc * 2;
        const float v0 = c_o[nt][0] * inv0, v1 = c_o[nt][1] * inv0;
        const uint32_t h01 = packbf(v0, v1);
        *reinterpret_cast<uint32_t*>(g_attn_hi + off0 + c) = h01;
        *reinterpret_cast<uint32_t*>(g_attn_lo + off0 + c) = packlo(v0, v1, h01);
        const float v2 = c_o[nt][2] * inv1, v3 = c_o[nt][3] * inv1;
        const uint32_t h23 = packbf(v2, v3);
        *reinterpret_cast<uint32_t*>(g_attn_hi + off1 + c) = h23;
        *reinterpret_cast<uint32_t*>(g_attn_lo + off1 + c) = packlo(v2, v3, h23);
    }
}

// ------------------------------- launch ---------------------------------------
extern "C" void kernel_launch(void* const* d_in, const int* in_sizes, int n_in,
                              void* d_out, int out_size)
{
    const float* hidden = (const float*)d_in[0];
    const float* cosv   = (const float*)d_in[1];
    const float* sinv   = (const float*)d_in[2];
    const float* Wq     = (const float*)d_in[3];
    const float* Wk     = (const float*)d_in[4];
    const float* Wv     = (const float*)d_in[5];
    const float* Wo     = (const float*)d_in[6];
    const float* qw     = (const float*)d_in[7];
    const float* kw     = (const float*)d_in[8];
    float* out          = (float*)d_out;

    __nv_bfloat162 *phh, *phl, *pqh, *pql, *pkh, *pkl, *pvh, *pvl, *poh, *pol;
    cudaGetSymbolAddress((void**)&phh, g_hid_hi);
    cudaGetSymbolAddress((void**)&phl, g_hid_lo);
    cudaGetSymbolAddress((void**)&pqh, g_wq_hi);
    cudaGetSymbolAddress((void**)&pql, g_wq_lo);
    cudaGetSymbolAddress((void**)&pkh, g_wk_hi);
    cudaGetSymbolAddress((void**)&pkl, g_wk_lo);
    cudaGetSymbolAddress((void**)&pvh, g_wv_hi);
    cudaGetSymbolAddress((void**)&pvl, g_wv_lo);
    cudaGetSymbolAddress((void**)&poh, g_wo_hi);
    cudaGetSymbolAddress((void**)&pol, g_wo_lo);

    cudaFuncSetAttribute(gemm_qkv_bf16, cudaFuncAttributeMaxDynamicSharedMemorySize, GEMM_SMEM);
    cudaFuncSetAttribute(gemm_o_bf16,   cudaFuncAttributeMaxDynamicSharedMemorySize, GEMM_SMEM);
    cudaFuncSetAttribute(flash_mma_kernel, cudaFuncAttributeMaxDynamicSharedMemorySize, FLASH_SMEM);

    // prep: split inputs/weights to bf16 hi/lo
    {
        const int nh4 = MROWS * HIDD / 4;
        split_bf16_pass<<<(nh4 + 255) / 256, 256>>>((const float4*)hidden, phh, phl, nh4);
        const int nq4 = NH * HD * HIDD / 4;
        const int nk4 = NKV * HD * HIDD / 4;
        split_bf16_pass<<<(nq4 + 255) / 256, 256>>>((const float4*)Wq, pqh, pql, nq4);
        split_bf16_pass<<<(nk4 + 255) / 256, 256>>>((const float4*)Wk, pkh, pkl, nk4);
        split_bf16_pass<<<(nk4 + 255) / 256, 256>>>((const float4*)Wv, pvh, pvl, nk4);
        split_bf16_pass<<<(nq4 + 255) / 256, 256>>>((const float4*)Wo, poh, pol, nq4);
    }

    // Fused QKV projections (bf16x3 tensor core)
    gemm_qkv_bf16<<<dim3(24, MROWS / 128), 256, GEMM_SMEM>>>();

    // RMSNorm + RoPE (q f32 in-place, k -> bf16 hi/lo flash layout)
    {
        const int warps = MROWS * NH + MROWS * NKV;
        const int threads = warps * 32;
        norm_rope_kernel<<<(threads + 255) / 256, 256>>>(cosv, sinv, qw, kw);
    }

    // V -> V^T bf16 hi/lo
    v_transpose_kernel<<<dim3(SS / 64, BB * NKV), 256>>>();

    // bf16 tensor-core causal flash attention
    flash_mma_kernel<<<dim3(SS / FBQ, BB * NH), 256, FLASH_SMEM>>>();

    // output projection -> d_out
    gemm_o_bf16<<<dim3(HIDD / 128, MROWS / 128), 256, GEMM_SMEM>>>(out);
}

// round 14
// speedup vs baseline: 3.1665x; 1.1138x over previous
#include <cuda_runtime.h>
#include <cuda_bf16.h>
#include <float.h>
#include <stdint.h>

// Problem constants
#define BB   2
#define SS   2048
#define HIDD 2048
#define NH   32
#define NKV  8
#define HD   64
#define MROWS (BB*SS)          // 4096
#define SCALE 0.125f           // HD^-0.5
#define EPS   1e-6f

// ---------------- scratch -----------------------------------------------------
__device__ float g_q[(size_t)MROWS * NH * HD];
__device__ float g_k[(size_t)MROWS * NKV * HD];
__device__ float g_v[(size_t)MROWS * NKV * HD];

__device__ __align__(16) __nv_bfloat16 g_hid_hi[(size_t)MROWS * HIDD];
__device__ __align__(16) __nv_bfloat16 g_hid_lo[(size_t)MROWS * HIDD];
__device__ __align__(16) __nv_bfloat16 g_attn_hi[(size_t)MROWS * NH * HD];
__device__ __align__(16) __nv_bfloat16 g_attn_lo[(size_t)MROWS * NH * HD];
__device__ __align__(16) __nv_bfloat16 g_wq_hi[(size_t)NH  * HD * HIDD];
__device__ __align__(16) __nv_bfloat16 g_wq_lo[(size_t)NH  * HD * HIDD];
__device__ __align__(16) __nv_bfloat16 g_wk_hi[(size_t)NKV * HD * HIDD];
__device__ __align__(16) __nv_bfloat16 g_wk_lo[(size_t)NKV * HD * HIDD];
__device__ __align__(16) __nv_bfloat16 g_wv_hi[(size_t)NKV * HD * HIDD];
__device__ __align__(16) __nv_bfloat16 g_wv_lo[(size_t)NKV * HD * HIDD];
__device__ __align__(16) __nv_bfloat16 g_wo_hi[(size_t)HIDD * NH * HD];
__device__ __align__(16) __nv_bfloat16 g_wo_lo[(size_t)HIDD * NH * HD];

// flash operands
__device__ __align__(16) __nv_bfloat16 g_fk_hi[(size_t)BB * NKV * SS * HD];
__device__ __align__(16) __nv_bfloat16 g_fk_lo[(size_t)BB * NKV * SS * HD];
__device__ __align__(16) __nv_bfloat16 g_vT_hi[(size_t)BB * NKV * HD * SS];
__device__ __align__(16) __nv_bfloat16 g_vT_lo[(size_t)BB * NKV * HD * SS];

// ---------------- helpers ------------------------------------------------------
__device__ __forceinline__ uint32_t packbf(float x, float y) {
    __nv_bfloat162 t = __floats2bfloat162_rn(x, y);
    return *reinterpret_cast<uint32_t*>(&t);
}
__device__ __forceinline__ uint32_t packlo(float x, float y, uint32_t hi) {
    __nv_bfloat162 h = *reinterpret_cast<__nv_bfloat162*>(&hi);
    return packbf(x - __bfloat162float(h.x), y - __bfloat162float(h.y));
}

__device__ __forceinline__ void mma_bf16(float c[4],
    uint32_t a0, uint32_t a1, uint32_t a2, uint32_t a3,
    uint32_t b0, uint32_t b1)
{
    asm volatile(
        "mma.sync.aligned.m16n8k16.row.col.f32.bf16.bf16.f32 "
        "{%0,%1,%2,%3}, {%4,%5,%6,%7}, {%8,%9}, {%0,%1,%2,%3};"
        : "+f"(c[0]), "+f"(c[1]), "+f"(c[2]), "+f"(c[3])
        : "r"(a0), "r"(a1), "r"(a2), "r"(a3), "r"(b0), "r"(b1));
}

__device__ __forceinline__ void cp16(uint32_t dst, const void* src) {
    asm volatile("cp.async.cg.shared.global [%0], [%1], 16;" :: "r"(dst), "l"(src));
}

__device__ __forceinline__ void ldsm4(uint32_t& r0, uint32_t& r1,
                                      uint32_t& r2, uint32_t& r3, uint32_t addr)
{
    asm volatile("ldmatrix.sync.aligned.m8n8.x4.shared.b16 {%0,%1,%2,%3}, [%4];"
                 : "=r"(r0), "=r"(r1), "=r"(r2), "=r"(r3) : "r"(addr));
}

// ---------------- prep: split fp32 -> bf16 {hi, lo} ----------------------------
__global__ void split_bf16_pass(const float4* __restrict__ src,
                                __nv_bfloat162* __restrict__ hi,
                                __nv_bfloat162* __restrict__ lo, int n4)
{
    const int i = blockIdx.x * blockDim.x + threadIdx.x;
    if (i >= n4) return;
    float4 v = src[i];
    __nv_bfloat16 h0 = __float2bfloat16_rn(v.x);
    __nv_bfloat16 h1 = __float2bfloat16_rn(v.y);
    __nv_bfloat16 h2 = __float2bfloat16_rn(v.z);
    __nv_bfloat16 h3 = __float2bfloat16_rn(v.w);
    hi[i * 2 + 0] = __nv_bfloat162(h0, h1);
    hi[i * 2 + 1] = __nv_bfloat162(h2, h3);
    lo[i * 2 + 0] = __nv_bfloat162(
        __float2bfloat16_rn(v.x - __bfloat162float(h0)),
        __float2bfloat16_rn(v.y - __bfloat162float(h1)));
    lo[i * 2 + 1] = __nv_bfloat162(
        __float2bfloat16_rn(v.z - __bfloat162float(h2)),
        __float2bfloat16_rn(v.w - __bfloat162float(h3)));
}

// ---------------- bf16x3 cp.async GEMM with ldmatrix ---------------------------
// Block tile 128x128, TBK=16, 4-stage cp.async ring.
// SMEM rows: 16 bf16 (32 B data) in 48 B stride rows -> ldmatrix 8-row phases
// hit word banks 12r mod 32: all distinct, conflict-free.
// Fragments via ldmatrix.x4 (12/iter vs 48 scalar LDS).
#define TBK 16
#define NSTAGE 4
#define RSW 12
#define TILEB (128 * RSW * 4)         // 6144 bytes per tile-split
#define STB (4 * TILEB)               // 24576 bytes per stage
#define GEMM_SMEM (NSTAGE * STB)      // 98304

__device__ __forceinline__ void gemm_body_bf16(
    const __nv_bfloat16* __restrict__ Ahi, const __nv_bfloat16* __restrict__ Alo,
    const __nv_bfloat16* __restrict__ Bhi, const __nv_bfloat16* __restrict__ Blo,
    float* __restrict__ C, int N, int K, int m0, int n0)
{
    extern __shared__ uint32_t smw[];
    const uint32_t sbase = (uint32_t)__cvta_generic_to_shared(smw);

    const int t    = threadIdx.x;
    const int lane = t & 31;
    const int warp = t >> 5;
    const int wm   = warp & 1;
    const int wn   = warp >> 1;
    const int grp  = lane >> 2;
    const int kc   = lane & 3;

    const int lrow = t >> 1;
    const int lhalf = t & 1;
    const size_t gA = (size_t)(m0 + lrow) * K + lhalf * 8;
    const size_t gB = (size_t)(n0 + lrow) * K + lhalf * 8;
    const uint32_t dOff = lrow * 48 + lhalf * 16;

    // ldmatrix per-thread offsets
    const int l15 = lane & 15;
    const int l7  = lane & 7;
    const uint32_t aKhalf = (lane >> 4) * 16;          // A: lanes 16-31 -> k8-15
    const uint32_t bKhalf = ((lane >> 3) & 1) * 16;    // B: lanes 8-15/24-31 -> k8-15
    const int bRow8  = (lane >> 4) * 8;                // B: lanes 16-31 -> 2nd n-block

    float acc[4][4][4];
#pragma unroll
    for (int i = 0; i < 4; i++)
#pragma unroll
        for (int j = 0; j < 4; j++)
#pragma unroll
            for (int f = 0; f < 4; f++) acc[i][j][f] = 0.f;

    const int NT = K / TBK;

#pragma unroll
    for (int s = 0; s < NSTAGE - 1; s++) {
        const int koff = s * TBK;
        const uint32_t sb = sbase + s * STB;
        cp16(sb + dOff,             Ahi + gA + koff);
        cp16(sb + TILEB + dOff,     Alo + gA + koff);
        cp16(sb + 2 * TILEB + dOff, Bhi + gB + koff);
        cp16(sb + 3 * TILEB + dOff, Blo + gB + koff);
        asm volatile("cp.async.commit_group;" ::: "memory");
    }

#pragma unroll 4
    for (int kt = 0; kt < NT; kt++) {
        asm volatile("cp.async.wait_group %0;" :: "n"(NSTAGE - 2) : "memory");
        __syncthreads();

        const int kn = kt + NSTAGE - 1;
        if (kn < NT) {
            const int s = kn & (NSTAGE - 1);
            const int koff = kn * TBK;
            const uint32_t sb = sbase + s * STB;
            cp16(sb + dOff,             Ahi + gA + koff);
            cp16(sb + TILEB + dOff,     Alo + gA + koff);
            cp16(sb + 2 * TILEB + dOff, Bhi + gB + koff);
            cp16(sb + 3 * TILEB + dOff, Blo + gB + koff);
        }
        asm volatile("cp.async.commit_group;" ::: "memory");

        const uint32_t stb = sbase + (kt & (NSTAGE - 1)) * STB;

        uint32_t ah[4][4], al[4][4];
#pragma unroll
        for (int mt = 0; mt < 4; mt++) {
            const uint32_t ra = stb + (uint32_t)(wm * 64 + mt * 16 + l15) * 48 + aKhalf;
            ldsm4(ah[mt][0], ah[mt][1], ah[mt][2], ah[mt][3], ra);
            ldsm4(al[mt][0], al[mt][1], al[mt][2], al[mt][3], ra + TILEB);
        }
        uint32_t bh[4][2], bl[4][2];
#pragma unroll
        for (int p = 0; p < 2; p++) {
            const uint32_t rb = stb + 2 * TILEB
                + (uint32_t)(wn * 32 + p * 16 + bRow8 + l7) * 48 + bKhalf;
            ldsm4(bh[2*p][0], bh[2*p][1], bh[2*p+1][0], bh[2*p+1][1], rb);
            ldsm4(bl[2*p][0], bl[2*p][1], bl[2*p+1][0], bl[2*p+1][1], rb + TILEB);
        }

#pragma unroll
        for (int mt = 0; mt < 4; mt++) {
#pragma unroll
            for (int nt = 0; nt < 4; nt++) {
                mma_bf16(acc[mt][nt], ah[mt][0], ah[mt][1], ah[mt][2], ah[mt][3],
                         bh[nt][0], bh[nt][1]);
                mma_bf16(acc[mt][nt], al[mt][0], al[mt][1], al[mt][2], al[mt][3],
                         bh[nt][0], bh[nt][1]);
                mma_bf16(acc[mt][nt], ah[mt][0], ah[mt][1], ah[mt][2], ah[mt][3],
                         bl[nt][0], bl[nt][1]);
            }
        }
    }

#pragma unroll
    for (int mt = 0; mt < 4; mt++) {
        const int row = m0 + wm * 64 + mt * 16 + grp;
#pragma unroll
        for (int nt = 0; nt < 4; nt++) {
            const int col = n0 + wn * 32 + nt * 8 + kc * 2;
            *reinterpret_cast<float2*>(C + (size_t)row * N + col) =
                make_float2(acc[mt][nt][0], acc[mt][nt][1]);
            *reinterpret_cast<float2*>(C + (size_t)(row + 8) * N + col) =
                make_float2(acc[mt][nt][2], acc[mt][nt][3]);
        }
    }
}

__global__ __launch_bounds__(256, 2) void gemm_qkv_bf16()
{
    const int bx = blockIdx.x;
    const int m0 = blockIdx.y * 128;
    const __nv_bfloat16 *Bh, *Bl; float* C; int N, n0;
    if (bx < 16)      { Bh = g_wq_hi; Bl = g_wq_lo; C = g_q; N = NH  * HD; n0 = bx * 128; }
    else if (bx < 20) { Bh = g_wk_hi; Bl = g_wk_lo; C = g_k; N = NKV * HD; n0 = (bx - 16) * 128; }
    else              { Bh = g_wv_hi; Bl = g_wv_lo; C = g_v; N = NKV * HD; n0 = (bx - 20) * 128; }
    gemm_body_bf16(g_hid_hi, g_hid_lo, Bh, Bl, C, N, HIDD, m0, n0);
}

__global__ __launch_bounds__(256, 2) void gemm_o_bf16(float* __restrict__ out)
{
    gemm_body_bf16(g_attn_hi, g_attn_lo, g_wo_hi, g_wo_lo,
                   out, HIDD, NH * HD, blockIdx.y * 128, blockIdx.x * 128);
}

// ---------------- RMSNorm + RoPE: q in-place f32; k -> bf16 hi/lo --------------
__global__ void norm_rope_kernel(
    const float* __restrict__ cosv, const float* __restrict__ sinv,
    const float* __restrict__ qw,   const float* __restrict__ kw)
{
    const int gid  = blockIdx.x * blockDim.x + threadIdx.x;
    const int wid  = gid >> 5;
    const int lane = gid & 31;
    const int nqr  = MROWS * NH;
    const int ntot = nqr + MROWS * NKV;
    if (wid >= ntot) return;

    const bool isq = (wid < nqr);
    float* base;
    int bs, kvh = 0;
    const float* w;
    if (isq) { base = g_q + (size_t)wid * HD;  bs = wid / NH; w = qw; }
    else {
        int r = wid - nqr;
        base = g_k + (size_t)r * HD;
        bs = r / NKV; kvh = r % NKV; w = kw;
    }

    float x0 = base[lane];
    float x1 = base[lane + 32];
    float ss = x0 * x0 + x1 * x1;
#pragma unroll
    for (int o = 16; o > 0; o >>= 1) ss += __shfl_xor_sync(0xffffffffu, ss, o);
    const float rinv = rsqrtf(ss * (1.0f / HD) + EPS);

    const float n0 = w[lane]      * (x0 * rinv);
    const float n1 = w[lane + 32] * (x1 * rinv);

    const float c0 = cosv[(size_t)bs * HD + lane];
    const float c1 = cosv[(size_t)bs * HD + lane + 32];
    const float s0 = sinv[(size_t)bs * HD + lane];
    const float s1 = sinv[(size_t)bs * HD + lane + 32];

    const float o0 = n0 * c0 - n1 * s0;
    const float o1 = n1 * c1 + n0 * s1;

    if (isq) {
        base[lane]      = o0;
        base[lane + 32] = o1;
    } else {
        const int b_  = bs >> 11;
        const int key = bs & (SS - 1);
        const size_t o = (((size_t)b_ * NKV + kvh) * SS + key) * HD;
        __nv_bfloat16 h0 = __float2bfloat16_rn(o0);
        __nv_bfloat16 h1 = __float2bfloat16_rn(o1);
        g_fk_hi[o + lane]      = h0;
        g_fk_hi[o + lane + 32] = h1;
        g_fk_lo[o + lane]      = __float2bfloat16_rn(o0 - __bfloat162float(h0));
        g_fk_lo[o + lane + 32] = __float2bfloat16_rn(o1 - __bfloat162float(h1));
    }
}

// ---------------- V transpose: f32 [b][key][kvh][d] -> bf16 [b][kvh][d][key] ---
__global__ void v_transpose_kernel()
{
    __shared__ float ts[64][68];
    const int bk = blockIdx.y;
    const int k0 = blockIdx.x * 64;
    const int b  = bk / NKV, kvh = bk % NKV;
    const int t  = threadIdx.x;

#pragma unroll
    for (int i = 0; i < 4; i++) {
        const int idx = t + i * 256;
        const int row = idx >> 4;
        const int c4  = (idx & 15) * 4;
        *reinterpret_cast<float4*>(&ts[row][c4]) =
            *reinterpret_cast<const float4*>(
                g_v + ((size_t)(b * SS + k0 + row) * NKV + kvh) * HD + c4);
    }
    __syncthreads();

    const int d  = t >> 2;
    const int kb = (t & 3) * 16;
    const size_t off = ((size_t)bk * HD + d) * SS + k0 + kb;
    uint32_t hi[8], lo[8];
#pragma unroll
    for (int j = 0; j < 8; j++) {
        const float v0 = ts[kb + 2 * j][d];
        const float v1 = ts[kb + 2 * j + 1][d];
        hi[j] = packbf(v0, v1);
        lo[j] = packlo(v0, v1, hi[j]);
    }
    reinterpret_cast<uint4*>(g_vT_hi + off)[0] = make_uint4(hi[0], hi[1], hi[2], hi[3]);
    reinterpret_cast<uint4*>(g_vT_hi + off)[1] = make_uint4(hi[4], hi[5], hi[6], hi[7]);
    reinterpret_cast<uint4*>(g_vT_lo + off)[0] = make_uint4(lo[0], lo[1], lo[2], lo[3]);
    reinterpret_cast<uint4*>(g_vT_lo + off)[1] = make_uint4(lo[4], lo[5], lo[6], lo[7]);
}

// ---------------- bf16 tensor-core causal flash attention ----------------------
// Double-buffered 64-key tiles (prefetch t+1 before waiting on t) + ldmatrix
// fragment loads. Rows stride 36 words (144 B): ldmatrix phases conflict-free.
#define FBQ 128
#define FKW 36
#define FBUF (4 * 64 * FKW * 4)          // 36864 B per buffer
#define FREG (64 * FKW * 4)              // 9216 B per tile-split
#define FLASH_SMEM (2 * FBUF)            // 73728 B

__global__ __launch_bounds__(256, 2) void flash_mma_kernel()
{
    const int bh  = blockIdx.y;
    const int b   = bh / NH;
    const int h   = bh % NH;
    const int kvh = h / (NH / NKV);
    const int q0  = blockIdx.x * FBQ;
    const int tid = threadIdx.x;
    const int lane = tid & 31;
    const int w    = tid >> 5;
    const int grp  = lane >> 2;
    const int kc   = lane & 3;

    extern __shared__ uint32_t fsm[];
    const uint32_t sb = (uint32_t)__cvta_generic_to_shared(fsm);

    const size_t kvb = (size_t)b * NKV + kvh;
    const __nv_bfloat16* gKh = g_fk_hi + kvb * SS * HD;
    const __nv_bfloat16* gKl = g_fk_lo + kvb * SS * HD;
    const __nv_bfloat16* gVh = g_vT_hi + kvb * HD * SS;
    const __nv_bfloat16* gVl = g_vT_lo + kvb * HD * SS;

    // ldmatrix B-operand offsets
    const int l7  = lane & 7;
    const uint32_t bKhalf = ((lane >> 3) & 1) * 16;
    const int bRow8  = (lane >> 4) * 8;

    // Q fragments (bf16 hi/lo, pre-scaled)
    const int qrow0 = q0 + w * 16 + grp;
    const float* Q0 = g_q + ((size_t)(b * SS + qrow0) * NH + h) * HD;
    const float* Q1 = Q0 + (size_t)8 * NH * HD;
    uint32_t aQh[4][4], aQl[4][4];
#pragma unroll
    for (int ks = 0; ks < 4; ks++) {
#pragma unroll
        for (int p = 0; p < 4; p++) {
            const float* Qr = (p & 1) ? Q1 : Q0;
            const int d = ks * 16 + ((p >> 1) ? 8 : 0) + kc * 2;
            float2 v = *reinterpret_cast<const float2*>(Qr + d);
            v.x *= SCALE; v.y *= SCALE;
            aQh[ks][p] = packbf(v.x, v.y);
            aQl[ks][p] = packlo(v.x, v.y, aQh[ks][p]);
        }
    }

    float c_o[8][4];
#pragma unroll
    for (int nt = 0; nt < 8; nt++)
#pragma unroll
        for (int f = 0; f < 4; f++) c_o[nt][f] = 0.f;

    float m0 = -FLT_MAX, m1 = -FLT_MAX, l0 = 0.f, l1 = 0.f;

    const int NT = (q0 + FBQ) / 64;

    // prefetch tile 0 -> buf 0
    {
#pragma unroll
        for (int r = 0; r < 2; r++) {
            const int idx = tid + r * 256;
            const int row = idx >> 3;
            const int ch  = idx & 7;
            const uint32_t doff = row * 144 + ch * 16;
            cp16(sb + doff,            gKh + (size_t)row * HD + ch * 8);
            cp16(sb + FREG + doff,     gKl + (size_t)row * HD + ch * 8);
            cp16(sb + 2 * FREG + doff, gVh + (size_t)row * SS + ch * 8);
            cp16(sb + 3 * FREG + doff, gVl + (size_t)row * SS + ch * 8);
        }
        asm volatile("cp.async.commit_group;" ::: "memory");
    }

    for (int ti = 0; ti < NT; ti++) {
        const int k0 = ti * 64;
        // prefetch tile ti+1 into other buffer (its prior readers finished
        // at the trailing barrier of iteration ti-1)
        if (ti + 1 < NT) {
            const int kn = k0 + 64;
            const uint32_t bo = sb + ((ti + 1) & 1) * FBUF;
#pragma unroll
            for (int r = 0; r < 2; r++) {
                const int idx = tid + r * 256;
                const int row = idx >> 3;
                const int ch  = idx & 7;
                const uint32_t doff = row * 144 + ch * 16;
                cp16(bo + doff,            gKh + (size_t)(kn + row) * HD + ch * 8);
                cp16(bo + FREG + doff,     gKl + (size_t)(kn + row) * HD + ch * 8);
                cp16(bo + 2 * FREG + doff, gVh + (size_t)row * SS + kn + ch * 8);
                cp16(bo + 3 * FREG + doff, gVl + (size_t)row * SS + kn + ch * 8);
            }
            asm volatile("cp.async.commit_group;" ::: "memory");
            asm volatile("cp.async.wait_group 1;" ::: "memory");
        } else {
            asm volatile("cp.async.wait_group 0;" ::: "memory");
        }
        __syncthreads();

        const uint32_t buf = sb + (ti & 1) * FBUF;

        // ---- S = Q @ K^T (bf16x3, ldmatrix B frags) ----
        float c_s[8][4];
#pragma unroll
        for (int nt = 0; nt < 8; nt++)
#pragma unroll
            for (int f = 0; f < 4; f++) c_s[nt][f] = 0.f;

#pragma unroll
        for (int ks = 0; ks < 4; ks++) {
            uint32_t kh[8][2], kl[8][2];
#pragma unroll
            for (int p = 0; p < 4; p++) {
                const uint32_t rb = buf
                    + (uint32_t)(p * 16 + bRow8 + l7) * 144 + ks * 32 + bKhalf;
                ldsm4(kh[2*p][0], kh[2*p][1], kh[2*p+1][0], kh[2*p+1][1], rb);
                ldsm4(kl[2*p][0], kl[2*p][1], kl[2*p+1][0], kl[2*p+1][1], rb + FREG);
            }
#pragma unroll
            for (int nt = 0; nt < 8; nt++) {
                mma_bf16(c_s[nt], aQh[ks][0], aQh[ks][1], aQh[ks][2], aQh[ks][3],
                         kh[nt][0], kh[nt][1]);
                mma_bf16(c_s[nt], aQl[ks][0], aQl[ks][1], aQl[ks][2], aQl[ks][3],
                         kh[nt][0], kh[nt][1]);
                mma_bf16(c_s[nt], aQh[ks][0], aQh[ks][1], aQh[ks][2], aQh[ks][3],
                         kl[nt][0], kl[nt][1]);
            }
        }

        // ---- causal mask (diagonal tiles only) ----
        if (k0 + 64 > q0) {
#pragma unroll
            for (int nt = 0; nt < 8; nt++) {
                const int col = k0 + nt * 8 + kc * 2;
                if (col     > qrow0)     c_s[nt][0] = -FLT_MAX;
                if (col + 1 > qrow0)     c_s[nt][1] = -FLT_MAX;
                if (col     > qrow0 + 8) c_s[nt][2] = -FLT_MAX;
                if (col + 1 > qrow0 + 8) c_s[nt][3] = -FLT_MAX;
            }
        }

        // ---- online softmax ----
        float mx0 = -FLT_MAX, mx1 = -FLT_MAX;
#pragma unroll
        for (int nt = 0; nt < 8; nt++) {
            mx0 = fmaxf(mx0, fmaxf(c_s[nt][0], c_s[nt][1]));
            mx1 = fmaxf(mx1, fmaxf(c_s[nt][2], c_s[nt][3]));
        }
        mx0 = fmaxf(mx0, __shfl_xor_sync(0xffffffffu, mx0, 1));
        mx0 = fmaxf(mx0, __shfl_xor_sync(0xffffffffu, mx0, 2));
        mx1 = fmaxf(mx1, __shfl_xor_sync(0xffffffffu, mx1, 1));
        mx1 = fmaxf(mx1, __shfl_xor_sync(0xffffffffu, mx1, 2));

        const float mn0 = fmaxf(m0, mx0);
        const float mn1 = fmaxf(m1, mx1);
        const float cor0 = __expf(m0 - mn0);
        const float cor1 = __expf(m1 - mn1);
        m0 = mn0; m1 = mn1;

        float rs0 = 0.f, rs1 = 0.f;
#pragma unroll
        for (int nt = 0; nt < 8; nt++) {
            c_s[nt][0] = __expf(c_s[nt][0] - mn0);
            c_s[nt][1] = __expf(c_s[nt][1] - mn0);
            c_s[nt][2] = __expf(c_s[nt][2] - mn1);
            c_s[nt][3] = __expf(c_s[nt][3] - mn1);
            rs0 += c_s[nt][0] + c_s[nt][1];
            rs1 += c_s[nt][2] + c_s[nt][3];
        }
        rs0 += __shfl_xor_sync(0xffffffffu, rs0, 1);
        rs0 += __shfl_xor_sync(0xffffffffu, rs0, 2);
        rs1 += __shfl_xor_sync(0xffffffffu, rs1, 1);
        rs1 += __shfl_xor_sync(0xffffffffu, rs1, 2);
        l0 = l0 * cor0 + rs0;
        l1 = l1 * cor1 + rs1;

#pragma unroll
        for (int nt = 0; nt < 8; nt++) {
            c_o[nt][0] *= cor0; c_o[nt][1] *= cor0;
            c_o[nt][2] *= cor1; c_o[nt][3] *= cor1;
        }

        // ---- O += P @ V (bf16x3, register repack + ldmatrix V frags) ----
#pragma unroll
        for (int ks = 0; ks < 4; ks++) {
            const uint32_t p0 = packbf(c_s[2*ks][0],   c_s[2*ks][1]);
            const uint32_t p1 = packbf(c_s[2*ks][2],   c_s[2*ks][3]);
            const uint32_t p2 = packbf(c_s[2*ks+1][0], c_s[2*ks+1][1]);
            const uint32_t p3 = packbf(c_s[2*ks+1][2], c_s[2*ks+1][3]);
            const uint32_t q0l = packlo(c_s[2*ks][0],   c_s[2*ks][1],   p0);
            const uint32_t q1l = packlo(c_s[2*ks][2],   c_s[2*ks][3],   p1);
            const uint32_t q2l = packlo(c_s[2*ks+1][0], c_s[2*ks+1][1], p2);
            const uint32_t q3l = packlo(c_s[2*ks+1][2], c_s[2*ks+1][3], p3);
            uint32_t vh[8][2], vl[8][2];
#pragma unroll
            for (int p = 0; p < 4; p++) {
                const uint32_t rb = buf + 2 * FREG
                    + (uint32_t)(p * 16 + bRow8 + l7) * 144 + ks * 32 + bKhalf;
                ldsm4(vh[2*p][0], vh[2*p][1], vh[2*p+1][0], vh[2*p+1][1], rb);
                ldsm4(vl[2*p][0], vl[2*p][1], vl[2*p+1][0], vl[2*p+1][1], rb + FREG);
            }
#pragma unroll
            for (int nt = 0; nt < 8; nt++) {
                mma_bf16(c_o[nt], p0, p1, p2, p3, vh[nt][0], vh[nt][1]);
                mma_bf16(c_o[nt], q0l, q1l, q2l, q3l, vh[nt][0], vh[nt][1]);
                mma_bf16(c_o[nt], p0, p1, p2, p3, vl[nt][0], vl[nt][1]);
            }
        }
        __syncthreads();   // all warps done reading buf before tile ti+2 overwrites
    }

    // ---- epilogue: normalize and store bf16 {hi,lo} for O-projection ----
    const float inv0 = 1.f / l0;
    const float inv1 = 1.f / l1;
    const size_t off0 = ((size_t)(b * SS + qrow0) * NH + h) * HD;
    const size_t off1 = off0 + (size_t)8 * NH * HD;
#pragma unroll
    for (int nt = 0; nt < 8; nt++) {
        const int c = nt * 8 + kc * 2;
        const float v0 = c_o[nt][0] * inv0, v1 = c_o[nt][1] * inv0;
        const uint32_t h01 = packbf(v0, v1);
        *reinterpret_cast<uint32_t*>(g_attn_hi + off0 + c) = h01;
        *reinterpret_cast<uint32_t*>(g_attn_lo + off0 + c) = packlo(v0, v1, h01);
        const float v2 = c_o[nt][2] * inv1, v3 = c_o[nt][3] * inv1;
        const uint32_t h23 = packbf(v2, v3);
        *reinterpret_cast<uint32_t*>(g_attn_hi + off1 + c) = h23;
        *reinterpret_cast<uint32_t*>(g_attn_lo + off1 + c) = packlo(v2, v3, h23);
    }
}

// ------------------------------- launch ---------------------------------------
extern "C" void kernel_launch(void* const* d_in, const int* in_sizes, int n_in,
                              void* d_out, int out_size)
{
    const float* hidden = (const float*)d_in[0];
    const float* cosv   = (const float*)d_in[1];
    const float* sinv   = (const float*)d_in[2];
    const float* Wq     = (const float*)d_in[3];
    const float* Wk     = (const float*)d_in[4];
    const float* Wv     = (const float*)d_in[5];
    const float* Wo     = (const float*)d_in[6];
    const float* qw     = (const float*)d_in[7];
    const float* kw     = (const float*)d_in[8];
    float* out          = (float*)d_out;

    __nv_bfloat162 *phh, *phl, *pqh, *pql, *pkh, *pkl, *pvh, *pvl, *poh, *pol;
    cudaGetSymbolAddress((void**)&phh, g_hid_hi);
    cudaGetSymbolAddress((void**)&phl, g_hid_lo);
    cudaGetSymbolAddress((void**)&pqh, g_wq_hi);
    cudaGetSymbolAddress((void**)&pql, g_wq_lo);
    cudaGetSymbolAddress((void**)&pkh, g_wk_hi);
    cudaGetSymbolAddress((void**)&pkl, g_wk_lo);
    cudaGetSymbolAddress((void**)&pvh, g_wv_hi);
    cudaGetSymbolAddress((void**)&pvl, g_wv_lo);
    cudaGetSymbolAddress((void**)&poh, g_wo_hi);
    cudaGetSymbolAddress((void**)&pol, g_wo_lo);

    cudaFuncSetAttribute(gemm_qkv_bf16, cudaFuncAttributeMaxDynamicSharedMemorySize, GEMM_SMEM);
    cudaFuncSetAttribute(gemm_o_bf16,   cudaFuncAttributeMaxDynamicSharedMemorySize, GEMM_SMEM);
    cudaFuncSetAttribute(flash_mma_kernel, cudaFuncAttributeMaxDynamicSharedMemorySize, FLASH_SMEM);

    // prep: split inputs/weights to bf16 hi/lo
    {
        const int nh4 = MROWS * HIDD / 4;
        split_bf16_pass<<<(nh4 + 255) / 256, 256>>>((const float4*)hidden, phh, phl, nh4);
        const int nq4 = NH * HD * HIDD / 4;
        const int nk4 = NKV * HD * HIDD / 4;
        split_bf16_pass<<<(nq4 + 255) / 256, 256>>>((const float4*)Wq, pqh, pql, nq4);
        split_bf16_pass<<<(nk4 + 255) / 256, 256>>>((const float4*)Wk, pkh, pkl, nk4);
        split_bf16_pass<<<(nk4 + 255) / 256, 256>>>((const float4*)Wv, pvh, pvl, nk4);
        split_bf16_pass<<<(nq4 + 255) / 256, 256>>>((const float4*)Wo, poh, pol, nq4);
    }

    // Fused QKV projections (bf16x3 tensor core + ldmatrix)
    gemm_qkv_bf16<<<dim3(24, MROWS / 128), 256, GEMM_SMEM>>>();

    // RMSNorm + RoPE (q f32 in-place, k -> bf16 hi/lo flash layout)
    {
        const int warps = MROWS * NH + MROWS * NKV;
        const int threads = warps * 32;
        norm_rope_kernel<<<(threads + 255) / 256, 256>>>(cosv, sinv, qw, kw);
    }

    // V -> V^T bf16 hi/lo
    v_transpose_kernel<<<dim3(SS / 64, BB * NKV), 256>>>();

    // bf16 tensor-core causal flash attention (double-buffered + ldmatrix)
    flash_mma_kernel<<<dim3(SS / FBQ, BB * NH), 256, FLASH_SMEM>>>();

    // output projection -> d_out
    gemm_o_bf16<<<dim3(HIDD / 128, MROWS / 128), 256, GEMM_SMEM>>>(out);
}

// round 15
// speedup vs baseline: 4.2026x; 1.3272x over previous
#include <cuda_runtime.h>
#include <cuda_fp16.h>
#include <float.h>
#include <stdint.h>

// Problem constants
#define BB   2
#define SS   2048
#define HIDD 2048
#define NH   32
#define NKV  8
#define HD   64
#define MROWS (BB*SS)          // 4096
#define SCALE 0.125f           // HD^-0.5
#define EPS   1e-6f

// ---------------- scratch -----------------------------------------------------
__device__ float g_q[(size_t)MROWS * NH * HD];
__device__ float g_k[(size_t)MROWS * NKV * HD];
__device__ float g_v[(size_t)MROWS * NKV * HD];

// fp16 hi/lo splits: lo kept on the A side only (2-term scheme)
__device__ __align__(16) __half g_hid_hi[(size_t)MROWS * HIDD];
__device__ __align__(16) __half g_hid_lo[(size_t)MROWS * HIDD];
__device__ __align__(16) __half g_attn_hi[(size_t)MROWS * NH * HD];
__device__ __align__(16) __half g_attn_lo[(size_t)MROWS * NH * HD];
__device__ __align__(16) __half g_wq_hi[(size_t)NH  * HD * HIDD];
__device__ __align__(16) __half g_wk_hi[(size_t)NKV * HD * HIDD];
__device__ __align__(16) __half g_wv_hi[(size_t)NKV * HD * HIDD];
__device__ __align__(16) __half g_wo_hi[(size_t)HIDD * NH * HD];

// flash operands: K (post-rope) fp16 hi in [b][kvh][key][d]; V^T fp16 hi [b][kvh][d][key]
__device__ __align__(16) __half g_fk_hi[(size_t)BB * NKV * SS * HD];
__device__ __align__(16) __half g_vT_hi[(size_t)BB * NKV * HD * SS];

// ---------------- helpers ------------------------------------------------------
__device__ __forceinline__ uint32_t packh(float x, float y) {
    __half2 t = __floats2half2_rn(x, y);
    return *reinterpret_cast<uint32_t*>(&t);
}
__device__ __forceinline__ uint32_t packhlo(float x, float y, uint32_t hi) {
    __half2 h = *reinterpret_cast<__half2*>(&hi);
    return packh(x - __half2float(h.x), y - __half2float(h.y));
}

__device__ __forceinline__ void mma_f16(float c[4],
    uint32_t a0, uint32_t a1, uint32_t a2, uint32_t a3,
    uint32_t b0, uint32_t b1)
{
    asm volatile(
        "mma.sync.aligned.m16n8k16.row.col.f32.f16.f16.f32 "
        "{%0,%1,%2,%3}, {%4,%5,%6,%7}, {%8,%9}, {%0,%1,%2,%3};"
        : "+f"(c[0]), "+f"(c[1]), "+f"(c[2]), "+f"(c[3])
        : "r"(a0), "r"(a1), "r"(a2), "r"(a3), "r"(b0), "r"(b1));
}

__device__ __forceinline__ void cp16(uint32_t dst, const void* src) {
    asm volatile("cp.async.cg.shared.global [%0], [%1], 16;" :: "r"(dst), "l"(src));
}

__device__ __forceinline__ void ldsm4(uint32_t& r0, uint32_t& r1,
                                      uint32_t& r2, uint32_t& r3, uint32_t addr)
{
    asm volatile("ldmatrix.sync.aligned.m8n8.x4.shared.b16 {%0,%1,%2,%3}, [%4];"
                 : "=r"(r0), "=r"(r1), "=r"(r2), "=r"(r3) : "r"(addr));
}

// ---------------- prep passes ---------------------------------------------------
__global__ void split_f16_pass(const float4* __restrict__ src,
                               __half2* __restrict__ hi,
                               __half2* __restrict__ lo, int n4)
{
    const int i = blockIdx.x * blockDim.x + threadIdx.x;
    if (i >= n4) return;
    float4 v = src[i];
    __half h0 = __float2half_rn(v.x);
    __half h1 = __float2half_rn(v.y);
    __half h2 = __float2half_rn(v.z);
    __half h3 = __float2half_rn(v.w);
    hi[i * 2 + 0] = __half2(h0, h1);
    hi[i * 2 + 1] = __half2(h2, h3);
    lo[i * 2 + 0] = __half2(__float2half_rn(v.x - __half2float(h0)),
                            __float2half_rn(v.y - __half2float(h1)));
    lo[i * 2 + 1] = __half2(__float2half_rn(v.z - __half2float(h2)),
                            __float2half_rn(v.w - __half2float(h3)));
}

__global__ void hi_f16_pass(const float4* __restrict__ src,
                            __half2* __restrict__ hi, int n4)
{
    const int i = blockIdx.x * blockDim.x + threadIdx.x;
    if (i >= n4) return;
    float4 v = src[i];
    hi[i * 2 + 0] = __half2(__float2half_rn(v.x), __float2half_rn(v.y));
    hi[i * 2 + 1] = __half2(__float2half_rn(v.z), __float2half_rn(v.w));
}

// ---------------- fp16x2 cp.async GEMM with ldmatrix ----------------------------
// C = (Ahi+Alo)[M,K] @ Bhi[N,K]^T.  Block tile 128x128, TBK=16, 6-stage ring.
// Stage = 3 tiles {Ahi, Alo, Bhi} x 6144 B. 32 mma / kt / warp (2 terms).
#define TBK 16
#define NSTAGE 6
#define RSW 12
#define TILEB (128 * RSW * 4)         // 6144 bytes per tile-split
#define STB (3 * TILEB)               // 18432 bytes per stage
#define GEMM_SMEM (NSTAGE * STB)      // 110592

__device__ __forceinline__ void gemm_body_f16(
    const __half* __restrict__ Ahi, const __half* __restrict__ Alo,
    const __half* __restrict__ Bhi,
    float* __restrict__ C, int N, int K, int m0, int n0)
{
    extern __shared__ uint32_t smw[];
    const uint32_t sbase = (uint32_t)__cvta_generic_to_shared(smw);

    const int t    = threadIdx.x;
    const int lane = t & 31;
    const int warp = t >> 5;
    const int wm   = warp & 1;
    const int wn   = warp >> 1;
    const int grp  = lane >> 2;
    const int kc   = lane & 3;

    const int lrow = t >> 1;
    const int lhalf = t & 1;
    const size_t gA = (size_t)(m0 + lrow) * K + lhalf * 8;
    const size_t gB = (size_t)(n0 + lrow) * K + lhalf * 8;
    const uint32_t dOff = lrow * 48 + lhalf * 16;

    // ldmatrix per-thread offsets
    const int l15 = lane & 15;
    const int l7  = lane & 7;
    const uint32_t aKhalf = (lane >> 4) * 16;
    const uint32_t bKhalf = ((lane >> 3) & 1) * 16;
    const int bRow8  = (lane >> 4) * 8;

    float acc[4][4][4];
#pragma unroll
    for (int i = 0; i < 4; i++)
#pragma unroll
        for (int j = 0; j < 4; j++)
#pragma unroll
            for (int f = 0; f < 4; f++) acc[i][j][f] = 0.f;

    const int NT = K / TBK;

#pragma unroll
    for (int s = 0; s < NSTAGE - 1; s++) {
        const int koff = s * TBK;
        const uint32_t sb = sbase + s * STB;
        cp16(sb + dOff,             Ahi + gA + koff);
        cp16(sb + TILEB + dOff,     Alo + gA + koff);
        cp16(sb + 2 * TILEB + dOff, Bhi + gB + koff);
        asm volatile("cp.async.commit_group;" ::: "memory");
    }

#pragma unroll 2
    for (int kt = 0; kt < NT; kt++) {
        asm volatile("cp.async.wait_group %0;" :: "n"(NSTAGE - 2) : "memory");
        __syncthreads();

        const int kn = kt + NSTAGE - 1;
        if (kn < NT) {
            const int s = kn % NSTAGE;
            const int koff = kn * TBK;
            const uint32_t sb = sbase + s * STB;
            cp16(sb + dOff,             Ahi + gA + koff);
            cp16(sb + TILEB + dOff,     Alo + gA + koff);
            cp16(sb + 2 * TILEB + dOff, Bhi + gB + koff);
        }
        asm volatile("cp.async.commit_group;" ::: "memory");

        const uint32_t stb = sbase + (kt % NSTAGE) * STB;

        uint32_t ah[4][4], al[4][4];
#pragma unroll
        for (int mt = 0; mt < 4; mt++) {
            const uint32_t ra = stb + (uint32_t)(wm * 64 + mt * 16 + l15) * 48 + aKhalf;
            ldsm4(ah[mt][0], ah[mt][1], ah[mt][2], ah[mt][3], ra);
            ldsm4(al[mt][0], al[mt][1], al[mt][2], al[mt][3], ra + TILEB);
        }
        uint32_t bh[4][2];
#pragma unroll
        for (int p = 0; p < 2; p++) {
            const uint32_t rb = stb + 2 * TILEB
                + (uint32_t)(wn * 32 + p * 16 + bRow8 + l7) * 48 + bKhalf;
            ldsm4(bh[2*p][0], bh[2*p][1], bh[2*p+1][0], bh[2*p+1][1], rb);
        }

#pragma unroll
        for (int mt = 0; mt < 4; mt++) {
#pragma unroll
            for (int nt = 0; nt < 4; nt++) {
                mma_f16(acc[mt][nt], ah[mt][0], ah[mt][1], ah[mt][2], ah[mt][3],
                        bh[nt][0], bh[nt][1]);
                mma_f16(acc[mt][nt], al[mt][0], al[mt][1], al[mt][2], al[mt][3],
                        bh[nt][0], bh[nt][1]);
            }
        }
    }

#pragma unroll
    for (int mt = 0; mt < 4; mt++) {
        const int row = m0 + wm * 64 + mt * 16 + grp;
#pragma unroll
        for (int nt = 0; nt < 4; nt++) {
            const int col = n0 + wn * 32 + nt * 8 + kc * 2;
            *reinterpret_cast<float2*>(C + (size_t)row * N + col) =
                make_float2(acc[mt][nt][0], acc[mt][nt][1]);
            *reinterpret_cast<float2*>(C + (size_t)(row + 8) * N + col) =
                make_float2(acc[mt][nt][2], acc[mt][nt][3]);
        }
    }
}

__global__ __launch_bounds__(256, 2) void gemm_qkv_f16()
{
    const int bx = blockIdx.x;
    const int m0 = blockIdx.y * 128;
    const __half* Bh; float* C; int N, n0;
    if (bx < 16)      { Bh = g_wq_hi; C = g_q; N = NH  * HD; n0 = bx * 128; }
    else if (bx < 20) { Bh = g_wk_hi; C = g_k; N = NKV * HD; n0 = (bx - 16) * 128; }
    else              { Bh = g_wv_hi; C = g_v; N = NKV * HD; n0 = (bx - 20) * 128; }
    gemm_body_f16(g_hid_hi, g_hid_lo, Bh, C, N, HIDD, m0, n0);
}

__global__ __launch_bounds__(256, 2) void gemm_o_f16(float* __restrict__ out)
{
    gemm_body_f16(g_attn_hi, g_attn_lo, g_wo_hi,
                  out, HIDD, NH * HD, blockIdx.y * 128, blockIdx.x * 128);
}

// ---------------- RMSNorm + RoPE: q in-place f32; k -> fp16 hi ------------------
__global__ void norm_rope_kernel(
    const float* __restrict__ cosv, const float* __restrict__ sinv,
    const float* __restrict__ qw,   const float* __restrict__ kw)
{
    const int gid  = blockIdx.x * blockDim.x + threadIdx.x;
    const int wid  = gid >> 5;
    const int lane = gid & 31;
    const int nqr  = MROWS * NH;
    const int ntot = nqr + MROWS * NKV;
    if (wid >= ntot) return;

    const bool isq = (wid < nqr);
    float* base;
    int bs, kvh = 0;
    const float* w;
    if (isq) { base = g_q + (size_t)wid * HD;  bs = wid / NH; w = qw; }
    else {
        int r = wid - nqr;
        base = g_k + (size_t)r * HD;
        bs = r / NKV; kvh = r % NKV; w = kw;
    }

    float x0 = base[lane];
    float x1 = base[lane + 32];
    float ss = x0 * x0 + x1 * x1;
#pragma unroll
    for (int o = 16; o > 0; o >>= 1) ss += __shfl_xor_sync(0xffffffffu, ss, o);
    const float rinv = rsqrtf(ss * (1.0f / HD) + EPS);

    const float n0 = w[lane]      * (x0 * rinv);
    const float n1 = w[lane + 32] * (x1 * rinv);

    const float c0 = cosv[(size_t)bs * HD + lane];
    const float c1 = cosv[(size_t)bs * HD + lane + 32];
    const float s0 = sinv[(size_t)bs * HD + lane];
    const float s1 = sinv[(size_t)bs * HD + lane + 32];

    const float o0 = n0 * c0 - n1 * s0;
    const float o1 = n1 * c1 + n0 * s1;

    if (isq) {
        base[lane]      = o0;
        base[lane + 32] = o1;
    } else {
        const int b_  = bs >> 11;
        const int key = bs & (SS - 1);
        const size_t o = (((size_t)b_ * NKV + kvh) * SS + key) * HD;
        g_fk_hi[o + lane]      = __float2half_rn(o0);
        g_fk_hi[o + lane + 32] = __float2half_rn(o1);
    }
}

// ---------------- V transpose: f32 [b][key][kvh][d] -> fp16 [b][kvh][d][key] ----
__global__ void v_transpose_kernel()
{
    __shared__ float ts[64][68];
    const int bk = blockIdx.y;
    const int k0 = blockIdx.x * 64;
    const int b  = bk / NKV, kvh = bk % NKV;
    const int t  = threadIdx.x;

#pragma unroll
    for (int i = 0; i < 4; i++) {
        const int idx = t + i * 256;
        const int row = idx >> 4;
        const int c4  = (idx & 15) * 4;
        *reinterpret_cast<float4*>(&ts[row][c4]) =
            *reinterpret_cast<const float4*>(
                g_v + ((size_t)(b * SS + k0 + row) * NKV + kvh) * HD + c4);
    }
    __syncthreads();

    const int d  = t >> 2;
    const int kb = (t & 3) * 16;
    const size_t off = ((size_t)bk * HD + d) * SS + k0 + kb;
    uint32_t hi[8];
#pragma unroll
    for (int j = 0; j < 8; j++)
        hi[j] = packh(ts[kb + 2 * j][d], ts[kb + 2 * j + 1][d]);
    reinterpret_cast<uint4*>(g_vT_hi + off)[0] = make_uint4(hi[0], hi[1], hi[2], hi[3]);
    reinterpret_cast<uint4*>(g_vT_hi + off)[1] = make_uint4(hi[4], hi[5], hi[6], hi[7]);
}

// ---------------- fp16 tensor-core causal flash attention -----------------------
// S = (Qh+Ql)·Kh^T ; P = exp(S-m) split hi/lo in regs; O += (Ph+Pl)·Vh.
// Tile buffer = {Kh, Vh} (18432 B), double-buffered; ldmatrix fragment loads.
#define FBQ 128
#define FKW 36
#define FREG (64 * FKW * 4)              // 9216 B per tile-split
#define FBUF (2 * FREG)                  // 18432 B per buffer
#define FLASH_SMEM (2 * FBUF)            // 36864 B

__global__ __launch_bounds__(256, 2) void flash_mma_kernel()
{
    const int bh  = blockIdx.y;
    const int b   = bh / NH;
    const int h   = bh % NH;
    const int kvh = h / (NH / NKV);
    const int q0  = blockIdx.x * FBQ;
    const int tid = threadIdx.x;
    const int lane = tid & 31;
    const int w    = tid >> 5;
    const int grp  = lane >> 2;
    const int kc   = lane & 3;

    extern __shared__ uint32_t fsm[];
    const uint32_t sb = (uint32_t)__cvta_generic_to_shared(fsm);

    const size_t kvb = (size_t)b * NKV + kvh;
    const __half* gKh = g_fk_hi + kvb * SS * HD;
    const __half* gVh = g_vT_hi + kvb * HD * SS;

    const int l7  = lane & 7;
    const uint32_t bKhalf = ((lane >> 3) & 1) * 16;
    const int bRow8  = (lane >> 4) * 8;

    // Q fragments (fp16 hi/lo, pre-scaled)
    const int qrow0 = q0 + w * 16 + grp;
    const float* Q0 = g_q + ((size_t)(b * SS + qrow0) * NH + h) * HD;
    const float* Q1 = Q0 + (size_t)8 * NH * HD;
    uint32_t aQh[4][4], aQl[4][4];
#pragma unroll
    for (int ks = 0; ks < 4; ks++) {
#pragma unroll
        for (int p = 0; p < 4; p++) {
            const float* Qr = (p & 1) ? Q1 : Q0;
            const int d = ks * 16 + ((p >> 1) ? 8 : 0) + kc * 2;
            float2 v = *reinterpret_cast<const float2*>(Qr + d);
            v.x *= SCALE; v.y *= SCALE;
            aQh[ks][p] = packh(v.x, v.y);
            aQl[ks][p] = packhlo(v.x, v.y, aQh[ks][p]);
        }
    }

    float c_o[8][4];
#pragma unroll
    for (int nt = 0; nt < 8; nt++)
#pragma unroll
        for (int f = 0; f < 4; f++) c_o[nt][f] = 0.f;

    float m0 = -FLT_MAX, m1 = -FLT_MAX, l0 = 0.f, l1 = 0.f;

    const int NT = (q0 + FBQ) / 64;

    // prefetch tile 0 -> buf 0 (2 regions x 512 chunks, 2/thread each)
    {
#pragma unroll
        for (int r = 0; r < 2; r++) {
            const int idx = tid + r * 256;
            const int row = idx >> 3;
            const int ch  = idx & 7;
            const uint32_t doff = row * 144 + ch * 16;
            cp16(sb + doff,        gKh + (size_t)row * HD + ch * 8);
            cp16(sb + FREG + doff, gVh + (size_t)row * SS + ch * 8);
        }
        asm volatile("cp.async.commit_group;" ::: "memory");
    }

    for (int ti = 0; ti < NT; ti++) {
        const int k0 = ti * 64;
        if (ti + 1 < NT) {
            const int kn = k0 + 64;
            const uint32_t bo = sb + ((ti + 1) & 1) * FBUF;
#pragma unroll
            for (int r = 0; r < 2; r++) {
                const int idx = tid + r * 256;
                const int row = idx >> 3;
                const int ch  = idx & 7;
                const uint32_t doff = row * 144 + ch * 16;
                cp16(bo + doff,        gKh + (size_t)(kn + row) * HD + ch * 8);
                cp16(bo + FREG + doff, gVh + (size_t)row * SS + kn + ch * 8);
            }
            asm volatile("cp.async.commit_group;" ::: "memory");
            asm volatile("cp.async.wait_group 1;" ::: "memory");
        } else {
            asm volatile("cp.async.wait_group 0;" ::: "memory");
        }
        __syncthreads();

        const uint32_t buf = sb + (ti & 1) * FBUF;

        // ---- S = Q @ K^T (fp16x2) ----
        float c_s[8][4];
#pragma unroll
        for (int nt = 0; nt < 8; nt++)
#pragma unroll
            for (int f = 0; f < 4; f++) c_s[nt][f] = 0.f;

#pragma unroll
        for (int ks = 0; ks < 4; ks++) {
            uint32_t kh[8][2];
#pragma unroll
            for (int p = 0; p < 4; p++) {
                const uint32_t rb = buf
                    + (uint32_t)(p * 16 + bRow8 + l7) * 144 + ks * 32 + bKhalf;
                ldsm4(kh[2*p][0], kh[2*p][1], kh[2*p+1][0], kh[2*p+1][1], rb);
            }
#pragma unroll
            for (int nt = 0; nt < 8; nt++) {
                mma_f16(c_s[nt], aQh[ks][0], aQh[ks][1], aQh[ks][2], aQh[ks][3],
                        kh[nt][0], kh[nt][1]);
                mma_f16(c_s[nt], aQl[ks][0], aQl[ks][1], aQl[ks][2], aQl[ks][3],
                        kh[nt][0], kh[nt][1]);
            }
        }

        // ---- causal mask (diagonal tiles only) ----
        if (k0 + 64 > q0) {
#pragma unroll
            for (int nt = 0; nt < 8; nt++) {
                const int col = k0 + nt * 8 + kc * 2;
                if (col     > qrow0)     c_s[nt][0] = -FLT_MAX;
                if (col + 1 > qrow0)     c_s[nt][1] = -FLT_MAX;
                if (col     > qrow0 + 8) c_s[nt][2] = -FLT_MAX;
                if (col + 1 > qrow0 + 8) c_s[nt][3] = -FLT_MAX;
            }
        }

        // ---- online softmax ----
        float mx0 = -FLT_MAX, mx1 = -FLT_MAX;
#pragma unroll
        for (int nt = 0; nt < 8; nt++) {
            mx0 = fmaxf(mx0, fmaxf(c_s[nt][0], c_s[nt][1]));
            mx1 = fmaxf(mx1, fmaxf(c_s[nt][2], c_s[nt][3]));
        }
        mx0 = fmaxf(mx0, __shfl_xor_sync(0xffffffffu, mx0, 1));
        mx0 = fmaxf(mx0, __shfl_xor_sync(0xffffffffu, mx0, 2));
        mx1 = fmaxf(mx1, __shfl_xor_sync(0xffffffffu, mx1, 1));
        mx1 = fmaxf(mx1, __shfl_xor_sync(0xffffffffu, mx1, 2));

        const float mn0 = fmaxf(m0, mx0);
        const float mn1 = fmaxf(m1, mx1);
        const float cor0 = __expf(m0 - mn0);
        const float cor1 = __expf(m1 - mn1);
        m0 = mn0; m1 = mn1;

        float rs0 = 0.f, rs1 = 0.f;
#pragma unroll
        for (int nt = 0; nt < 8; nt++) {
            c_s[nt][0] = __expf(c_s[nt][0] - mn0);
            c_s[nt][1] = __expf(c_s[nt][1] - mn0);
            c_s[nt][2] = __expf(c_s[nt][2] - mn1);
            c_s[nt][3] = __expf(c_s[nt][3] - mn1);
            rs0 += c_s[nt][0] + c_s[nt][1];
            rs1 += c_s[nt][2] + c_s[nt][3];
        }
        rs0 += __shfl_xor_sync(0xffffffffu, rs0, 1);
        rs0 += __shfl_xor_sync(0xffffffffu, rs0, 2);
        rs1 += __shfl_xor_sync(0xffffffffu, rs1, 1);
        rs1 += __shfl_xor_sync(0xffffffffu, rs1, 2);
        l0 = l0 * cor0 + rs0;
        l1 = l1 * cor1 + rs1;

#pragma unroll
        for (int nt = 0; nt < 8; nt++) {
            c_o[nt][0] *= cor0; c_o[nt][1] *= cor0;
            c_o[nt][2] *= cor1; c_o[nt][3] *= cor1;
        }

        // ---- O += P @ V (fp16x2, register repack) ----
#pragma unroll
        for (int ks = 0; ks < 4; ks++) {
            const uint32_t p0 = packh(c_s[2*ks][0],   c_s[2*ks][1]);
            const uint32_t p1 = packh(c_s[2*ks][2],   c_s[2*ks][3]);
            const uint32_t p2 = packh(c_s[2*ks+1][0], c_s[2*ks+1][1]);
            const uint32_t p3 = packh(c_s[2*ks+1][2], c_s[2*ks+1][3]);
            const uint32_t q0l = packhlo(c_s[2*ks][0],   c_s[2*ks][1],   p0);
            const uint32_t q1l = packhlo(c_s[2*ks][2],   c_s[2*ks][3],   p1);
            const uint32_t q2l = packhlo(c_s[2*ks+1][0], c_s[2*ks+1][1], p2);
            const uint32_t q3l = packhlo(c_s[2*ks+1][2], c_s[2*ks+1][3], p3);
            uint32_t vh[8][2];
#pragma unroll
            for (int p = 0; p < 4; p++) {
                const uint32_t rb = buf + FREG
                    + (uint32_t)(p * 16 + bRow8 + l7) * 144 + ks * 32 + bKhalf;
                ldsm4(vh[2*p][0], vh[2*p][1], vh[2*p+1][0], vh[2*p+1][1], rb);
            }
#pragma unroll
            for (int nt = 0; nt < 8; nt++) {
                mma_f16(c_o[nt], p0, p1, p2, p3, vh[nt][0], vh[nt][1]);
                mma_f16(c_o[nt], q0l, q1l, q2l, q3l, vh[nt][0], vh[nt][1]);
            }
        }
        __syncthreads();
    }

    // ---- epilogue: normalize and store fp16 {hi,lo} for O-projection ----
    const float inv0 = 1.f / l0;
    const float inv1 = 1.f / l1;
    const size_t off0 = ((size_t)(b * SS + qrow0) * NH + h) * HD;
    const size_t off1 = off0 + (size_t)8 * NH * HD;
#pragma unroll
    for (int nt = 0; nt < 8; nt++) {
        const int c = nt * 8 + kc * 2;
        const float v0 = c_o[nt][0] * inv0, v1 = c_o[nt][1] * inv0;
        const uint32_t h01 = packh(v0, v1);
        *reinterpret_cast<uint32_t*>(g_attn_hi + off0 + c) = h01;
        *reinterpret_cast<uint32_t*>(g_attn_lo + off0 + c) = packhlo(v0, v1, h01);
        const float v2 = c_o[nt][2] * inv1, v3 = c_o[nt][3] * inv1;
        const uint32_t h23 = packh(v2, v3);
        *reinterpret_cast<uint32_t*>(g_attn_hi + off1 + c) = h23;
        *reinterpret_cast<uint32_t*>(g_attn_lo + off1 + c) = packhlo(v2, v3, h23);
    }
}

// ------------------------------- launch ---------------------------------------
extern "C" void kernel_launch(void* const* d_in, const int* in_sizes, int n_in,
                              void* d_out, int out_size)
{
    const float* hidden = (const float*)d_in[0];
    const float* cosv   = (const float*)d_in[1];
    const float* sinv   = (const float*)d_in[2];
    const float* Wq     = (const float*)d_in[3];
    const float* Wk     = (const float*)d_in[4];
    const float* Wv     = (const float*)d_in[5];
    const float* Wo     = (const float*)d_in[6];
    const float* qw     = (const float*)d_in[7];
    const float* kw     = (const float*)d_in[8];
    float* out          = (float*)d_out;

    __half2 *phh, *phl, *pqh, *pkh, *pvh, *poh;
    cudaGetSymbolAddress((void**)&phh, g_hid_hi);
    cudaGetSymbolAddress((void**)&phl, g_hid_lo);
    cudaGetSymbolAddress((void**)&pqh, g_wq_hi);
    cudaGetSymbolAddress((void**)&pkh, g_wk_hi);
    cudaGetSymbolAddress((void**)&pvh, g_wv_hi);
    cudaGetSymbolAddress((void**)&poh, g_wo_hi);

    cudaFuncSetAttribute(gemm_qkv_f16, cudaFuncAttributeMaxDynamicSharedMemorySize, GEMM_SMEM);
    cudaFuncSetAttribute(gemm_o_f16,   cudaFuncAttributeMaxDynamicSharedMemorySize, GEMM_SMEM);
    cudaFuncSetAttribute(flash_mma_kernel, cudaFuncAttributeMaxDynamicSharedMemorySize, FLASH_SMEM);

    // prep: hidden -> fp16 hi/lo; weights -> fp16 hi only
    {
        const int nh4 = MROWS * HIDD / 4;
        split_f16_pass<<<(nh4 + 255) / 256, 256>>>((const float4*)hidden, phh, phl, nh4);
        const int nq4 = NH * HD * HIDD / 4;
        const int nk4 = NKV * HD * HIDD / 4;
        hi_f16_pass<<<(nq4 + 255) / 256, 256>>>((const float4*)Wq, pqh, nq4);
        hi_f16_pass<<<(nk4 + 255) / 256, 256>>>((const float4*)Wk, pkh, nk4);
        hi_f16_pass<<<(nk4 + 255) / 256, 256>>>((const float4*)Wv, pvh, nk4);
        hi_f16_pass<<<(nq4 + 255) / 256, 256>>>((const float4*)Wo, poh, nq4);
    }

    // Fused QKV projections (fp16x2 tensor core + ldmatrix)
    gemm_qkv_f16<<<dim3(24, MROWS / 128), 256, GEMM_SMEM>>>();

    // RMSNorm + RoPE (q f32 in-place, k -> fp16 flash layout)
    {
        const int warps = MROWS * NH + MROWS * NKV;
        const int threads = warps * 32;
        norm_rope_kernel<<<(threads + 255) / 256, 256>>>(cosv, sinv, qw, kw);
    }

    // V -> V^T fp16
    v_transpose_kernel<<<dim3(SS / 64, BB * NKV), 256>>>();

    // fp16 tensor-core causal flash attention (double-buffered + ldmatrix)
    flash_mma_kernel<<<dim3(SS / FBQ, BB * NH), 256, FLASH_SMEM>>>();

    // output projection -> d_out
    gemm_o_f16<<<dim3(HIDD / 128, MROWS / 128), 256, GEMM_SMEM>>>(out);
}

// round 16
// speedup vs baseline: 4.5259x; 1.0769x over previous
#include <cuda_runtime.h>
#include <cuda_fp16.h>
#include <float.h>
#include <stdint.h>

// Problem constants
#define BB   2
#define SS   2048
#define HIDD 2048
#define NH   32
#define NKV  8
#define HD   64
#define MROWS (BB*SS)          // 4096
#define SCALE 0.125f           // HD^-0.5
#define EPS   1e-6f

// ---------------- scratch -----------------------------------------------------
__device__ float g_q[(size_t)MROWS * NH * HD];
__device__ float g_k[(size_t)MROWS * NKV * HD];
__device__ float g_v[(size_t)MROWS * NKV * HD];

// fp16 hi/lo splits: lo kept on the A side only (2-term scheme)
__device__ __align__(16) __half g_hid_hi[(size_t)MROWS * HIDD];
__device__ __align__(16) __half g_hid_lo[(size_t)MROWS * HIDD];
__device__ __align__(16) __half g_attn_hi[(size_t)MROWS * NH * HD];
__device__ __align__(16) __half g_attn_lo[(size_t)MROWS * NH * HD];
__device__ __align__(16) __half g_wq_hi[(size_t)NH  * HD * HIDD];
__device__ __align__(16) __half g_wk_hi[(size_t)NKV * HD * HIDD];
__device__ __align__(16) __half g_wv_hi[(size_t)NKV * HD * HIDD];
__device__ __align__(16) __half g_wo_hi[(size_t)HIDD * NH * HD];

// flash operands: K (post-rope) fp16 hi in [b][kvh][key][d]; V^T fp16 hi [b][kvh][d][key]
__device__ __align__(16) __half g_fk_hi[(size_t)BB * NKV * SS * HD];
__device__ __align__(16) __half g_vT_hi[(size_t)BB * NKV * HD * SS];

// ---------------- helpers ------------------------------------------------------
__device__ __forceinline__ uint32_t packh(float x, float y) {
    __half2 t = __floats2half2_rn(x, y);
    return *reinterpret_cast<uint32_t*>(&t);
}
__device__ __forceinline__ uint32_t packhlo(float x, float y, uint32_t hi) {
    __half2 h = *reinterpret_cast<__half2*>(&hi);
    return packh(x - __half2float(h.x), y - __half2float(h.y));
}

__device__ __forceinline__ void mma_f16(float c[4],
    uint32_t a0, uint32_t a1, uint32_t a2, uint32_t a3,
    uint32_t b0, uint32_t b1)
{
    asm volatile(
        "mma.sync.aligned.m16n8k16.row.col.f32.f16.f16.f32 "
        "{%0,%1,%2,%3}, {%4,%5,%6,%7}, {%8,%9}, {%0,%1,%2,%3};"
        : "+f"(c[0]), "+f"(c[1]), "+f"(c[2]), "+f"(c[3])
        : "r"(a0), "r"(a1), "r"(a2), "r"(a3), "r"(b0), "r"(b1));
}

__device__ __forceinline__ void cp16(uint32_t dst, const void* src) {
    asm volatile("cp.async.cg.shared.global [%0], [%1], 16;" :: "r"(dst), "l"(src));
}

__device__ __forceinline__ void ldsm4(uint32_t& r0, uint32_t& r1,
                                      uint32_t& r2, uint32_t& r3, uint32_t addr)
{
    asm volatile("ldmatrix.sync.aligned.m8n8.x4.shared.b16 {%0,%1,%2,%3}, [%4];"
                 : "=r"(r0), "=r"(r1), "=r"(r2), "=r"(r3) : "r"(addr));
}

// ---------------- fused prep: hidden -> hi/lo; 4 weights -> hi ------------------
__device__ __forceinline__ void f4_to_hi(const float4 v, __half2* hi, int i) {
    hi[i * 2 + 0] = __half2(__float2half_rn(v.x), __float2half_rn(v.y));
    hi[i * 2 + 1] = __half2(__float2half_rn(v.z), __float2half_rn(v.w));
}

#define NH4_ (MROWS * HIDD / 4)
#define NQ4_ (NH  * HD * HIDD / 4)
#define NK4_ (NKV * HD * HIDD / 4)
#define PREP_TOT (NH4_ + 2 * NQ4_ + 2 * NK4_)

__global__ void prep_all(const float4* __restrict__ hidden,
                         const float4* __restrict__ Wq, const float4* __restrict__ Wk,
                         const float4* __restrict__ Wv, const float4* __restrict__ Wo)
{
    int i = blockIdx.x * blockDim.x + threadIdx.x;
    if (i >= PREP_TOT) return;
    if (i < NH4_) {
        float4 v = hidden[i];
        __half2* hi = reinterpret_cast<__half2*>(g_hid_hi);
        __half2* lo = reinterpret_cast<__half2*>(g_hid_lo);
        __half h0 = __float2half_rn(v.x), h1 = __float2half_rn(v.y);
        __half h2 = __float2half_rn(v.z), h3 = __float2half_rn(v.w);
        hi[i * 2 + 0] = __half2(h0, h1);
        hi[i * 2 + 1] = __half2(h2, h3);
        lo[i * 2 + 0] = __half2(__float2half_rn(v.x - __half2float(h0)),
                                __float2half_rn(v.y - __half2float(h1)));
        lo[i * 2 + 1] = __half2(__float2half_rn(v.z - __half2float(h2)),
                                __float2half_rn(v.w - __half2float(h3)));
        return;
    }
    i -= NH4_;
    if (i < NQ4_) { f4_to_hi(Wq[i], reinterpret_cast<__half2*>(g_wq_hi), i); return; }
    i -= NQ4_;
    if (i < NK4_) { f4_to_hi(Wk[i], reinterpret_cast<__half2*>(g_wk_hi), i); return; }
    i -= NK4_;
    if (i < NK4_) { f4_to_hi(Wv[i], reinterpret_cast<__half2*>(g_wv_hi), i); return; }
    i -= NK4_;
    f4_to_hi(Wo[i], reinterpret_cast<__half2*>(g_wo_hi), i);
}

// ---------------- fp16x2 cp.async GEMM with ldmatrix ----------------------------
// C = (Ahi+Alo)[M,K] @ Bhi[N,K]^T.  Block tile 128x128.
// TBK=32 per stage (2 k16 halves), NSTAGE=3: ONE barrier bundle per 32 k-elems
// (was per 16) -- halves pipeline overhead; SMEM 90 KB (2 CTAs/SM).
// Row stride 80 B: ldmatrix phases hit banks 20r mod 32 (all distinct) and
// cp.async stores 20r+4c cover all 32 banks -- conflict-free both ways.
#define TBK 32
#define NSTAGE 3
#define RSB 80                         // bytes per SMEM row (64 data + 16 pad)
#define TILEB (128 * RSB)              // 10240 bytes per tile-split
#define STB (3 * TILEB)                // 30720 bytes per stage {Ahi, Alo, Bhi}
#define GEMM_SMEM (NSTAGE * STB)       // 92160

__device__ __forceinline__ void gemm_body_f16(
    const __half* __restrict__ Ahi, const __half* __restrict__ Alo,
    const __half* __restrict__ Bhi,
    float* __restrict__ C, int N, int K, int m0, int n0)
{
    extern __shared__ uint32_t smw[];
    const uint32_t sbase = (uint32_t)__cvta_generic_to_shared(smw);

    const int t    = threadIdx.x;
    const int lane = t & 31;
    const int warp = t >> 5;
    const int wm   = warp & 1;
    const int wn   = warp >> 1;
    const int grp  = lane >> 2;
    const int kc   = lane & 3;

    // loader: 2 chunks per tile-split per thread (idx 0..511: row=idx>>2, ch=idx&3)
    const int r0i = t, r1i = t + 256;
    const int row0 = r0i >> 2, ch0 = r0i & 3;
    const int row1 = r1i >> 2, ch1 = r1i & 3;
    const size_t gA0 = (size_t)(m0 + row0) * K + ch0 * 8;
    const size_t gA1 = (size_t)(m0 + row1) * K + ch1 * 8;
    const size_t gB0 = (size_t)(n0 + row0) * K + ch0 * 8;
    const size_t gB1 = (size_t)(n0 + row1) * K + ch1 * 8;
    const uint32_t d0 = row0 * RSB + ch0 * 16;
    const uint32_t d1 = row1 * RSB + ch1 * 16;

    // ldmatrix per-thread offsets
    const int l15 = lane & 15;
    const int l7  = lane & 7;
    const uint32_t aKhalf = (lane >> 4) * 16;
    const uint32_t bKhalf = ((lane >> 3) & 1) * 16;
    const int bRow8  = (lane >> 4) * 8;

    float acc[4][4][4];
#pragma unroll
    for (int i = 0; i < 4; i++)
#pragma unroll
        for (int j = 0; j < 4; j++)
#pragma unroll
            for (int f = 0; f < 4; f++) acc[i][j][f] = 0.f;

    const int NT = K / TBK;

#pragma unroll
    for (int s = 0; s < NSTAGE - 1; s++) {
        const int koff = s * TBK;
        const uint32_t sb = sbase + s * STB;
        cp16(sb + d0,             Ahi + gA0 + koff);
        cp16(sb + d1,             Ahi + gA1 + koff);
        cp16(sb + TILEB + d0,     Alo + gA0 + koff);
        cp16(sb + TILEB + d1,     Alo + gA1 + koff);
        cp16(sb + 2 * TILEB + d0, Bhi + gB0 + koff);
        cp16(sb + 2 * TILEB + d1, Bhi + gB1 + koff);
        asm volatile("cp.async.commit_group;" ::: "memory");
    }

#pragma unroll 2
    for (int kt = 0; kt < NT; kt++) {
        asm volatile("cp.async.wait_group %0;" :: "n"(NSTAGE - 2) : "memory");
        __syncthreads();

        const int kn = kt + NSTAGE - 1;
        if (kn < NT) {
            const int s = kn % NSTAGE;
            const int koff = kn * TBK;
            const uint32_t sb = sbase + s * STB;
            cp16(sb + d0,             Ahi + gA0 + koff);
            cp16(sb + d1,             Ahi + gA1 + koff);
            cp16(sb + TILEB + d0,     Alo + gA0 + koff);
            cp16(sb + TILEB + d1,     Alo + gA1 + koff);
            cp16(sb + 2 * TILEB + d0, Bhi + gB0 + koff);
            cp16(sb + 2 * TILEB + d1, Bhi + gB1 + koff);
        }
        asm volatile("cp.async.commit_group;" ::: "memory");

        const uint32_t stb = sbase + (kt % NSTAGE) * STB;

#pragma unroll
        for (int ks = 0; ks < 2; ks++) {
            uint32_t ah[4][4], al[4][4];
#pragma unroll
            for (int mt = 0; mt < 4; mt++) {
                const uint32_t ra = stb + (uint32_t)(wm * 64 + mt * 16 + l15) * RSB
                                    + ks * 32 + aKhalf;
                ldsm4(ah[mt][0], ah[mt][1], ah[mt][2], ah[mt][3], ra);
                ldsm4(al[mt][0], al[mt][1], al[mt][2], al[mt][3], ra + TILEB);
            }
            uint32_t bh[4][2];
#pragma unroll
            for (int p = 0; p < 2; p++) {
                const uint32_t rb = stb + 2 * TILEB
                    + (uint32_t)(wn * 32 + p * 16 + bRow8 + l7) * RSB + ks * 32 + bKhalf;
                ldsm4(bh[2*p][0], bh[2*p][1], bh[2*p+1][0], bh[2*p+1][1], rb);
            }

#pragma unroll
            for (int mt = 0; mt < 4; mt++) {
#pragma unroll
                for (int nt = 0; nt < 4; nt++) {
                    mma_f16(acc[mt][nt], ah[mt][0], ah[mt][1], ah[mt][2], ah[mt][3],
                            bh[nt][0], bh[nt][1]);
                    mma_f16(acc[mt][nt], al[mt][0], al[mt][1], al[mt][2], al[mt][3],
                            bh[nt][0], bh[nt][1]);
                }
            }
        }
    }

#pragma unroll
    for (int mt = 0; mt < 4; mt++) {
        const int row = m0 + wm * 64 + mt * 16 + grp;
#pragma unroll
        for (int nt = 0; nt < 4; nt++) {
            const int col = n0 + wn * 32 + nt * 8 + kc * 2;
            *reinterpret_cast<float2*>(C + (size_t)row * N + col) =
                make_float2(acc[mt][nt][0], acc[mt][nt][1]);
            *reinterpret_cast<float2*>(C + (size_t)(row + 8) * N + col) =
                make_float2(acc[mt][nt][2], acc[mt][nt][3]);
        }
    }
}

__global__ __launch_bounds__(256, 2) void gemm_qkv_f16()
{
    const int bx = blockIdx.x;
    const int m0 = blockIdx.y * 128;
    const __half* Bh; float* C; int N, n0;
    if (bx < 16)      { Bh = g_wq_hi; C = g_q; N = NH  * HD; n0 = bx * 128; }
    else if (bx < 20) { Bh = g_wk_hi; C = g_k; N = NKV * HD; n0 = (bx - 16) * 128; }
    else              { Bh = g_wv_hi; C = g_v; N = NKV * HD; n0 = (bx - 20) * 128; }
    gemm_body_f16(g_hid_hi, g_hid_lo, Bh, C, N, HIDD, m0, n0);
}

__global__ __launch_bounds__(256, 2) void gemm_o_f16(float* __restrict__ out)
{
    gemm_body_f16(g_attn_hi, g_attn_lo, g_wo_hi,
                  out, HIDD, NH * HD, blockIdx.y * 128, blockIdx.x * 128);
}

// ---------------- RMSNorm + RoPE: q in-place f32; k -> fp16 hi ------------------
__global__ void norm_rope_kernel(
    const float* __restrict__ cosv, const float* __restrict__ sinv,
    const float* __restrict__ qw,   const float* __restrict__ kw)
{
    const int gid  = blockIdx.x * blockDim.x + threadIdx.x;
    const int wid  = gid >> 5;
    const int lane = gid & 31;
    const int nqr  = MROWS * NH;
    const int ntot = nqr + MROWS * NKV;
    if (wid >= ntot) return;

    const bool isq = (wid < nqr);
    float* base;
    int bs, kvh = 0;
    const float* w;
    if (isq) { base = g_q + (size_t)wid * HD;  bs = wid / NH; w = qw; }
    else {
        int r = wid - nqr;
        base = g_k + (size_t)r * HD;
        bs = r / NKV; kvh = r % NKV; w = kw;
    }

    float x0 = base[lane];
    float x1 = base[lane + 32];
    float ss = x0 * x0 + x1 * x1;
#pragma unroll
    for (int o = 16; o > 0; o >>= 1) ss += __shfl_xor_sync(0xffffffffu, ss, o);
    const float rinv = rsqrtf(ss * (1.0f / HD) + EPS);

    const float n0 = w[lane]      * (x0 * rinv);
    const float n1 = w[lane + 32] * (x1 * rinv);

    const float c0 = cosv[(size_t)bs * HD + lane];
    const float c1 = cosv[(size_t)bs * HD + lane + 32];
    const float s0 = sinv[(size_t)bs * HD + lane];
    const float s1 = sinv[(size_t)bs * HD + lane + 32];

    const float o0 = n0 * c0 - n1 * s0;
    const float o1 = n1 * c1 + n0 * s1;

    if (isq) {
        base[lane]      = o0;
        base[lane + 32] = o1;
    } else {
        const int b_  = bs >> 11;
        const int key = bs & (SS - 1);
        const size_t o = (((size_t)b_ * NKV + kvh) * SS + key) * HD;
        g_fk_hi[o + lane]      = __float2half_rn(o0);
        g_fk_hi[o + lane + 32] = __float2half_rn(o1);
    }
}

// ---------------- V transpose: f32 [b][key][kvh][d] -> fp16 [b][kvh][d][key] ----
__global__ void v_transpose_kernel()
{
    __shared__ float ts[64][68];
    const int bk = blockIdx.y;
    const int k0 = blockIdx.x * 64;
    const int b  = bk / NKV, kvh = bk % NKV;
    const int t  = threadIdx.x;

#pragma unroll
    for (int i = 0; i < 4; i++) {
        const int idx = t + i * 256;
        const int row = idx >> 4;
        const int c4  = (idx & 15) * 4;
        *reinterpret_cast<float4*>(&ts[row][c4]) =
            *reinterpret_cast<const float4*>(
                g_v + ((size_t)(b * SS + k0 + row) * NKV + kvh) * HD + c4);
    }
    __syncthreads();

    const int d  = t >> 2;
    const int kb = (t & 3) * 16;
    const size_t off = ((size_t)bk * HD + d) * SS + k0 + kb;
    uint32_t hi[8];
#pragma unroll
    for (int j = 0; j < 8; j++)
        hi[j] = packh(ts[kb + 2 * j][d], ts[kb + 2 * j + 1][d]);
    reinterpret_cast<uint4*>(g_vT_hi + off)[0] = make_uint4(hi[0], hi[1], hi[2], hi[3]);
    reinterpret_cast<uint4*>(g_vT_hi + off)[1] = make_uint4(hi[4], hi[5], hi[6], hi[7]);
}

// ---------------- fp16 tensor-core causal flash attention -----------------------
// S = (Qh+Ql)·Kh^T ; P = exp(S-m) split hi/lo in regs; O += (Ph+Pl)·Vh.
// Tile buffer = {Kh, Vh} (18432 B), double-buffered; ldmatrix fragment loads.
#define FBQ 128
#define FKW 36
#define FREG (64 * FKW * 4)              // 9216 B per tile-split
#define FBUF (2 * FREG)                  // 18432 B per buffer
#define FLASH_SMEM (2 * FBUF)            // 36864 B

__global__ __launch_bounds__(256, 2) void flash_mma_kernel()
{
    const int bh  = blockIdx.y;
    const int b   = bh / NH;
    const int h   = bh % NH;
    const int kvh = h / (NH / NKV);
    const int q0  = blockIdx.x * FBQ;
    const int tid = threadIdx.x;
    const int lane = tid & 31;
    const int w    = tid >> 5;
    const int grp  = lane >> 2;
    const int kc   = lane & 3;

    extern __shared__ uint32_t fsm[];
    const uint32_t sb = (uint32_t)__cvta_generic_to_shared(fsm);

    const size_t kvb = (size_t)b * NKV + kvh;
    const __half* gKh = g_fk_hi + kvb * SS * HD;
    const __half* gVh = g_vT_hi + kvb * HD * SS;

    const int l7  = lane & 7;
    const uint32_t bKhalf = ((lane >> 3) & 1) * 16;
    const int bRow8  = (lane >> 4) * 8;

    // Q fragments (fp16 hi/lo, pre-scaled)
    const int qrow0 = q0 + w * 16 + grp;
    const float* Q0 = g_q + ((size_t)(b * SS + qrow0) * NH + h) * HD;
    const float* Q1 = Q0 + (size_t)8 * NH * HD;
    uint32_t aQh[4][4], aQl[4][4];
#pragma unroll
    for (int ks = 0; ks < 4; ks++) {
#pragma unroll
        for (int p = 0; p < 4; p++) {
            const float* Qr = (p & 1) ? Q1 : Q0;
            const int d = ks * 16 + ((p >> 1) ? 8 : 0) + kc * 2;
            float2 v = *reinterpret_cast<const float2*>(Qr + d);
            v.x *= SCALE; v.y *= SCALE;
            aQh[ks][p] = packh(v.x, v.y);
            aQl[ks][p] = packhlo(v.x, v.y, aQh[ks][p]);
        }
    }

    float c_o[8][4];
#pragma unroll
    for (int nt = 0; nt < 8; nt++)
#pragma unroll
        for (int f = 0; f < 4; f++) c_o[nt][f] = 0.f;

    float m0 = -FLT_MAX, m1 = -FLT_MAX, l0 = 0.f, l1 = 0.f;

    const int NT = (q0 + FBQ) / 64;

    // prefetch tile 0 -> buf 0
    {
#pragma unroll
        for (int r = 0; r < 2; r++) {
            const int idx = tid + r * 256;
            const int row = idx >> 3;
            const int ch  = idx & 7;
            const uint32_t doff = row * 144 + ch * 16;
            cp16(sb + doff,        gKh + (size_t)row * HD + ch * 8);
            cp16(sb + FREG + doff, gVh + (size_t)row * SS + ch * 8);
        }
        asm volatile("cp.async.commit_group;" ::: "memory");
    }

    for (int ti = 0; ti < NT; ti++) {
        const int k0 = ti * 64;
        if (ti + 1 < NT) {
            const int kn = k0 + 64;
            const uint32_t bo = sb + ((ti + 1) & 1) * FBUF;
#pragma unroll
            for (int r = 0; r < 2; r++) {
                const int idx = tid + r * 256;
                const int row = idx >> 3;
                const int ch  = idx & 7;
                const uint32_t doff = row * 144 + ch * 16;
                cp16(bo + doff,        gKh + (size_t)(kn + row) * HD + ch * 8);
                cp16(bo + FREG + doff, gVh + (size_t)row * SS + kn + ch * 8);
            }
            asm volatile("cp.async.commit_group;" ::: "memory");
            asm volatile("cp.async.wait_group 1;" ::: "memory");
        } else {
            asm volatile("cp.async.wait_group 0;" ::: "memory");
        }
        __syncthreads();

        const uint32_t buf = sb + (ti & 1) * FBUF;

        // ---- S = Q @ K^T (fp16x2) ----
        float c_s[8][4];
#pragma unroll
        for (int nt = 0; nt < 8; nt++)
#pragma unroll
            for (int f = 0; f < 4; f++) c_s[nt][f] = 0.f;

#pragma unroll
        for (int ks = 0; ks < 4; ks++) {
            uint32_t kh[8][2];
#pragma unroll
            for (int p = 0; p < 4; p++) {
                const uint32_t rb = buf
                    + (uint32_t)(p * 16 + bRow8 + l7) * 144 + ks * 32 + bKhalf;
                ldsm4(kh[2*p][0], kh[2*p][1], kh[2*p+1][0], kh[2*p+1][1], rb);
            }
#pragma unroll
            for (int nt = 0; nt < 8; nt++) {
                mma_f16(c_s[nt], aQh[ks][0], aQh[ks][1], aQh[ks][2], aQh[ks][3],
                        kh[nt][0], kh[nt][1]);
                mma_f16(c_s[nt], aQl[ks][0], aQl[ks][1], aQl[ks][2], aQl[ks][3],
                        kh[nt][0], kh[nt][1]);
            }
        }

        // ---- causal mask (diagonal tiles only) ----
        if (k0 + 64 > q0) {
#pragma unroll
            for (int nt = 0; nt < 8; nt++) {
                const int col = k0 + nt * 8 + kc * 2;
                if (col     > qrow0)     c_s[nt][0] = -FLT_MAX;
                if (col + 1 > qrow0)     c_s[nt][1] = -FLT_MAX;
                if (col     > qrow0 + 8) c_s[nt][2] = -FLT_MAX;
                if (col + 1 > qrow0 + 8) c_s[nt][3] = -FLT_MAX;
            }
        }

        // ---- online softmax ----
        float mx0 = -FLT_MAX, mx1 = -FLT_MAX;
#pragma unroll
        for (int nt = 0; nt < 8; nt++) {
            mx0 = fmaxf(mx0, fmaxf(c_s[nt][0], c_s[nt][1]));
            mx1 = fmaxf(mx1, fmaxf(c_s[nt][2], c_s[nt][3]));
        }
        mx0 = fmaxf(mx0, __shfl_xor_sync(0xffffffffu, mx0, 1));
        mx0 = fmaxf(mx0, __shfl_xor_sync(0xffffffffu, mx0, 2));
        mx1 = fmaxf(mx1, __shfl_xor_sync(0xffffffffu, mx1, 1));
        mx1 = fmaxf(mx1, __shfl_xor_sync(0xffffffffu, mx1, 2));

        const float mn0 = fmaxf(m0, mx0);
        const float mn1 = fmaxf(m1, mx1);
        const float cor0 = __expf(m0 - mn0);
        const float cor1 = __expf(m1 - mn1);
        m0 = mn0; m1 = mn1;

        float rs0 = 0.f, rs1 = 0.f;
#pragma unroll
        for (int nt = 0; nt < 8; nt++) {
            c_s[nt][0] = __expf(c_s[nt][0] - mn0);
            c_s[nt][1] = __expf(c_s[nt][1] - mn0);
            c_s[nt][2] = __expf(c_s[nt][2] - mn1);
            c_s[nt][3] = __expf(c_s[nt][3] - mn1);
            rs0 += c_s[nt][0] + c_s[nt][1];
            rs1 += c_s[nt][2] + c_s[nt][3];
        }
        rs0 += __shfl_xor_sync(0xffffffffu, rs0, 1);
        rs0 += __shfl_xor_sync(0xffffffffu, rs0, 2);
        rs1 += __shfl_xor_sync(0xffffffffu, rs1, 1);
        rs1 += __shfl_xor_sync(0xffffffffu, rs1, 2);
        l0 = l0 * cor0 + rs0;
        l1 = l1 * cor1 + rs1;

#pragma unroll
        for (int nt = 0; nt < 8; nt++) {
            c_o[nt][0] *= cor0; c_o[nt][1] *= cor0;
            c_o[nt][2] *= cor1; c_o[nt][3] *= cor1;
        }

        // ---- O += P @ V (fp16x2, register repack) ----
#pragma unroll
        for (int ks = 0; ks < 4; ks++) {
            const uint32_t p0 = packh(c_s[2*ks][0],   c_s[2*ks][1]);
            const uint32_t p1 = packh(c_s[2*ks][2],   c_s[2*ks][3]);
            const uint32_t p2 = packh(c_s[2*ks+1][0], c_s[2*ks+1][1]);
            const uint32_t p3 = packh(c_s[2*ks+1][2], c_s[2*ks+1][3]);
            const uint32_t q0l = packhlo(c_s[2*ks][0],   c_s[2*ks][1],   p0);
            const uint32_t q1l = packhlo(c_s[2*ks][2],   c_s[2*ks][3],   p1);
            const uint32_t q2l = packhlo(c_s[2*ks+1][0], c_s[2*ks+1][1], p2);
            const uint32_t q3l = packhlo(c_s[2*ks+1][2], c_s[2*ks+1][3], p3);
            uint32_t vh[8][2];
#pragma unroll
            for (int p = 0; p < 4; p++) {
                const uint32_t rb = buf + FREG
                    + (uint32_t)(p * 16 + bRow8 + l7) * 144 + ks * 32 + bKhalf;
                ldsm4(vh[2*p][0], vh[2*p][1], vh[2*p+1][0], vh[2*p+1][1], rb);
            }
#pragma unroll
            for (int nt = 0; nt < 8; nt++) {
                mma_f16(c_o[nt], p0, p1, p2, p3, vh[nt][0], vh[nt][1]);
                mma_f16(c_o[nt], q0l, q1l, q2l, q3l, vh[nt][0], vh[nt][1]);
            }
        }
        __syncthreads();
    }

    // ---- epilogue: normalize and store fp16 {hi,lo} for O-projection ----
    const float inv0 = 1.f / l0;
    const float inv1 = 1.f / l1;
    const size_t off0 = ((size_t)(b * SS + qrow0) * NH + h) * HD;
    const size_t off1 = off0 + (size_t)8 * NH * HD;
#pragma unroll
    for (int nt = 0; nt < 8; nt++) {
        const int c = nt * 8 + kc * 2;
        const float v0 = c_o[nt][0] * inv0, v1 = c_o[nt][1] * inv0;
        const uint32_t h01 = packh(v0, v1);
        *reinterpret_cast<uint32_t*>(g_attn_hi + off0 + c) = h01;
        *reinterpret_cast<uint32_t*>(g_attn_lo + off0 + c) = packhlo(v0, v1, h01);
        const float v2 = c_o[nt][2] * inv1, v3 = c_o[nt][3] * inv1;
        const uint32_t h23 = packh(v2, v3);
        *reinterpret_cast<uint32_t*>(g_attn_hi + off1 + c) = h23;
        *reinterpret_cast<uint32_t*>(g_attn_lo + off1 + c) = packhlo(v2, v3, h23);
    }
}

// ------------------------------- launch ---------------------------------------
extern "C" void kernel_launch(void* const* d_in, const int* in_sizes, int n_in,
                              void* d_out, int out_size)
{
    const float* hidden = (const float*)d_in[0];
    const float* cosv   = (const float*)d_in[1];
    const float* sinv   = (const float*)d_in[2];
    const float* Wq     = (const float*)d_in[3];
    const float* Wk     = (const float*)d_in[4];
    const float* Wv     = (const float*)d_in[5];
    const float* Wo     = (const float*)d_in[6];
    const float* qw     = (const float*)d_in[7];
    const float* kw     = (const float*)d_in[8];
    float* out          = (float*)d_out;

    cudaFuncSetAttribute(gemm_qkv_f16, cudaFuncAttributeMaxDynamicSharedMemorySize, GEMM_SMEM);
    cudaFuncSetAttribute(gemm_o_f16,   cudaFuncAttributeMaxDynamicSharedMemorySize, GEMM_SMEM);
    cudaFuncSetAttribute(flash_mma_kernel, cudaFuncAttributeMaxDynamicSharedMemorySize, FLASH_SMEM);

    // fused prep: hidden -> fp16 hi/lo; 4 weights -> fp16 hi (one launch)
    prep_all<<<(PREP_TOT + 255) / 256, 256>>>(
        (const float4*)hidden, (const float4*)Wq, (const float4*)Wk,
        (const float4*)Wv, (const float4*)Wo);

    // Fused QKV projections (fp16x2 tensor core + ldmatrix, TBK=32)
    gemm_qkv_f16<<<dim3(24, MROWS / 128), 256, GEMM_SMEM>>>();

    // RMSNorm + RoPE (q f32 in-place, k -> fp16 flash layout)
    {
        const int warps = MROWS * NH + MROWS * NKV;
        const int threads = warps * 32;
        norm_rope_kernel<<<(threads + 255) / 256, 256>>>(cosv, sinv, qw, kw);
    }

    // V -> V^T fp16
    v_transpose_kernel<<<dim3(SS / 64, BB * NKV), 256>>>();

    // fp16 tensor-core causal flash attention (double-buffered + ldmatrix)
    flash_mma_kernel<<<dim3(SS / FBQ, BB * NH), 256, FLASH_SMEM>>>();

    // output projection -> d_out
    gemm_o_f16<<<dim3(HIDD / 128, MROWS / 128), 256, GEMM_SMEM>>>(out);
}

// round 17
// speedup vs baseline: 4.5613x; 1.0078x over previous
#include <cuda_runtime.h>
#include <cuda_fp16.h>
#include <float.h>
#include <stdint.h>

// Problem constants
#define BB   2
#define SS   2048
#define HIDD 2048
#define NH   32
#define NKV  8
#define HD   64
#define MROWS (BB*SS)          // 4096
#define SCALE 0.125f           // HD^-0.5
#define EPS   1e-6f

// ---------------- scratch -----------------------------------------------------
__device__ float g_q[(size_t)MROWS * NH * HD];
__device__ float g_k[(size_t)MROWS * NKV * HD];
__device__ float g_v[(size_t)MROWS * NKV * HD];

// fp16 hi/lo splits: lo kept on the A side only (2-term scheme)
__device__ __align__(16) __half g_hid_hi[(size_t)MROWS * HIDD];
__device__ __align__(16) __half g_hid_lo[(size_t)MROWS * HIDD];
__device__ __align__(16) __half g_attn_hi[(size_t)MROWS * NH * HD];
__device__ __align__(16) __half g_attn_lo[(size_t)MROWS * NH * HD];
__device__ __align__(16) __half g_wq_hi[(size_t)NH  * HD * HIDD];
__device__ __align__(16) __half g_wk_hi[(size_t)NKV * HD * HIDD];
__device__ __align__(16) __half g_wv_hi[(size_t)NKV * HD * HIDD];
__device__ __align__(16) __half g_wo_hi[(size_t)HIDD * NH * HD];

// flash operands: K (post-rope) fp16 hi in [b][kvh][key][d]; V^T fp16 hi [b][kvh][d][key]
__device__ __align__(16) __half g_fk_hi[(size_t)BB * NKV * SS * HD];
__device__ __align__(16) __half g_vT_hi[(size_t)BB * NKV * HD * SS];

// ---------------- helpers ------------------------------------------------------
__device__ __forceinline__ uint32_t packh(float x, float y) {
    __half2 t = __floats2half2_rn(x, y);
    return *reinterpret_cast<uint32_t*>(&t);
}
__device__ __forceinline__ uint32_t packhlo(float x, float y, uint32_t hi) {
    __half2 h = *reinterpret_cast<__half2*>(&hi);
    return packh(x - __half2float(h.x), y - __half2float(h.y));
}

__device__ __forceinline__ void mma_f16(float c[4],
    uint32_t a0, uint32_t a1, uint32_t a2, uint32_t a3,
    uint32_t b0, uint32_t b1)
{
    asm volatile(
        "mma.sync.aligned.m16n8k16.row.col.f32.f16.f16.f32 "
        "{%0,%1,%2,%3}, {%4,%5,%6,%7}, {%8,%9}, {%0,%1,%2,%3};"
        : "+f"(c[0]), "+f"(c[1]), "+f"(c[2]), "+f"(c[3])
        : "r"(a0), "r"(a1), "r"(a2), "r"(a3), "r"(b0), "r"(b1));
}

__device__ __forceinline__ void cp16(uint32_t dst, const void* src) {
    asm volatile("cp.async.cg.shared.global [%0], [%1], 16;" :: "r"(dst), "l"(src));
}

__device__ __forceinline__ void ldsm4(uint32_t& r0, uint32_t& r1,
                                      uint32_t& r2, uint32_t& r3, uint32_t addr)
{
    asm volatile("ldmatrix.sync.aligned.m8n8.x4.shared.b16 {%0,%1,%2,%3}, [%4];"
                 : "=r"(r0), "=r"(r1), "=r"(r2), "=r"(r3) : "r"(addr));
}

// ---------------- fused prep: hidden -> hi/lo; 4 weights -> hi ------------------
__device__ __forceinline__ void f4_to_hi(const float4 v, __half2* hi, int i) {
    hi[i * 2 + 0] = __half2(__float2half_rn(v.x), __float2half_rn(v.y));
    hi[i * 2 + 1] = __half2(__float2half_rn(v.z), __float2half_rn(v.w));
}

#define NH4_ (MROWS * HIDD / 4)
#define NQ4_ (NH  * HD * HIDD / 4)
#define NK4_ (NKV * HD * HIDD / 4)
#define PREP_TOT (NH4_ + 2 * NQ4_ + 2 * NK4_)

__global__ void prep_all(const float4* __restrict__ hidden,
                         const float4* __restrict__ Wq, const float4* __restrict__ Wk,
                         const float4* __restrict__ Wv, const float4* __restrict__ Wo)
{
    int i = blockIdx.x * blockDim.x + threadIdx.x;
    if (i >= PREP_TOT) return;
    if (i < NH4_) {
        float4 v = hidden[i];
        __half2* hi = reinterpret_cast<__half2*>(g_hid_hi);
        __half2* lo = reinterpret_cast<__half2*>(g_hid_lo);
        __half h0 = __float2half_rn(v.x), h1 = __float2half_rn(v.y);
        __half h2 = __float2half_rn(v.z), h3 = __float2half_rn(v.w);
        hi[i * 2 + 0] = __half2(h0, h1);
        hi[i * 2 + 1] = __half2(h2, h3);
        lo[i * 2 + 0] = __half2(__float2half_rn(v.x - __half2float(h0)),
                                __float2half_rn(v.y - __half2float(h1)));
        lo[i * 2 + 1] = __half2(__float2half_rn(v.z - __half2float(h2)),
                                __float2half_rn(v.w - __half2float(h3)));
        return;
    }
    i -= NH4_;
    if (i < NQ4_) { f4_to_hi(Wq[i], reinterpret_cast<__half2*>(g_wq_hi), i); return; }
    i -= NQ4_;
    if (i < NK4_) { f4_to_hi(Wk[i], reinterpret_cast<__half2*>(g_wk_hi), i); return; }
    i -= NK4_;
    if (i < NK4_) { f4_to_hi(Wv[i], reinterpret_cast<__half2*>(g_wv_hi), i); return; }
    i -= NK4_;
    f4_to_hi(Wo[i], reinterpret_cast<__half2*>(g_wo_hi), i);
}

// ---------------- fp16x2 cp.async GEMM with ldmatrix ----------------------------
// C = (Ahi+Alo)[M,K] @ Bhi[N,K]^T.  Block tile 128x128, TBK=32, NSTAGE=3.
// Warp grid 4(M) x 2(N): warp tile 32x64 -> per kt only 16 ldsm (A 8, B 8)
// vs 20 with the 2x4 grid; mma count unchanged (64/kt).
// Row stride 80 B: ldmatrix phases hit banks 20r mod 32 (all distinct);
// cp.async stores 20r+4c cover all 32 banks -- conflict-free both ways.
#define TBK 32
#define NSTAGE 3
#define RSB 80                         // bytes per SMEM row (64 data + 16 pad)
#define TILEB (128 * RSB)              // 10240 bytes per tile-split
#define STB (3 * TILEB)                // 30720 bytes per stage {Ahi, Alo, Bhi}
#define GEMM_SMEM (NSTAGE * STB)       // 92160

__device__ __forceinline__ void gemm_body_f16(
    const __half* __restrict__ Ahi, const __half* __restrict__ Alo,
    const __half* __restrict__ Bhi,
    float* __restrict__ C, int N, int K, int m0, int n0)
{
    extern __shared__ uint32_t smw[];
    const uint32_t sbase = (uint32_t)__cvta_generic_to_shared(smw);

    const int t    = threadIdx.x;
    const int lane = t & 31;
    const int warp = t >> 5;
    const int wm   = warp & 3;              // 4 warps along M (32 rows each)
    const int wn   = warp >> 2;             // 2 warps along N (64 cols each)
    const int grp  = lane >> 2;
    const int kc   = lane & 3;

    // loader: 2 chunks per tile-split per thread (idx 0..511: row=idx>>2, ch=idx&3)
    const int r0i = t, r1i = t + 256;
    const int row0 = r0i >> 2, ch0 = r0i & 3;
    const int row1 = r1i >> 2, ch1 = r1i & 3;
    const size_t gA0 = (size_t)(m0 + row0) * K + ch0 * 8;
    const size_t gA1 = (size_t)(m0 + row1) * K + ch1 * 8;
    const size_t gB0 = (size_t)(n0 + row0) * K + ch0 * 8;
    const size_t gB1 = (size_t)(n0 + row1) * K + ch1 * 8;
    const uint32_t d0 = row0 * RSB + ch0 * 16;
    const uint32_t d1 = row1 * RSB + ch1 * 16;

    // ldmatrix per-thread offsets
    const int l15 = lane & 15;
    const int l7  = lane & 7;
    const uint32_t aKhalf = (lane >> 4) * 16;
    const uint32_t bKhalf = ((lane >> 3) & 1) * 16;
    const int bRow8  = (lane >> 4) * 8;

    float acc[2][8][4];
#pragma unroll
    for (int i = 0; i < 2; i++)
#pragma unroll
        for (int j = 0; j < 8; j++)
#pragma unroll
            for (int f = 0; f < 4; f++) acc[i][j][f] = 0.f;

    const int NT = K / TBK;

#pragma unroll
    for (int s = 0; s < NSTAGE - 1; s++) {
        const int koff = s * TBK;
        const uint32_t sb = sbase + s * STB;
        cp16(sb + d0,             Ahi + gA0 + koff);
        cp16(sb + d1,             Ahi + gA1 + koff);
        cp16(sb + TILEB + d0,     Alo + gA0 + koff);
        cp16(sb + TILEB + d1,     Alo + gA1 + koff);
        cp16(sb + 2 * TILEB + d0, Bhi + gB0 + koff);
        cp16(sb + 2 * TILEB + d1, Bhi + gB1 + koff);
        asm volatile("cp.async.commit_group;" ::: "memory");
    }

#pragma unroll 2
    for (int kt = 0; kt < NT; kt++) {
        asm volatile("cp.async.wait_group %0;" :: "n"(NSTAGE - 2) : "memory");
        __syncthreads();

        const int kn = kt + NSTAGE - 1;
        if (kn < NT) {
            const int s = kn % NSTAGE;
            const int koff = kn * TBK;
            const uint32_t sb = sbase + s * STB;
            cp16(sb + d0,             Ahi + gA0 + koff);
            cp16(sb + d1,             Ahi + gA1 + koff);
            cp16(sb + TILEB + d0,     Alo + gA0 + koff);
            cp16(sb + TILEB + d1,     Alo + gA1 + koff);
            cp16(sb + 2 * TILEB + d0, Bhi + gB0 + koff);
            cp16(sb + 2 * TILEB + d1, Bhi + gB1 + koff);
        }
        asm volatile("cp.async.commit_group;" ::: "memory");

        const uint32_t stb = sbase + (kt % NSTAGE) * STB;

#pragma unroll
        for (int ks = 0; ks < 2; ks++) {
            uint32_t ah[2][4], al[2][4];
#pragma unroll
            for (int mt = 0; mt < 2; mt++) {
                const uint32_t ra = stb + (uint32_t)(wm * 32 + mt * 16 + l15) * RSB
                                    + ks * 32 + aKhalf;
                ldsm4(ah[mt][0], ah[mt][1], ah[mt][2], ah[mt][3], ra);
                ldsm4(al[mt][0], al[mt][1], al[mt][2], al[mt][3], ra + TILEB);
            }
            uint32_t bh[8][2];
#pragma unroll
            for (int p = 0; p < 4; p++) {
                const uint32_t rb = stb + 2 * TILEB
                    + (uint32_t)(wn * 64 + p * 16 + bRow8 + l7) * RSB + ks * 32 + bKhalf;
                ldsm4(bh[2*p][0], bh[2*p][1], bh[2*p+1][0], bh[2*p+1][1], rb);
            }

#pragma unroll
            for (int mt = 0; mt < 2; mt++) {
#pragma unroll
                for (int nt = 0; nt < 8; nt++) {
                    mma_f16(acc[mt][nt], ah[mt][0], ah[mt][1], ah[mt][2], ah[mt][3],
                            bh[nt][0], bh[nt][1]);
                    mma_f16(acc[mt][nt], al[mt][0], al[mt][1], al[mt][2], al[mt][3],
                            bh[nt][0], bh[nt][1]);
                }
            }
        }
    }

#pragma unroll
    for (int mt = 0; mt < 2; mt++) {
        const int row = m0 + wm * 32 + mt * 16 + grp;
#pragma unroll
        for (int nt = 0; nt < 8; nt++) {
            const int col = n0 + wn * 64 + nt * 8 + kc * 2;
            *reinterpret_cast<float2*>(C + (size_t)row * N + col) =
                make_float2(acc[mt][nt][0], acc[mt][nt][1]);
            *reinterpret_cast<float2*>(C + (size_t)(row + 8) * N + col) =
                make_float2(acc[mt][nt][2], acc[mt][nt][3]);
        }
    }
}

__global__ __launch_bounds__(256, 2) void gemm_qkv_f16()
{
    const int bx = blockIdx.x;
    const int m0 = blockIdx.y * 128;
    const __half* Bh; float* C; int N, n0;
    if (bx < 16)      { Bh = g_wq_hi; C = g_q; N = NH  * HD; n0 = bx * 128; }
    else if (bx < 20) { Bh = g_wk_hi; C = g_k; N = NKV * HD; n0 = (bx - 16) * 128; }
    else              { Bh = g_wv_hi; C = g_v; N = NKV * HD; n0 = (bx - 20) * 128; }
    gemm_body_f16(g_hid_hi, g_hid_lo, Bh, C, N, HIDD, m0, n0);
}

__global__ __launch_bounds__(256, 2) void gemm_o_f16(float* __restrict__ out)
{
    gemm_body_f16(g_attn_hi, g_attn_lo, g_wo_hi,
                  out, HIDD, NH * HD, blockIdx.y * 128, blockIdx.x * 128);
}

// ---------------- RMSNorm + RoPE: q in-place f32; k -> fp16 hi ------------------
__global__ void norm_rope_kernel(
    const float* __restrict__ cosv, const float* __restrict__ sinv,
    const float* __restrict__ qw,   const float* __restrict__ kw)
{
    const int gid  = blockIdx.x * blockDim.x + threadIdx.x;
    const int wid  = gid >> 5;
    const int lane = gid & 31;
    const int nqr  = MROWS * NH;
    const int ntot = nqr + MROWS * NKV;
    if (wid >= ntot) return;

    const bool isq = (wid < nqr);
    float* base;
    int bs, kvh = 0;
    const float* w;
    if (isq) { base = g_q + (size_t)wid * HD;  bs = wid / NH; w = qw; }
    else {
        int r = wid - nqr;
        base = g_k + (size_t)r * HD;
        bs = r / NKV; kvh = r % NKV; w = kw;
    }

    float x0 = base[lane];
    float x1 = base[lane + 32];
    float ss = x0 * x0 + x1 * x1;
#pragma unroll
    for (int o = 16; o > 0; o >>= 1) ss += __shfl_xor_sync(0xffffffffu, ss, o);
    const float rinv = rsqrtf(ss * (1.0f / HD) + EPS);

    const float n0 = w[lane]      * (x0 * rinv);
    const float n1 = w[lane + 32] * (x1 * rinv);

    const float c0 = cosv[(size_t)bs * HD + lane];
    const float c1 = cosv[(size_t)bs * HD + lane + 32];
    const float s0 = sinv[(size_t)bs * HD + lane];
    const float s1 = sinv[(size_t)bs * HD + lane + 32];

    const float o0 = n0 * c0 - n1 * s0;
    const float o1 = n1 * c1 + n0 * s1;

    if (isq) {
        base[lane]      = o0;
        base[lane + 32] = o1;
    } else {
        const int b_  = bs >> 11;
        const int key = bs & (SS - 1);
        const size_t o = (((size_t)b_ * NKV + kvh) * SS + key) * HD;
        g_fk_hi[o + lane]      = __float2half_rn(o0);
        g_fk_hi[o + lane + 32] = __float2half_rn(o1);
    }
}

// ---------------- V transpose: f32 [b][key][kvh][d] -> fp16 [b][kvh][d][key] ----
__global__ void v_transpose_kernel()
{
    __shared__ float ts[64][68];
    const int bk = blockIdx.y;
    const int k0 = blockIdx.x * 64;
    const int b  = bk / NKV, kvh = bk % NKV;
    const int t  = threadIdx.x;

#pragma unroll
    for (int i = 0; i < 4; i++) {
        const int idx = t + i * 256;
        const int row = idx >> 4;
        const int c4  = (idx & 15) * 4;
        *reinterpret_cast<float4*>(&ts[row][c4]) =
            *reinterpret_cast<const float4*>(
                g_v + ((size_t)(b * SS + k0 + row) * NKV + kvh) * HD + c4);
    }
    __syncthreads();

    const int d  = t >> 2;
    const int kb = (t & 3) * 16;
    const size_t off = ((size_t)bk * HD + d) * SS + k0 + kb;
    uint32_t hi[8];
#pragma unroll
    for (int j = 0; j < 8; j++)
        hi[j] = packh(ts[kb + 2 * j][d], ts[kb + 2 * j + 1][d]);
    reinterpret_cast<uint4*>(g_vT_hi + off)[0] = make_uint4(hi[0], hi[1], hi[2], hi[3]);
    reinterpret_cast<uint4*>(g_vT_hi + off)[1] = make_uint4(hi[4], hi[5], hi[6], hi[7]);
}

// ---------------- fp16 tensor-core causal flash attention -----------------------
// S = (Qh+Ql)·Kh^T ; P = exp(S-m) split hi/lo in regs; O += (Ph+Pl)·Vh.
// Tile buffer = {Kh, Vh} (18432 B), double-buffered; ldmatrix fragment loads.
// CTA order REVERSED along x so the heaviest (largest q0) blocks launch first.
#define FBQ 128
#define FKW 36
#define FREG (64 * FKW * 4)              // 9216 B per tile-split
#define FBUF (2 * FREG)                  // 18432 B per buffer
#define FLASH_SMEM (2 * FBUF)            // 36864 B

__global__ __launch_bounds__(256, 2) void flash_mma_kernel()
{
    const int bh  = blockIdx.y;
    const int b   = bh / NH;
    const int h   = bh % NH;
    const int kvh = h / (NH / NKV);
    const int q0  = (gridDim.x - 1 - blockIdx.x) * FBQ;   // heavy blocks first
    const int tid = threadIdx.x;
    const int lane = tid & 31;
    const int w    = tid >> 5;
    const int grp  = lane >> 2;
    const int kc   = lane & 3;

    extern __shared__ uint32_t fsm[];
    const uint32_t sb = (uint32_t)__cvta_generic_to_shared(fsm);

    const size_t kvb = (size_t)b * NKV + kvh;
    const __half* gKh = g_fk_hi + kvb * SS * HD;
    const __half* gVh = g_vT_hi + kvb * HD * SS;

    const int l7  = lane & 7;
    const uint32_t bKhalf = ((lane >> 3) & 1) * 16;
    const int bRow8  = (lane >> 4) * 8;

    // Q fragments (fp16 hi/lo, pre-scaled)
    const int qrow0 = q0 + w * 16 + grp;
    const float* Q0 = g_q + ((size_t)(b * SS + qrow0) * NH + h) * HD;
    const float* Q1 = Q0 + (size_t)8 * NH * HD;
    uint32_t aQh[4][4], aQl[4][4];
#pragma unroll
    for (int ks = 0; ks < 4; ks++) {
#pragma unroll
        for (int p = 0; p < 4; p++) {
            const float* Qr = (p & 1) ? Q1 : Q0;
            const int d = ks * 16 + ((p >> 1) ? 8 : 0) + kc * 2;
            float2 v = *reinterpret_cast<const float2*>(Qr + d);
            v.x *= SCALE; v.y *= SCALE;
            aQh[ks][p] = packh(v.x, v.y);
            aQl[ks][p] = packhlo(v.x, v.y, aQh[ks][p]);
        }
    }

    float c_o[8][4];
#pragma unroll
    for (int nt = 0; nt < 8; nt++)
#pragma unroll
        for (int f = 0; f < 4; f++) c_o[nt][f] = 0.f;

    float m0 = -FLT_MAX, m1 = -FLT_MAX, l0 = 0.f, l1 = 0.f;

    const int NT = (q0 + FBQ) / 64;

    // prefetch tile 0 -> buf 0
    {
#pragma unroll
        for (int r = 0; r < 2; r++) {
            const int idx = tid + r * 256;
            const int row = idx >> 3;
            const int ch  = idx & 7;
            const uint32_t doff = row * 144 + ch * 16;
            cp16(sb + doff,        gKh + (size_t)row * HD + ch * 8);
            cp16(sb + FREG + doff, gVh + (size_t)row * SS + ch * 8);
        }
        asm volatile("cp.async.commit_group;" ::: "memory");
    }

    for (int ti = 0; ti < NT; ti++) {
        const int k0 = ti * 64;
        if (ti + 1 < NT) {
            const int kn = k0 + 64;
            const uint32_t bo = sb + ((ti + 1) & 1) * FBUF;
#pragma unroll
            for (int r = 0; r < 2; r++) {
                const int idx = tid + r * 256;
                const int row = idx >> 3;
                const int ch  = idx & 7;
                const uint32_t doff = row * 144 + ch * 16;
                cp16(bo + doff,        gKh + (size_t)(kn + row) * HD + ch * 8);
                cp16(bo + FREG + doff, gVh + (size_t)row * SS + kn + ch * 8);
            }
            asm volatile("cp.async.commit_group;" ::: "memory");
            asm volatile("cp.async.wait_group 1;" ::: "memory");
        } else {
            asm volatile("cp.async.wait_group 0;" ::: "memory");
        }
        __syncthreads();

        const uint32_t buf = sb + (ti & 1) * FBUF;

        // ---- S = Q @ K^T (fp16x2) ----
        float c_s[8][4];
#pragma unroll
        for (int nt = 0; nt < 8; nt++)
#pragma unroll
            for (int f = 0; f < 4; f++) c_s[nt][f] = 0.f;

#pragma unroll
        for (int ks = 0; ks < 4; ks++) {
            uint32_t kh[8][2];
#pragma unroll
            for (int p = 0; p < 4; p++) {
                const uint32_t rb = buf
                    + (uint32_t)(p * 16 + bRow8 + l7) * 144 + ks * 32 + bKhalf;
                ldsm4(kh[2*p][0], kh[2*p][1], kh[2*p+1][0], kh[2*p+1][1], rb);
            }
#pragma unroll
            for (int nt = 0; nt < 8; nt++) {
                mma_f16(c_s[nt], aQh[ks][0], aQh[ks][1], aQh[ks][2], aQh[ks][3],
                        kh[nt][0], kh[nt][1]);
                mma_f16(c_s[nt], aQl[ks][0], aQl[ks][1], aQl[ks][2], aQl[ks][3],
                        kh[nt][0], kh[nt][1]);
            }
        }

        // ---- causal mask (diagonal tiles only) ----
        if (k0 + 64 > q0) {
#pragma unroll
            for (int nt = 0; nt < 8; nt++) {
                const int col = k0 + nt * 8 + kc * 2;
                if (col     > qrow0)     c_s[nt][0] = -FLT_MAX;
                if (col + 1 > qrow0)     c_s[nt][1] = -FLT_MAX;
                if (col     > qrow0 + 8) c_s[nt][2] = -FLT_MAX;
                if (col + 1 > qrow0 + 8) c_s[nt][3] = -FLT_MAX;
            }
        }

        // ---- online softmax ----
        float mx0 = -FLT_MAX, mx1 = -FLT_MAX;
#pragma unroll
        for (int nt = 0; nt < 8; nt++) {
            mx0 = fmaxf(mx0, fmaxf(c_s[nt][0], c_s[nt][1]));
            mx1 = fmaxf(mx1, fmaxf(c_s[nt][2], c_s[nt][3]));
        }
        mx0 = fmaxf(mx0, __shfl_xor_sync(0xffffffffu, mx0, 1));
        mx0 = fmaxf(mx0, __shfl_xor_sync(0xffffffffu, mx0, 2));
        mx1 = fmaxf(mx1, __shfl_xor_sync(0xffffffffu, mx1, 1));
        mx1 = fmaxf(mx1, __shfl_xor_sync(0xffffffffu, mx1, 2));

        const float mn0 = fmaxf(m0, mx0);
        const float mn1 = fmaxf(m1, mx1);
        const float cor0 = __expf(m0 - mn0);
        const float cor1 = __expf(m1 - mn1);
        m0 = mn0; m1 = mn1;

        float rs0 = 0.f, rs1 = 0.f;
#pragma unroll
        for (int nt = 0; nt < 8; nt++) {
            c_s[nt][0] = __expf(c_s[nt][0] - mn0);
            c_s[nt][1] = __expf(c_s[nt][1] - mn0);
            c_s[nt][2] = __expf(c_s[nt][2] - mn1);
            c_s[nt][3] = __expf(c_s[nt][3] - mn1);
            rs0 += c_s[nt][0] + c_s[nt][1];
            rs1 += c_s[nt][2] + c_s[nt][3];
        }
        rs0 += __shfl_xor_sync(0xffffffffu, rs0, 1);
        rs0 += __shfl_xor_sync(0xffffffffu, rs0, 2);
        rs1 += __shfl_xor_sync(0xffffffffu, rs1, 1);
        rs1 += __shfl_xor_sync(0xffffffffu, rs1, 2);
        l0 = l0 * cor0 + rs0;
        l1 = l1 * cor1 + rs1;

#pragma unroll
        for (int nt = 0; nt < 8; nt++) {
            c_o[nt][0] *= cor0; c_o[nt][1] *= cor0;
            c_o[nt][2] *= cor1; c_o[nt][3] *= cor1;
        }

        // ---- O += P @ V (fp16x2, register repack) ----
#pragma unroll
        for (int ks = 0; ks < 4; ks++) {
            const uint32_t p0 = packh(c_s[2*ks][0],   c_s[2*ks][1]);
            const uint32_t p1 = packh(c_s[2*ks][2],   c_s[2*ks][3]);
            const uint32_t p2 = packh(c_s[2*ks+1][0], c_s[2*ks+1][1]);
            const uint32_t p3 = packh(c_s[2*ks+1][2], c_s[2*ks+1][3]);
            const uint32_t q0l = packhlo(c_s[2*ks][0],   c_s[2*ks][1],   p0);
            const uint32_t q1l = packhlo(c_s[2*ks][2],   c_s[2*ks][3],   p1);
            const uint32_t q2l = packhlo(c_s[2*ks+1][0], c_s[2*ks+1][1], p2);
            const uint32_t q3l = packhlo(c_s[2*ks+1][2], c_s[2*ks+1][3], p3);
            uint32_t vh[8][2];
#pragma unroll
            for (int p = 0; p < 4; p++) {
                const uint32_t rb = buf + FREG
                    + (uint32_t)(p * 16 + bRow8 + l7) * 144 + ks * 32 + bKhalf;
                ldsm4(vh[2*p][0], vh[2*p][1], vh[2*p+1][0], vh[2*p+1][1], rb);
            }
#pragma unroll
            for (int nt = 0; nt < 8; nt++) {
                mma_f16(c_o[nt], p0, p1, p2, p3, vh[nt][0], vh[nt][1]);
                mma_f16(c_o[nt], q0l, q1l, q2l, q3l, vh[nt][0], vh[nt][1]);
            }
        }
        __syncthreads();
    }

    // ---- epilogue: normalize and store fp16 {hi,lo} for O-projection ----
    const float inv0 = 1.f / l0;
    const float inv1 = 1.f / l1;
    const size_t off0 = ((size_t)(b * SS + qrow0) * NH + h) * HD;
    const size_t off1 = off0 + (size_t)8 * NH * HD;
#pragma unroll
    for (int nt = 0; nt < 8; nt++) {
        const int c = nt * 8 + kc * 2;
        const float v0 = c_o[nt][0] * inv0, v1 = c_o[nt][1] * inv0;
        const uint32_t h01 = packh(v0, v1);
        *reinterpret_cast<uint32_t*>(g_attn_hi + off0 + c) = h01;
        *reinterpret_cast<uint32_t*>(g_attn_lo + off0 + c) = packhlo(v0, v1, h01);
        const float v2 = c_o[nt][2] * inv1, v3 = c_o[nt][3] * inv1;
        const uint32_t h23 = packh(v2, v3);
        *reinterpret_cast<uint32_t*>(g_attn_hi + off1 + c) = h23;
        *reinterpret_cast<uint32_t*>(g_attn_lo + off1 + c) = packhlo(v2, v3, h23);
    }
}

// ------------------------------- launch ---------------------------------------
extern "C" void kernel_launch(void* const* d_in, const int* in_sizes, int n_in,
                              void* d_out, int out_size)
{
    const float* hidden = (const float*)d_in[0];
    const float* cosv   = (const float*)d_in[1];
    const float* sinv   = (const float*)d_in[2];
    const float* Wq     = (const float*)d_in[3];
    const float* Wk     = (const float*)d_in[4];
    const float* Wv     = (const float*)d_in[5];
    const float* Wo     = (const float*)d_in[6];
    const float* qw     = (const float*)d_in[7];
    const float* kw     = (const float*)d_in[8];
    float* out          = (float*)d_out;

    cudaFuncSetAttribute(gemm_qkv_f16, cudaFuncAttributeMaxDynamicSharedMemorySize, GEMM_SMEM);
    cudaFuncSetAttribute(gemm_o_f16,   cudaFuncAttributeMaxDynamicSharedMemorySize, GEMM_SMEM);
    cudaFuncSetAttribute(flash_mma_kernel, cudaFuncAttributeMaxDynamicSharedMemorySize, FLASH_SMEM);

    // fused prep: hidden -> fp16 hi/lo; 4 weights -> fp16 hi (one launch)
    prep_all<<<(PREP_TOT + 255) / 256, 256>>>(
        (const float4*)hidden, (const float4*)Wq, (const float4*)Wk,
        (const float4*)Wv, (const float4*)Wo);

    // Fused QKV projections (fp16x2 tensor core + ldmatrix, TBK=32)
    gemm_qkv_f16<<<dim3(24, MROWS / 128), 256, GEMM_SMEM>>>();

    // RMSNorm + RoPE (q f32 in-place, k -> fp16 flash layout)
    {
        const int warps = MROWS * NH + MROWS * NKV;
        const int threads = warps * 32;
        norm_rope_kernel<<<(threads + 255) / 256, 256>>>(cosv, sinv, qw, kw);
    }

    // V -> V^T fp16
    v_transpose_kernel<<<dim3(SS / 64, BB * NKV), 256>>>();

    // fp16 tensor-core causal flash attention (double-buffered + ldmatrix)
    flash_mma_kernel<<<dim3(SS / FBQ, BB * NH), 256, FLASH_SMEM>>>();

    // output projection -> d_out
    gemm_o_f16<<<dim3(HIDD / 128, MROWS / 128), 256, GEMM_SMEM>>>(out);
}